// round 1
// baseline (speedup 1.0000x reference)
#include <cuda_runtime.h>
#include <math.h>

#define B_   4
#define T_   2048
#define D_   256
#define H_   4
#define DH   64
#define C_   64
#define NC   (T_/C_)     // 32 chunks
#define BHN  (B_*H_)     // 16
#define M_   (B_*T_)     // 8192
#define EPS_ 1e-6f

// ---------------- scratch (global __device__ arrays; no runtime alloc) -------
__device__ float g_Q[M_*D_];                 // feature-mapped Q
__device__ float g_K[M_*D_];                 // feature-mapped K
__device__ float g_V[M_*D_];                 // V
__device__ float g_y[M_*D_];                 // attention output before Wo
__device__ float g_cKV[BHN*NC*DH*DH];        // per-chunk KV sums -> exclusive prefix
__device__ float g_cZ [BHN*NC*DH];           // per-chunk K sums  -> exclusive prefix

// ---------------- generic 64x64-tile fp32 GEMM: C = f(A @ W + b) -------------
// A: [M, 256] row-major, W: [256, 256] row-major, C: [M, 256]
// applyFeature: elu(x)+1 = (x>0 ? x+1 : exp(x))
__device__ __forceinline__ void gemm64x64(const float* __restrict__ A,
                                          const float* __restrict__ W,
                                          const float* __restrict__ bias,
                                          float* __restrict__ Cout,
                                          int applyFeature) {
    __shared__ float As[16][64+1];   // [k][m]
    __shared__ float Ws[16][64+1];   // [k][n]
    const int tid  = threadIdx.x;
    const int row0 = blockIdx.y * 64;
    const int col0 = blockIdx.x * 64;
    const int tx = tid & 15, ty = tid >> 4;

    float acc[4][4];
#pragma unroll
    for (int i = 0; i < 4; i++)
#pragma unroll
        for (int j = 0; j < 4; j++) acc[i][j] = 0.f;

    for (int k0 = 0; k0 < D_; k0 += 16) {
#pragma unroll
        for (int i = 0; i < 4; i++) {
            int e  = tid + i * 256;          // 0..1023
            int m  = e >> 4, kk = e & 15;    // A tile: 64 rows x 16 k
            As[kk][m] = A[(size_t)(row0 + m) * D_ + k0 + kk];
            int kk2 = e >> 6, n = e & 63;    // W tile: 16 k x 64 n
            Ws[kk2][n] = W[(size_t)(k0 + kk2) * D_ + col0 + n];
        }
        __syncthreads();
#pragma unroll
        for (int kk = 0; kk < 16; kk++) {
            float a[4], b[4];
#pragma unroll
            for (int i = 0; i < 4; i++) a[i] = As[kk][ty * 4 + i];
#pragma unroll
            for (int j = 0; j < 4; j++) b[j] = Ws[kk][tx * 4 + j];
#pragma unroll
            for (int i = 0; i < 4; i++)
#pragma unroll
                for (int j = 0; j < 4; j++) acc[i][j] += a[i] * b[j];
        }
        __syncthreads();
    }

#pragma unroll
    for (int i = 0; i < 4; i++) {
        int m = row0 + ty * 4 + i;
#pragma unroll
        for (int j = 0; j < 4; j++) {
            int n = col0 + tx * 4 + j;
            float v = acc[i][j] + bias[n];
            if (applyFeature) v = (v > 0.f) ? (v + 1.f) : expf(v);
            Cout[(size_t)m * D_ + n] = v;
        }
    }
}

// QKV projections: grid.z selects which projection (0=Q,1=K,2=V)
__global__ void qkv_proj_kernel(const float* __restrict__ x,
                                const float* __restrict__ Wq, const float* __restrict__ bq,
                                const float* __restrict__ Wk, const float* __restrict__ bk,
                                const float* __restrict__ Wv, const float* __restrict__ bv) {
    int z = blockIdx.z;
    const float* W = (z == 0) ? Wq : (z == 1) ? Wk : Wv;
    const float* b = (z == 0) ? bq : (z == 1) ? bk : bv;
    float* out     = (z == 0) ? g_Q : (z == 1) ? g_K : g_V;
    gemm64x64(x, W, b, out, z < 2);
}

// Final output GEMM: out = g_y @ Wo + bo
__global__ void out_proj_kernel(const float* __restrict__ Wo,
                                const float* __restrict__ bo,
                                float* __restrict__ out) {
    gemm64x64(g_y, Wo, bo, out, 0);
}

// ---------------- per-chunk KV/Z sums ---------------------------------------
__global__ void chunksum_kernel() {
    const int chunk = blockIdx.x, bh = blockIdx.y;
    const int b = bh >> 2, h = bh & 3;
    __shared__ float Ks[C_][DH+1];
    __shared__ float Vs[C_][DH+1];
    const int tid = threadIdx.x;
    const size_t base = (size_t)(b * T_ + chunk * C_) * D_ + h * DH;

    for (int e = tid; e < C_ * DH; e += 256) {
        int s = e >> 6, d = e & 63;
        Ks[s][d] = g_K[base + (size_t)s * D_ + d];
        Vs[s][d] = g_V[base + (size_t)s * D_ + d];
    }
    __syncthreads();

    const int d = tid >> 2, m0 = (tid & 3) * 16;
    float acc[16];
#pragma unroll
    for (int j = 0; j < 16; j++) acc[j] = 0.f;
    float zacc = 0.f;
    for (int s = 0; s < C_; s++) {
        float k = Ks[s][d];
        zacc += k;
#pragma unroll
        for (int j = 0; j < 16; j++) acc[j] += k * Vs[s][m0 + j];
    }
    size_t obase = ((size_t)(bh * NC + chunk) * DH + d) * DH + m0;
#pragma unroll
    for (int j = 0; j < 16; j++) g_cKV[obase + j] = acc[j];
    if ((tid & 3) == 0) g_cZ[(size_t)(bh * NC + chunk) * DH + d] = zacc;
}

// ---------------- exclusive prefix across chunks (per bh) -------------------
__global__ void prefix_kernel() {
    const int bh = blockIdx.x;
    const int tid = threadIdx.x;
    float run[16];
#pragma unroll
    for (int j = 0; j < 16; j++) run[j] = 0.f;
    float zrun = 0.f;
    for (int c = 0; c < NC; c++) {
        size_t base = (size_t)(bh * NC + c) * (DH * DH) + (size_t)tid * 16;
#pragma unroll
        for (int j = 0; j < 16; j++) {
            float t = g_cKV[base + j];
            g_cKV[base + j] = run[j];
            run[j] += t;
        }
        if (tid < DH) {
            size_t zb = (size_t)(bh * NC + c) * DH + tid;
            float t = g_cZ[zb];
            g_cZ[zb] = zrun;
            zrun += t;
        }
    }
}

// ---------------- per-chunk output ------------------------------------------
// smem layout (floats): Qs[64][65], Ks[64][65], Vs[64][65], As[64][65],
//                       Sp[64][65], dp[64*4], denom[64], Zp[64]
#define TILE_F  (64 * 65)
#define SMEM_D_FLOATS (5 * TILE_F + 64 * 4 + 64 + 64)
#define SMEM_D_BYTES  (SMEM_D_FLOATS * 4)

__global__ void chunk_out_kernel() {
    extern __shared__ float sm[];
    float (*Qs)[DH+1] = (float(*)[DH+1])(sm);
    float (*Ks)[DH+1] = (float(*)[DH+1])(sm + 1 * TILE_F);
    float (*Vs)[DH+1] = (float(*)[DH+1])(sm + 2 * TILE_F);
    float (*As)[DH+1] = (float(*)[DH+1])(sm + 3 * TILE_F);
    float (*Sp)[DH+1] = (float(*)[DH+1])(sm + 4 * TILE_F);
    float* dp    = sm + 5 * TILE_F;          // partial row-sums [64][4]
    float* denom = dp + 64 * 4;
    float* Zp    = denom + 64;

    const int chunk = blockIdx.x, bh = blockIdx.y;
    const int b = bh >> 2, h = bh & 3;
    const int tid = threadIdx.x;
    const size_t gbase = (size_t)(b * T_ + chunk * C_) * D_ + h * DH;
    const size_t cbase = (size_t)(bh * NC + chunk) * (DH * DH);

    for (int e = tid; e < C_ * DH; e += 256) {
        int r = e >> 6, d = e & 63;
        Qs[r][d] = g_Q[gbase + (size_t)r * D_ + d];
        Ks[r][d] = g_K[gbase + (size_t)r * D_ + d];
        Vs[r][d] = g_V[gbase + (size_t)r * D_ + d];
        Sp[r][d] = g_cKV[cbase + e];   // Sp[d][m] exclusive prefix state
    }
    if (tid < DH) Zp[tid] = g_cZ[(size_t)(bh * NC + chunk) * DH + tid];
    __syncthreads();

    const int t = tid >> 2, g = tid & 3;
    const int s0 = g * 16;

    // phase 2: attention scores A[t][s] = Q_t . K_s (store all, use s<=t)
    float rs = 0.f;
    for (int sj = 0; sj < 16; sj++) {
        int s = s0 + sj;
        float a = 0.f;
#pragma unroll
        for (int d = 0; d < DH; d++) a += Qs[t][d] * Ks[s][d];
        As[t][s] = a;
        if (s <= t) rs += a;
    }
    dp[t * 4 + g] = rs;
    __syncthreads();

    // phase 3: denominator per t
    if (tid < C_) {
        int tt = tid;
        float qz = 0.f;
#pragma unroll
        for (int d = 0; d < DH; d++) qz += Qs[tt][d] * Zp[d];
        denom[tt] = qz + dp[tt * 4 + 0] + dp[tt * 4 + 1]
                       + dp[tt * 4 + 2] + dp[tt * 4 + 3] + EPS_;
    }
    __syncthreads();

    // phase 4: out[t][m] = sum_{s<=t} A[t][s] V[s][m] + sum_d Q[t][d] Sp[d][m]
    const int m0 = g * 16;
    float acc[16];
#pragma unroll
    for (int j = 0; j < 16; j++) acc[j] = 0.f;
    for (int s = 0; s <= t; s++) {
        float a = As[t][s];
#pragma unroll
        for (int j = 0; j < 16; j++) acc[j] += a * Vs[s][m0 + j];
    }
#pragma unroll
    for (int d = 0; d < DH; d++) {
        float q = Qs[t][d];
#pragma unroll
        for (int j = 0; j < 16; j++) acc[j] += q * Sp[d][m0 + j];
    }
    float inv = 1.f / denom[t];
#pragma unroll
    for (int j = 0; j < 16; j++)
        g_y[gbase + (size_t)t * D_ + m0 + j] = acc[j] * inv;
}

// ---------------- launch -----------------------------------------------------
extern "C" void kernel_launch(void* const* d_in, const int* in_sizes, int n_in,
                              void* d_out, int out_size) {
    const float* x  = (const float*)d_in[0];
    const float* Wq = (const float*)d_in[1];
    const float* bq = (const float*)d_in[2];
    const float* Wk = (const float*)d_in[3];
    const float* bk = (const float*)d_in[4];
    const float* Wv = (const float*)d_in[5];
    const float* bv = (const float*)d_in[6];
    const float* Wo = (const float*)d_in[7];
    const float* bo = (const float*)d_in[8];
    float* out = (float*)d_out;

    cudaFuncSetAttribute(chunk_out_kernel,
                         cudaFuncAttributeMaxDynamicSharedMemorySize, SMEM_D_BYTES);

    dim3 gq(D_ / 64, M_ / 64, 3);      // (4, 128, 3)
    qkv_proj_kernel<<<gq, 256>>>(x, Wq, bq, Wk, bk, Wv, bv);

    chunksum_kernel<<<dim3(NC, BHN), 256>>>();
    prefix_kernel<<<BHN, 256>>>();
    chunk_out_kernel<<<dim3(NC, BHN), 256, SMEM_D_BYTES>>>();

    dim3 go(D_ / 64, M_ / 64, 1);
    out_proj_kernel<<<go, 256>>>(Wo, bo, out);
}

// round 4
// speedup vs baseline: 2.0852x; 2.0852x over previous
#include <cuda_runtime.h>
#include <math.h>

#define B_   4
#define T_   2048
#define D_   256
#define H_   4
#define DH   64
#define C_   64
#define NC   (T_/C_)     // 32 chunks
#define BHN  (B_*H_)     // 16
#define M_   (B_*T_)     // 8192
#define EPS_ 1e-6f

// ---------------- scratch ----------------------------------------------------
__device__ float g_Q[M_*D_];
__device__ float g_K[M_*D_];
__device__ float g_V[M_*D_];
__device__ float g_y[M_*D_];
__device__ float g_cKV[BHN*NC*DH*DH];
__device__ float g_cZ [BHN*NC*DH];

// ---------------- 128x128x16 fp32 SGEMM, 8x8 microtile ----------------------
// A: [M,256] row-major, W: [256,256] row-major, C = f(A@W + b)
__device__ __forceinline__ void sgemm128(const float* __restrict__ A,
                                         const float* __restrict__ W,
                                         const float* __restrict__ bias,
                                         float* __restrict__ Cout,
                                         int applyFeature) {
    __shared__ float As[16][132];   // [k][m], 132*4B row = 16B-aligned
    __shared__ float Ws[16][132];   // [k][n]
    const int tid  = threadIdx.x;
    const int row0 = blockIdx.y * 128;
    const int col0 = blockIdx.x * 128;
    const int tm = tid >> 4, tn = tid & 15;

    float acc[8][8];
#pragma unroll
    for (int i = 0; i < 8; i++)
#pragma unroll
        for (int j = 0; j < 8; j++) acc[i][j] = 0.f;

    for (int k0 = 0; k0 < D_; k0 += 16) {
#pragma unroll
        for (int i = 0; i < 2; i++) {
            int idx = tid + i * 256;                 // 0..511 float4s
            // A tile 128x16, store transposed
            int r  = idx >> 2, c4 = (idx & 3) << 2;
            float4 va = *(const float4*)(A + (size_t)(row0 + r) * D_ + k0 + c4);
            As[c4+0][r] = va.x; As[c4+1][r] = va.y;
            As[c4+2][r] = va.z; As[c4+3][r] = va.w;
            // W tile 16x128, direct
            int r2 = idx >> 5, c42 = (idx & 31) << 2;
            *(float4*)&Ws[r2][c42] =
                *(const float4*)(W + (size_t)(k0 + r2) * D_ + col0 + c42);
        }
        __syncthreads();
#pragma unroll
        for (int kk = 0; kk < 16; kk++) {
            float a[8], b[8];
            *(float4*)&a[0] = *(const float4*)&As[kk][tm * 8];
            *(float4*)&a[4] = *(const float4*)&As[kk][tm * 8 + 4];
            *(float4*)&b[0] = *(const float4*)&Ws[kk][tn * 8];
            *(float4*)&b[4] = *(const float4*)&Ws[kk][tn * 8 + 4];
#pragma unroll
            for (int i = 0; i < 8; i++)
#pragma unroll
                for (int j = 0; j < 8; j++) acc[i][j] += a[i] * b[j];
        }
        __syncthreads();
    }

#pragma unroll
    for (int i = 0; i < 8; i++) {
        int r = row0 + tm * 8 + i;
#pragma unroll
        for (int j0 = 0; j0 < 8; j0 += 4) {
            float4 o;
            int c = col0 + tn * 8 + j0;
            o.x = acc[i][j0+0] + bias[c+0];
            o.y = acc[i][j0+1] + bias[c+1];
            o.z = acc[i][j0+2] + bias[c+2];
            o.w = acc[i][j0+3] + bias[c+3];
            if (applyFeature) {
                o.x = (o.x > 0.f) ? (o.x + 1.f) : __expf(o.x);
                o.y = (o.y > 0.f) ? (o.y + 1.f) : __expf(o.y);
                o.z = (o.z > 0.f) ? (o.z + 1.f) : __expf(o.z);
                o.w = (o.w > 0.f) ? (o.w + 1.f) : __expf(o.w);
            }
            *(float4*)(Cout + (size_t)r * D_ + c) = o;
        }
    }
}

__global__ __launch_bounds__(256, 2)
void qkv_proj_kernel(const float* __restrict__ x,
                     const float* __restrict__ Wq, const float* __restrict__ bq,
                     const float* __restrict__ Wk, const float* __restrict__ bk,
                     const float* __restrict__ Wv, const float* __restrict__ bv) {
    int z = blockIdx.z;
    const float* W = (z == 0) ? Wq : (z == 1) ? Wk : Wv;
    const float* b = (z == 0) ? bq : (z == 1) ? bk : bv;
    float* out     = (z == 0) ? g_Q : (z == 1) ? g_K : g_V;
    sgemm128(x, W, b, out, z < 2);
}

__global__ __launch_bounds__(256, 2)
void out_proj_kernel(const float* __restrict__ Wo,
                     const float* __restrict__ bo,
                     float* __restrict__ out) {
    sgemm128(g_y, Wo, bo, out, 0);
}

// ---------------- per-chunk KV / Z sums (4x4 microtile, LDS.128) ------------
#define RW (DH + 4)   // 68 floats per row: 16B-aligned, conflict-benign

__global__ __launch_bounds__(256)
void chunksum_kernel() {
    __shared__ float Ks[C_][RW];
    __shared__ float Vs[C_][RW];
    const int chunk = blockIdx.x, bh = blockIdx.y;
    const int b = bh >> 2, h = bh & 3;
    const int tid = threadIdx.x;
    const size_t base = (size_t)(b * T_ + chunk * C_) * D_ + h * DH;

#pragma unroll
    for (int i = 0; i < 4; i++) {
        int idx = tid + i * 256;            // 1024 float4s
        int s = idx >> 4, c4 = (idx & 15) << 2;
        *(float4*)&Ks[s][c4] = *(const float4*)(g_K + base + (size_t)s * D_ + c4);
        *(float4*)&Vs[s][c4] = *(const float4*)(g_V + base + (size_t)s * D_ + c4);
    }
    __syncthreads();

    const int d0 = (tid >> 4) * 4, m0 = (tid & 15) * 4;
    float acc[4][4];
#pragma unroll
    for (int i = 0; i < 4; i++)
#pragma unroll
        for (int j = 0; j < 4; j++) acc[i][j] = 0.f;
    float z0 = 0.f, z1 = 0.f, z2 = 0.f, z3 = 0.f;

    for (int s = 0; s < C_; s++) {
        float4 k4 = *(const float4*)&Ks[s][d0];
        float4 v4 = *(const float4*)&Vs[s][m0];
        float ka[4] = {k4.x, k4.y, k4.z, k4.w};
        float vb[4] = {v4.x, v4.y, v4.z, v4.w};
#pragma unroll
        for (int i = 0; i < 4; i++)
#pragma unroll
            for (int j = 0; j < 4; j++) acc[i][j] += ka[i] * vb[j];
        if (m0 == 0) { z0 += k4.x; z1 += k4.y; z2 += k4.z; z3 += k4.w; }
    }

    size_t obase = (size_t)(bh * NC + chunk) * DH;
#pragma unroll
    for (int i = 0; i < 4; i++) {
        float4 o = {acc[i][0], acc[i][1], acc[i][2], acc[i][3]};
        *(float4*)&g_cKV[(obase + d0 + i) * DH + m0] = o;
    }
    if (m0 == 0) {
        float4 z = {z0, z1, z2, z3};
        *(float4*)&g_cZ[obase + d0] = z;
    }
}

// ---------------- exclusive prefix over chunks -------------------------------
__global__ __launch_bounds__(256)
void prefix_kernel() {
    const int bh = blockIdx.x, tid = threadIdx.x;
    float4 run[4];
#pragma unroll
    for (int j = 0; j < 4; j++) run[j] = make_float4(0.f, 0.f, 0.f, 0.f);
    float zrun = 0.f;
    for (int c = 0; c < NC; c++) {
        float* p = g_cKV + (size_t)(bh * NC + c) * (DH * DH) + (size_t)tid * 16;
#pragma unroll
        for (int j = 0; j < 4; j++) {
            float4 t = *(float4*)(p + j * 4);
            *(float4*)(p + j * 4) = run[j];
            run[j].x += t.x; run[j].y += t.y; run[j].z += t.z; run[j].w += t.w;
        }
        if (tid < DH) {
            float* zp = g_cZ + (size_t)(bh * NC + c) * DH + tid;
            float t = *zp; *zp = zrun; zrun += t;
        }
    }
}

// ---------------- per-chunk output (transposed tiles, LDS.128 everywhere) ----
#define TILE2 (C_ * RW)
#define SMEM_D_FLOATS (5 * TILE2 + 64 * 16 + 64 + 64)
#define SMEM_D_BYTES  (SMEM_D_FLOATS * 4)

__global__ __launch_bounds__(256)
void chunk_out_kernel() {
    extern __shared__ float sm[];
    float (*QT)[RW] = (float(*)[RW])(sm);               // [d][t]
    float (*KT)[RW] = (float(*)[RW])(sm + 1 * TILE2);   // [d][s]
    float (*Vs)[RW] = (float(*)[RW])(sm + 2 * TILE2);   // [s][m]
    float (*AT)[RW] = (float(*)[RW])(sm + 3 * TILE2);   // [s][t], causal-masked
    float (*Sp)[RW] = (float(*)[RW])(sm + 4 * TILE2);   // [d][m]
    float* dp    = sm + 5 * TILE2;                      // [t][16] partial sums
    float* denom = dp + 64 * 16;
    float* Zp    = denom + 64;

    const int chunk = blockIdx.x, bh = blockIdx.y;
    const int b = bh >> 2, h = bh & 3;
    const int tid = threadIdx.x;
    const size_t gbase = (size_t)(b * T_ + chunk * C_) * D_ + h * DH;
    const size_t cbase = (size_t)(bh * NC + chunk) * (DH * DH);

#pragma unroll
    for (int i = 0; i < 4; i++) {
        int idx = tid + i * 256;
        int r = idx >> 4, c4 = (idx & 15) << 2;
        float4 q = *(const float4*)(g_Q + gbase + (size_t)r * D_ + c4);
        QT[c4+0][r] = q.x; QT[c4+1][r] = q.y; QT[c4+2][r] = q.z; QT[c4+3][r] = q.w;
        float4 k = *(const float4*)(g_K + gbase + (size_t)r * D_ + c4);
        KT[c4+0][r] = k.x; KT[c4+1][r] = k.y; KT[c4+2][r] = k.z; KT[c4+3][r] = k.w;
        *(float4*)&Vs[r][c4] = *(const float4*)(g_V + gbase + (size_t)r * D_ + c4);
        *(float4*)&Sp[r][c4] = *(const float4*)(g_cKV + cbase + (size_t)idx * 4);
    }
    if (tid < DH) Zp[tid] = g_cZ[(size_t)(bh * NC + chunk) * DH + tid];
    __syncthreads();

    const int t0 = (tid >> 4) * 4;
    const int s0 = (tid & 15) * 4;
    const int sg = tid & 15;

    // phase 2: scores A = Q K^T (4t x 4s per thread)
    float a2[4][4];
#pragma unroll
    for (int i = 0; i < 4; i++)
#pragma unroll
        for (int j = 0; j < 4; j++) a2[i][j] = 0.f;
    for (int d = 0; d < DH; d++) {
        float4 q4 = *(const float4*)&QT[d][t0];
        float4 k4 = *(const float4*)&KT[d][s0];
        float qa[4] = {q4.x, q4.y, q4.z, q4.w};
        float kb[4] = {k4.x, k4.y, k4.z, k4.w};
#pragma unroll
        for (int i = 0; i < 4; i++)
#pragma unroll
            for (int j = 0; j < 4; j++) a2[i][j] += qa[i] * kb[j];
    }
    // causal mask, row-sums, store masked A^T
    float rs0 = 0.f, rs1 = 0.f, rs2 = 0.f, rs3 = 0.f;
#pragma unroll
    for (int j = 0; j < 4; j++) {
        float4 col;
        col.x = (s0 + j <= t0 + 0) ? a2[0][j] : 0.f; rs0 += col.x;
        col.y = (s0 + j <= t0 + 1) ? a2[1][j] : 0.f; rs1 += col.y;
        col.z = (s0 + j <= t0 + 2) ? a2[2][j] : 0.f; rs2 += col.z;
        col.w = (s0 + j <= t0 + 3) ? a2[3][j] : 0.f; rs3 += col.w;
        *(float4*)&AT[s0 + j][t0] = col;
    }
    dp[(t0 + 0) * 16 + sg] = rs0;
    dp[(t0 + 1) * 16 + sg] = rs1;
    dp[(t0 + 2) * 16 + sg] = rs2;
    dp[(t0 + 3) * 16 + sg] = rs3;
    __syncthreads();

    // phase 3: denominators (threads 0..63)
    if (tid < C_) {
        float qz = 0.f;
#pragma unroll
        for (int d = 0; d < DH; d++) qz += QT[d][tid] * Zp[d];
        float s = qz + EPS_;
        const float* dpr = &dp[tid * 16];
#pragma unroll
        for (int g2 = 0; g2 < 16; g2 += 4) {
            float4 v = *(const float4*)(dpr + g2);
            s += v.x + v.y + v.z + v.w;
        }
        denom[tid] = s;
    }

    // phase 4: out = A_masked @ V + Q @ Sp  (4t x 4m per thread)
    const int m0 = s0;
    float acc[4][4];
#pragma unroll
    for (int i = 0; i < 4; i++)
#pragma unroll
        for (int j = 0; j < 4; j++) acc[i][j] = 0.f;
    for (int s = 0; s < C_; s++) {
        float4 a4 = *(const float4*)&AT[s][t0];
        float4 v4 = *(const float4*)&Vs[s][m0];
        float aa[4] = {a4.x, a4.y, a4.z, a4.w};
        float vb[4] = {v4.x, v4.y, v4.z, v4.w};
#pragma unroll
        for (int i = 0; i < 4; i++)
#pragma unroll
            for (int j = 0; j < 4; j++) acc[i][j] += aa[i] * vb[j];
    }
    for (int d = 0; d < DH; d++) {
        float4 q4 = *(const float4*)&QT[d][t0];
        float4 p4 = *(const float4*)&Sp[d][m0];
        float qa[4] = {q4.x, q4.y, q4.z, q4.w};
        float pb[4] = {p4.x, p4.y, p4.z, p4.w};
#pragma unroll
        for (int i = 0; i < 4; i++)
#pragma unroll
            for (int j = 0; j < 4; j++) acc[i][j] += qa[i] * pb[j];
    }
    __syncthreads();   // denom ready for all threads

#pragma unroll
    for (int i = 0; i < 4; i++) {
        float inv = 1.f / denom[t0 + i];
        float4 o = {acc[i][0] * inv, acc[i][1] * inv,
                    acc[i][2] * inv, acc[i][3] * inv};
        *(float4*)(g_y + gbase + (size_t)(t0 + i) * D_ + m0) = o;
    }
}

// ---------------- launch -----------------------------------------------------
extern "C" void kernel_launch(void* const* d_in, const int* in_sizes, int n_in,
                              void* d_out, int out_size) {
    const float* x  = (const float*)d_in[0];
    const float* Wq = (const float*)d_in[1];
    const float* bq = (const float*)d_in[2];
    const float* Wk = (const float*)d_in[3];
    const float* bk = (const float*)d_in[4];
    const float* Wv = (const float*)d_in[5];
    const float* bv = (const float*)d_in[6];
    const float* Wo = (const float*)d_in[7];
    const float* bo = (const float*)d_in[8];
    float* out = (float*)d_out;

    cudaFuncSetAttribute(chunk_out_kernel,
                         cudaFuncAttributeMaxDynamicSharedMemorySize, SMEM_D_BYTES);

    dim3 gq(D_ / 128, M_ / 128, 3);     // (2, 64, 3)
    qkv_proj_kernel<<<gq, 256>>>(x, Wq, bq, Wk, bk, Wv, bv);

    chunksum_kernel<<<dim3(NC, BHN), 256>>>();
    prefix_kernel<<<BHN, 256>>>();
    chunk_out_kernel<<<dim3(NC, BHN), 256, SMEM_D_BYTES>>>();

    dim3 go(D_ / 128, M_ / 128, 1);     // (2, 64)
    out_proj_kernel<<<go, 256>>>(Wo, bo, out);
}

// round 6
// speedup vs baseline: 2.7709x; 1.3288x over previous
#include <cuda_runtime.h>
#include <cuda_bf16.h>
#include <stdint.h>
#include <math.h>

#define B_   4
#define T_   2048
#define D_   256
#define H_   4
#define DH   64
#define C_   64
#define NC   (T_/C_)     // 32
#define BHN  (B_*H_)     // 16
#define M_   (B_*T_)     // 8192
#define EPS_ 1e-6f

// ---------------- scratch ----------------------------------------------------
__device__ float g_Q[M_*D_];
__device__ float g_K[M_*D_];
__device__ float g_V[M_*D_];
__device__ float g_y[M_*D_];
__device__ float g_cKV[BHN*NC*DH*DH];
__device__ float g_cZ [BHN*NC*DH];
__device__ __nv_bfloat16 g_xh[M_*D_];
__device__ __nv_bfloat16 g_xl[M_*D_];
__device__ __nv_bfloat16 g_Wth[4*D_*D_];   // W^T, [n][k], bf16 hi
__device__ __nv_bfloat16 g_Wtl[4*D_*D_];   // W^T lo

// ---------------- PTX helpers (baseline features only) -----------------------
__device__ __forceinline__ uint32_t smem_u32(const void* p) {
    uint32_t a;
    asm("{ .reg .u64 t; cvta.to.shared.u64 t, %1; cvt.u32.u64 %0, t; }"
        : "=r"(a) : "l"(p));
    return a;
}
__device__ __forceinline__ void ldsm4(uint32_t* r, uint32_t addr) {
    asm volatile("ldmatrix.sync.aligned.m8n8.x4.shared.b16 {%0,%1,%2,%3}, [%4];"
        : "=r"(r[0]), "=r"(r[1]), "=r"(r[2]), "=r"(r[3]) : "r"(addr));
}
__device__ __forceinline__ void mma_bf16(float* c, const uint32_t* a,
                                         uint32_t b0, uint32_t b1) {
    asm volatile(
        "mma.sync.aligned.m16n8k16.row.col.f32.bf16.bf16.f32 "
        "{%0,%1,%2,%3}, {%4,%5,%6,%7}, {%8,%9}, {%0,%1,%2,%3};"
        : "+f"(c[0]), "+f"(c[1]), "+f"(c[2]), "+f"(c[3])
        : "r"(a[0]), "r"(a[1]), "r"(a[2]), "r"(a[3]), "r"(b0), "r"(b1));
}

// ---------------- conversion kernels -----------------------------------------
__global__ __launch_bounds__(256)
void split_kernel(const float* __restrict__ in,
                  __nv_bfloat16* __restrict__ oh,
                  __nv_bfloat16* __restrict__ ol) {
    int idx = blockIdx.x * 256 + threadIdx.x;        // float4 index
    float4 v = *(const float4*)(in + (size_t)idx * 4);
    float a[4] = {v.x, v.y, v.z, v.w};
#pragma unroll
    for (int j = 0; j < 4; j++) {
        __nv_bfloat16 h = __float2bfloat16_rn(a[j]);
        __nv_bfloat16 l = __float2bfloat16_rn(a[j] - __bfloat162float(h));
        oh[(size_t)idx * 4 + j] = h;
        ol[(size_t)idx * 4 + j] = l;
    }
}

__global__ __launch_bounds__(256)
void wt_kernel(const float* __restrict__ Wq, const float* __restrict__ Wk,
               const float* __restrict__ Wv, const float* __restrict__ Wo) {
    __shared__ float s[32][33];
    const int n0 = blockIdx.x * 32, k0 = blockIdx.y * 32, z = blockIdx.z;
    const float* W = (z == 0) ? Wq : (z == 1) ? Wk : (z == 2) ? Wv : Wo;
    const int tx = threadIdx.x, ty = threadIdx.y;
#pragma unroll
    for (int r = 0; r < 4; r++) {
        int k = k0 + ty + r * 8;
        s[ty + r * 8][tx] = W[(size_t)k * D_ + n0 + tx];
    }
    __syncthreads();
#pragma unroll
    for (int r = 0; r < 4; r++) {
        int n = n0 + ty + r * 8;
        float v = s[tx][ty + r * 8];
        __nv_bfloat16 h = __float2bfloat16_rn(v);
        __nv_bfloat16 l = __float2bfloat16_rn(v - __bfloat162float(h));
        size_t o = (size_t)z * D_ * D_ + (size_t)n * D_ + k0 + tx;
        g_Wth[o] = h;
        g_Wtl[o] = l;
    }
}

// ---------------- HMMA bf16-split GEMM ---------------------------------------
// C[128 x 128] tile per CTA.  8 warps (2m x 4n), each 64m x 32n.
// K chunked x64 via smem.  Row pitch 72 bf16 = 144B -> conflict-free ldmatrix.
#define APITCH 72
#define GEMM_SMEM (4 * 128 * APITCH * 2)   // Ah, Al, Bh, Bl  = 73728 B

__global__ __launch_bounds__(256)
void hmma_gemm_kernel(const __nv_bfloat16* __restrict__ Ah,
                      const __nv_bfloat16* __restrict__ Al,
                      const float* __restrict__ b0, const float* __restrict__ b1,
                      const float* __restrict__ b2,
                      float* __restrict__ dout, int mode) {
    extern __shared__ __nv_bfloat16 sm2[];
    __nv_bfloat16* sAh = sm2;
    __nv_bfloat16* sAl = sm2 + 128 * APITCH;
    __nv_bfloat16* sBh = sm2 + 2 * 128 * APITCH;
    __nv_bfloat16* sBl = sm2 + 3 * 128 * APITCH;

    const int tid = threadIdx.x, lane = tid & 31, wid = tid >> 5;
    const int warp_m = wid >> 2, warp_n = wid & 3;
    const int n0 = blockIdx.x * 128, row0 = blockIdx.y * 128;
    const int zy = blockIdx.z;
    const int z = (mode == 0) ? zy : 3;
    const float* bias = (mode == 0) ? ((zy == 0) ? b0 : (zy == 1) ? b1 : b2) : b0;
    float* Cout = (mode == 0) ? ((zy == 0) ? g_Q : (zy == 1) ? g_K : g_V) : dout;
    const int feat = (mode == 0) && (zy < 2);
    const __nv_bfloat16* Bh = g_Wth + (size_t)z * D_ * D_;
    const __nv_bfloat16* Bl = g_Wtl + (size_t)z * D_ * D_;

    float acc[4][4][4];
#pragma unroll
    for (int mt = 0; mt < 4; mt++)
#pragma unroll
        for (int nt = 0; nt < 4; nt++)
#pragma unroll
            for (int r = 0; r < 4; r++) acc[mt][nt][r] = 0.f;

    // ldmatrix lane roles
    const int i4 = lane >> 3, r8 = lane & 7;
    const int a_row = warp_m * 64 + (i4 & 1) * 8 + r8;   // + mt*16
    const int a_ku  = (i4 >> 1);                          // + ks*2
    const int b_row = warp_n * 32 + (i4 >> 1) * 8 + r8;  // + pt*16
    const int b_ku  = (i4 & 1);                           // + ks*2

    for (int kc = 0; kc < 4; kc++) {
#pragma unroll
        for (int i = 0; i < 4; i++) {
            int idx = tid + i * 256;           // 1024 16B-units
            int r = idx >> 3, u = idx & 7;
            size_t ga = (size_t)(row0 + r) * D_ + kc * 64 + u * 8;
            size_t gb = (size_t)(n0 + r) * D_ + kc * 64 + u * 8;
            *(uint4*)(sAh + r * APITCH + u * 8) = *(const uint4*)(Ah + ga);
            *(uint4*)(sAl + r * APITCH + u * 8) = *(const uint4*)(Al + ga);
            *(uint4*)(sBh + r * APITCH + u * 8) = *(const uint4*)(Bh + gb);
            *(uint4*)(sBl + r * APITCH + u * 8) = *(const uint4*)(Bl + gb);
        }
        __syncthreads();

#pragma unroll
        for (int ks = 0; ks < 4; ks++) {
            const int au = (ks * 2 + a_ku) * 8;
            const int bu = (ks * 2 + b_ku) * 8;
            uint32_t afr[4][4], bhf[2][4], blf[2][4];
#pragma unroll
            for (int mt = 0; mt < 4; mt++)
                ldsm4(afr[mt], smem_u32(sAh + (a_row + mt * 16) * APITCH + au));
#pragma unroll
            for (int pt = 0; pt < 2; pt++) {
                ldsm4(bhf[pt], smem_u32(sBh + (b_row + pt * 16) * APITCH + bu));
                ldsm4(blf[pt], smem_u32(sBl + (b_row + pt * 16) * APITCH + bu));
            }
            // hi*hi and hi*lo
#pragma unroll
            for (int mt = 0; mt < 4; mt++)
#pragma unroll
                for (int nt = 0; nt < 4; nt++) {
                    int pt = nt >> 1, sub = (nt & 1) * 2;
                    mma_bf16(acc[mt][nt], afr[mt], bhf[pt][sub], bhf[pt][sub + 1]);
                    mma_bf16(acc[mt][nt], afr[mt], blf[pt][sub], blf[pt][sub + 1]);
                }
            // lo*hi (reload A as lo)
#pragma unroll
            for (int mt = 0; mt < 4; mt++)
                ldsm4(afr[mt], smem_u32(sAl + (a_row + mt * 16) * APITCH + au));
#pragma unroll
            for (int mt = 0; mt < 4; mt++)
#pragma unroll
                for (int nt = 0; nt < 4; nt++) {
                    int pt = nt >> 1, sub = (nt & 1) * 2;
                    mma_bf16(acc[mt][nt], afr[mt], bhf[pt][sub], bhf[pt][sub + 1]);
                }
        }
        __syncthreads();
    }

    // epilogue: bias + optional elu+1, direct stores (float2 per acc pair)
    const int er = (lane >> 2), ec = (lane & 3) * 2;
#pragma unroll
    for (int mt = 0; mt < 4; mt++) {
        int r = row0 + warp_m * 64 + mt * 16 + er;
#pragma unroll
        for (int nt = 0; nt < 4; nt++) {
            int c = n0 + warp_n * 32 + nt * 8 + ec;
            float2 bv = *(const float2*)(bias + c);
            float2 o0 = {acc[mt][nt][0] + bv.x, acc[mt][nt][1] + bv.y};
            float2 o1 = {acc[mt][nt][2] + bv.x, acc[mt][nt][3] + bv.y};
            if (feat) {
                o0.x = (o0.x > 0.f) ? (o0.x + 1.f) : __expf(o0.x);
                o0.y = (o0.y > 0.f) ? (o0.y + 1.f) : __expf(o0.y);
                o1.x = (o1.x > 0.f) ? (o1.x + 1.f) : __expf(o1.x);
                o1.y = (o1.y > 0.f) ? (o1.y + 1.f) : __expf(o1.y);
            }
            *(float2*)(Cout + (size_t)r * D_ + c) = o0;
            *(float2*)(Cout + (size_t)(r + 8) * D_ + c) = o1;
        }
    }
}

// ---------------- per-chunk KV / Z sums --------------------------------------
#define RW (DH + 4)

__global__ __launch_bounds__(256)
void chunksum_kernel() {
    __shared__ float Ks[C_][RW];
    __shared__ float Vs[C_][RW];
    const int chunk = blockIdx.x, bh = blockIdx.y;
    const int b = bh >> 2, h = bh & 3;
    const int tid = threadIdx.x;
    const size_t base = (size_t)(b * T_ + chunk * C_) * D_ + h * DH;

#pragma unroll
    for (int i = 0; i < 4; i++) {
        int idx = tid + i * 256;
        int s = idx >> 4, c4 = (idx & 15) << 2;
        *(float4*)&Ks[s][c4] = *(const float4*)(g_K + base + (size_t)s * D_ + c4);
        *(float4*)&Vs[s][c4] = *(const float4*)(g_V + base + (size_t)s * D_ + c4);
    }
    __syncthreads();

    const int d0 = (tid >> 4) * 4, m0 = (tid & 15) * 4;
    float acc[4][4];
#pragma unroll
    for (int i = 0; i < 4; i++)
#pragma unroll
        for (int j = 0; j < 4; j++) acc[i][j] = 0.f;
    float z0 = 0.f, z1 = 0.f, z2 = 0.f, z3 = 0.f;

    for (int s = 0; s < C_; s++) {
        float4 k4 = *(const float4*)&Ks[s][d0];
        float4 v4 = *(const float4*)&Vs[s][m0];
        float ka[4] = {k4.x, k4.y, k4.z, k4.w};
        float vb[4] = {v4.x, v4.y, v4.z, v4.w};
#pragma unroll
        for (int i = 0; i < 4; i++)
#pragma unroll
            for (int j = 0; j < 4; j++) acc[i][j] += ka[i] * vb[j];
        if (m0 == 0) { z0 += k4.x; z1 += k4.y; z2 += k4.z; z3 += k4.w; }
    }

    size_t obase = (size_t)(bh * NC + chunk) * DH;
#pragma unroll
    for (int i = 0; i < 4; i++) {
        float4 o = {acc[i][0], acc[i][1], acc[i][2], acc[i][3]};
        *(float4*)&g_cKV[(obase + d0 + i) * DH + m0] = o;
    }
    if (m0 == 0) {
        float4 z = {z0, z1, z2, z3};
        *(float4*)&g_cZ[obase + d0] = z;
    }
}

// ---------------- exclusive prefix over chunks -------------------------------
__global__ __launch_bounds__(256)
void prefix_kernel() {
    const int bh = blockIdx.x, tid = threadIdx.x;
    float4 run[4];
#pragma unroll
    for (int j = 0; j < 4; j++) run[j] = make_float4(0.f, 0.f, 0.f, 0.f);
    float zrun = 0.f;
    for (int c = 0; c < NC; c++) {
        float* p = g_cKV + (size_t)(bh * NC + c) * (DH * DH) + (size_t)tid * 16;
#pragma unroll
        for (int j = 0; j < 4; j++) {
            float4 t = *(float4*)(p + j * 4);
            *(float4*)(p + j * 4) = run[j];
            run[j].x += t.x; run[j].y += t.y; run[j].z += t.z; run[j].w += t.w;
        }
        if (tid < DH) {
            float* zp = g_cZ + (size_t)(bh * NC + c) * DH + tid;
            float t = *zp; *zp = zrun; zrun += t;
        }
    }
}

// ---------------- per-chunk output -------------------------------------------
#define TILE2 (C_ * RW)
#define SMEM_D_FLOATS (5 * TILE2 + 64 * 16 + 64 + 64)
#define SMEM_D_BYTES  (SMEM_D_FLOATS * 4)

__global__ __launch_bounds__(256)
void chunk_out_kernel() {
    extern __shared__ float sm[];
    float (*QT)[RW] = (float(*)[RW])(sm);
    float (*KT)[RW] = (float(*)[RW])(sm + 1 * TILE2);
    float (*Vs)[RW] = (float(*)[RW])(sm + 2 * TILE2);
    float (*AT)[RW] = (float(*)[RW])(sm + 3 * TILE2);
    float (*Sp)[RW] = (float(*)[RW])(sm + 4 * TILE2);
    float* dp    = sm + 5 * TILE2;
    float* denom = dp + 64 * 16;
    float* Zp    = denom + 64;

    const int chunk = blockIdx.x, bh = blockIdx.y;
    const int b = bh >> 2, h = bh & 3;
    const int tid = threadIdx.x;
    const size_t gbase = (size_t)(b * T_ + chunk * C_) * D_ + h * DH;
    const size_t cbase = (size_t)(bh * NC + chunk) * (DH * DH);

#pragma unroll
    for (int i = 0; i < 4; i++) {
        int idx = tid + i * 256;
        int r = idx >> 4, c4 = (idx & 15) << 2;
        float4 q = *(const float4*)(g_Q + gbase + (size_t)r * D_ + c4);
        QT[c4+0][r] = q.x; QT[c4+1][r] = q.y; QT[c4+2][r] = q.z; QT[c4+3][r] = q.w;
        float4 k = *(const float4*)(g_K + gbase + (size_t)r * D_ + c4);
        KT[c4+0][r] = k.x; KT[c4+1][r] = k.y; KT[c4+2][r] = k.z; KT[c4+3][r] = k.w;
        *(float4*)&Vs[r][c4] = *(const float4*)(g_V + gbase + (size_t)r * D_ + c4);
        *(float4*)&Sp[r][c4] = *(const float4*)(g_cKV + cbase + (size_t)idx * 4);
    }
    if (tid < DH) Zp[tid] = g_cZ[(size_t)(bh * NC + chunk) * DH + tid];
    __syncthreads();

    const int t0 = (tid >> 4) * 4;
    const int s0 = (tid & 15) * 4;
    const int sg = tid & 15;

    float a2[4][4];
#pragma unroll
    for (int i = 0; i < 4; i++)
#pragma unroll
        for (int j = 0; j < 4; j++) a2[i][j] = 0.f;
    for (int d = 0; d < DH; d++) {
        float4 q4 = *(const float4*)&QT[d][t0];
        float4 k4 = *(const float4*)&KT[d][s0];
        float qa[4] = {q4.x, q4.y, q4.z, q4.w};
        float kb[4] = {k4.x, k4.y, k4.z, k4.w};
#pragma unroll
        for (int i = 0; i < 4; i++)
#pragma unroll
            for (int j = 0; j < 4; j++) a2[i][j] += qa[i] * kb[j];
    }
    float rs0 = 0.f, rs1 = 0.f, rs2 = 0.f, rs3 = 0.f;
#pragma unroll
    for (int j = 0; j < 4; j++) {
        float4 col;
        col.x = (s0 + j <= t0 + 0) ? a2[0][j] : 0.f; rs0 += col.x;
        col.y = (s0 + j <= t0 + 1) ? a2[1][j] : 0.f; rs1 += col.y;
        col.z = (s0 + j <= t0 + 2) ? a2[2][j] : 0.f; rs2 += col.z;
        col.w = (s0 + j <= t0 + 3) ? a2[3][j] : 0.f; rs3 += col.w;
        *(float4*)&AT[s0 + j][t0] = col;
    }
    dp[(t0 + 0) * 16 + sg] = rs0;
    dp[(t0 + 1) * 16 + sg] = rs1;
    dp[(t0 + 2) * 16 + sg] = rs2;
    dp[(t0 + 3) * 16 + sg] = rs3;
    __syncthreads();

    if (tid < C_) {
        float qz = 0.f;
#pragma unroll
        for (int d = 0; d < DH; d++) qz += QT[d][tid] * Zp[d];
        float s = qz + EPS_;
        const float* dpr = &dp[tid * 16];
#pragma unroll
        for (int g2 = 0; g2 < 16; g2 += 4) {
            float4 v = *(const float4*)(dpr + g2);
            s += v.x + v.y + v.z + v.w;
        }
        denom[tid] = s;
    }

    const int m0 = s0;
    float acc[4][4];
#pragma unroll
    for (int i = 0; i < 4; i++)
#pragma unroll
        for (int j = 0; j < 4; j++) acc[i][j] = 0.f;
    for (int s = 0; s < C_; s++) {
        float4 a4 = *(const float4*)&AT[s][t0];
        float4 v4 = *(const float4*)&Vs[s][m0];
        float aa[4] = {a4.x, a4.y, a4.z, a4.w};
        float vb[4] = {v4.x, v4.y, v4.z, v4.w};
#pragma unroll
        for (int i = 0; i < 4; i++)
#pragma unroll
            for (int j = 0; j < 4; j++) acc[i][j] += aa[i] * vb[j];
    }
    for (int d = 0; d < DH; d++) {
        float4 q4 = *(const float4*)&QT[d][t0];
        float4 p4 = *(const float4*)&Sp[d][m0];
        float qa[4] = {q4.x, q4.y, q4.z, q4.w};
        float pb[4] = {p4.x, p4.y, p4.z, p4.w};
#pragma unroll
        for (int i = 0; i < 4; i++)
#pragma unroll
            for (int j = 0; j < 4; j++) acc[i][j] += qa[i] * pb[j];
    }
    __syncthreads();

#pragma unroll
    for (int i = 0; i < 4; i++) {
        float inv = 1.f / denom[t0 + i];
        float4 o = {acc[i][0] * inv, acc[i][1] * inv,
                    acc[i][2] * inv, acc[i][3] * inv};
        *(float4*)(g_y + gbase + (size_t)(t0 + i) * D_ + m0) = o;
    }
}

// ---------------- launch -----------------------------------------------------
extern "C" void kernel_launch(void* const* d_in, const int* in_sizes, int n_in,
                              void* d_out, int out_size) {
    const float* x  = (const float*)d_in[0];
    const float* Wq = (const float*)d_in[1];
    const float* bq = (const float*)d_in[2];
    const float* Wk = (const float*)d_in[3];
    const float* bk = (const float*)d_in[4];
    const float* Wv = (const float*)d_in[5];
    const float* bv = (const float*)d_in[6];
    const float* Wo = (const float*)d_in[7];
    const float* bo = (const float*)d_in[8];
    float* out = (float*)d_out;

    cudaFuncSetAttribute(chunk_out_kernel,
                         cudaFuncAttributeMaxDynamicSharedMemorySize, SMEM_D_BYTES);
    cudaFuncSetAttribute(hmma_gemm_kernel,
                         cudaFuncAttributeMaxDynamicSharedMemorySize, GEMM_SMEM);

    __nv_bfloat16 *xh, *xl;
    float *y_;
    cudaGetSymbolAddress((void**)&xh, g_xh);
    cudaGetSymbolAddress((void**)&xl, g_xl);
    cudaGetSymbolAddress((void**)&y_, g_y);

    // split x, transpose+split weights
    split_kernel<<<M_ * D_ / 1024, 256>>>(x, xh, xl);
    wt_kernel<<<dim3(8, 8, 4), dim3(32, 8)>>>(Wq, Wk, Wv, Wo);

    // QKV projections via HMMA
    hmma_gemm_kernel<<<dim3(2, 64, 3), 256, GEMM_SMEM>>>(xh, xl, bq, bk, bv,
                                                         nullptr, 0);

    chunksum_kernel<<<dim3(NC, BHN), 256>>>();
    prefix_kernel<<<BHN, 256>>>();
    chunk_out_kernel<<<dim3(NC, BHN), 256, SMEM_D_BYTES>>>();

    // split y, output projection
    split_kernel<<<M_ * D_ / 1024, 256>>>(y_, xh, xl);
    hmma_gemm_kernel<<<dim3(2, 64, 1), 256, GEMM_SMEM>>>(xh, xl, bo, bo, bo,
                                                         out, 1);
}

// round 7
// speedup vs baseline: 2.7720x; 1.0004x over previous
#include <cuda_runtime.h>
#include <cuda_bf16.h>
#include <stdint.h>
#include <math.h>

#define B_   4
#define T_   2048
#define D_   256
#define H_   4
#define DH   64
#define C_   64
#define NC   (T_/C_)     // 32
#define BHN  (B_*H_)     // 16
#define M_   (B_*T_)     // 8192
#define EPS_ 1e-6f
#define PB   72          // bf16 tile pitch (144B, conflict-free ldmatrix)

// ---------------- scratch ----------------------------------------------------
__device__ float g_cKV[BHN*NC*DH*DH];
__device__ float g_cZ [BHN*NC*DH];
__device__ __nv_bfloat16 g_xh[M_*D_],  g_xl[M_*D_];
__device__ __nv_bfloat16 g_Wth[4*D_*D_], g_Wtl[4*D_*D_];  // W^T [n][k]
__device__ __nv_bfloat16 g_Qh[M_*D_],  g_Ql[M_*D_];
__device__ __nv_bfloat16 g_Kh[M_*D_],  g_Kl[M_*D_];
__device__ __nv_bfloat16 g_Vh[M_*D_],  g_Vl[M_*D_];
__device__ __nv_bfloat16 g_yh[M_*D_],  g_yl[M_*D_];
__device__ __nv_bfloat16 g_Sph[BHN*NC*DH*DH], g_Spl[BHN*NC*DH*DH];

// ---------------- PTX helpers (baseline features only) -----------------------
__device__ __forceinline__ uint32_t smem_u32(const void* p) {
    uint32_t a;
    asm("{ .reg .u64 t; cvta.to.shared.u64 t, %1; cvt.u32.u64 %0, t; }"
        : "=r"(a) : "l"(p));
    return a;
}
__device__ __forceinline__ void ldsm4(uint32_t* r, uint32_t addr) {
    asm volatile("ldmatrix.sync.aligned.m8n8.x4.shared.b16 {%0,%1,%2,%3}, [%4];"
        : "=r"(r[0]), "=r"(r[1]), "=r"(r[2]), "=r"(r[3]) : "r"(addr));
}
__device__ __forceinline__ void ldsm4t(uint32_t* r, uint32_t addr) {
    asm volatile("ldmatrix.sync.aligned.m8n8.x4.trans.shared.b16 {%0,%1,%2,%3}, [%4];"
        : "=r"(r[0]), "=r"(r[1]), "=r"(r[2]), "=r"(r[3]) : "r"(addr));
}
__device__ __forceinline__ void mma_bf16(float* c, const uint32_t* a,
                                         uint32_t b0, uint32_t b1) {
    asm volatile(
        "mma.sync.aligned.m16n8k16.row.col.f32.bf16.bf16.f32 "
        "{%0,%1,%2,%3}, {%4,%5,%6,%7}, {%8,%9}, {%0,%1,%2,%3};"
        : "+f"(c[0]), "+f"(c[1]), "+f"(c[2]), "+f"(c[3])
        : "r"(a[0]), "r"(a[1]), "r"(a[2]), "r"(a[3]), "r"(b0), "r"(b1));
}
// split two floats into packed bf16 hi / lo pairs
__device__ __forceinline__ void split2(float a, float b, uint32_t& h, uint32_t& l) {
    __nv_bfloat16 ha = __float2bfloat16_rn(a);
    __nv_bfloat16 hb = __float2bfloat16_rn(b);
    __nv_bfloat162 hv; hv.x = ha; hv.y = hb;
    __nv_bfloat162 lv;
    lv.x = __float2bfloat16_rn(a - __bfloat162float(ha));
    lv.y = __float2bfloat16_rn(b - __bfloat162float(hb));
    h = *(uint32_t*)&hv; l = *(uint32_t*)&lv;
}

// ---------------- conversion kernels -----------------------------------------
__global__ __launch_bounds__(256)
void split_kernel(const float* __restrict__ in,
                  __nv_bfloat16* __restrict__ oh,
                  __nv_bfloat16* __restrict__ ol) {
    int idx = blockIdx.x * 256 + threadIdx.x;
    float4 v = *(const float4*)(in + (size_t)idx * 4);
    float a[4] = {v.x, v.y, v.z, v.w};
#pragma unroll
    for (int j = 0; j < 4; j++) {
        __nv_bfloat16 h = __float2bfloat16_rn(a[j]);
        __nv_bfloat16 l = __float2bfloat16_rn(a[j] - __bfloat162float(h));
        oh[(size_t)idx * 4 + j] = h;
        ol[(size_t)idx * 4 + j] = l;
    }
}

__global__ __launch_bounds__(256)
void wt_kernel(const float* __restrict__ Wq, const float* __restrict__ Wk,
               const float* __restrict__ Wv, const float* __restrict__ Wo) {
    __shared__ float s[32][33];
    const int n0 = blockIdx.x * 32, k0 = blockIdx.y * 32, z = blockIdx.z;
    const float* W = (z == 0) ? Wq : (z == 1) ? Wk : (z == 2) ? Wv : Wo;
    const int tx = threadIdx.x, ty = threadIdx.y;
#pragma unroll
    for (int r = 0; r < 4; r++) {
        int k = k0 + ty + r * 8;
        s[ty + r * 8][tx] = W[(size_t)k * D_ + n0 + tx];
    }
    __syncthreads();
#pragma unroll
    for (int r = 0; r < 4; r++) {
        int n = n0 + ty + r * 8;
        float v = s[tx][ty + r * 8];
        __nv_bfloat16 h = __float2bfloat16_rn(v);
        __nv_bfloat16 l = __float2bfloat16_rn(v - __bfloat162float(h));
        size_t o = (size_t)z * D_ * D_ + (size_t)n * D_ + k0 + tx;
        g_Wth[o] = h;
        g_Wtl[o] = l;
    }
}

// ---------------- HMMA bf16-split GEMM ---------------------------------------
#define APITCH 72
#define GEMM_SMEM (4 * 128 * APITCH * 2)

__global__ __launch_bounds__(256)
void hmma_gemm_kernel(const __nv_bfloat16* __restrict__ Ah,
                      const __nv_bfloat16* __restrict__ Al,
                      const float* __restrict__ b0, const float* __restrict__ b1,
                      const float* __restrict__ b2,
                      float* __restrict__ dout, int mode) {
    extern __shared__ __nv_bfloat16 sm2[];
    __nv_bfloat16* sAh = sm2;
    __nv_bfloat16* sAl = sm2 + 128 * APITCH;
    __nv_bfloat16* sBh = sm2 + 2 * 128 * APITCH;
    __nv_bfloat16* sBl = sm2 + 3 * 128 * APITCH;

    const int tid = threadIdx.x, lane = tid & 31, wid = tid >> 5;
    const int warp_m = wid >> 2, warp_n = wid & 3;
    const int n0 = blockIdx.x * 128, row0 = blockIdx.y * 128;
    const int zy = blockIdx.z;
    const int z = (mode == 0) ? zy : 3;
    const float* bias = (mode == 0) ? ((zy == 0) ? b0 : (zy == 1) ? b1 : b2) : b0;
    const int feat = (mode == 0) && (zy < 2);
    const __nv_bfloat16* Bh = g_Wth + (size_t)z * D_ * D_;
    const __nv_bfloat16* Bl = g_Wtl + (size_t)z * D_ * D_;

    float acc[4][4][4];
#pragma unroll
    for (int mt = 0; mt < 4; mt++)
#pragma unroll
        for (int nt = 0; nt < 4; nt++)
#pragma unroll
            for (int r = 0; r < 4; r++) acc[mt][nt][r] = 0.f;

    const int i4 = lane >> 3, r8 = lane & 7;
    const int a_row = warp_m * 64 + (i4 & 1) * 8 + r8;
    const int a_ku  = (i4 >> 1);
    const int b_row = warp_n * 32 + (i4 >> 1) * 8 + r8;
    const int b_ku  = (i4 & 1);

    for (int kc = 0; kc < 4; kc++) {
#pragma unroll
        for (int i = 0; i < 4; i++) {
            int idx = tid + i * 256;
            int r = idx >> 3, u = idx & 7;
            size_t ga = (size_t)(row0 + r) * D_ + kc * 64 + u * 8;
            size_t gb = (size_t)(n0 + r) * D_ + kc * 64 + u * 8;
            *(uint4*)(sAh + r * APITCH + u * 8) = *(const uint4*)(Ah + ga);
            *(uint4*)(sAl + r * APITCH + u * 8) = *(const uint4*)(Al + ga);
            *(uint4*)(sBh + r * APITCH + u * 8) = *(const uint4*)(Bh + gb);
            *(uint4*)(sBl + r * APITCH + u * 8) = *(const uint4*)(Bl + gb);
        }
        __syncthreads();

#pragma unroll
        for (int ks = 0; ks < 4; ks++) {
            const int au = (ks * 2 + a_ku) * 8;
            const int bu = (ks * 2 + b_ku) * 8;
            uint32_t afr[4][4], bhf[2][4], blf[2][4];
#pragma unroll
            for (int mt = 0; mt < 4; mt++)
                ldsm4(afr[mt], smem_u32(sAh + (a_row + mt * 16) * APITCH + au));
#pragma unroll
            for (int pt = 0; pt < 2; pt++) {
                ldsm4(bhf[pt], smem_u32(sBh + (b_row + pt * 16) * APITCH + bu));
                ldsm4(blf[pt], smem_u32(sBl + (b_row + pt * 16) * APITCH + bu));
            }
#pragma unroll
            for (int mt = 0; mt < 4; mt++)
#pragma unroll
                for (int nt = 0; nt < 4; nt++) {
                    int pt = nt >> 1, sub = (nt & 1) * 2;
                    mma_bf16(acc[mt][nt], afr[mt], bhf[pt][sub], bhf[pt][sub + 1]);
                    mma_bf16(acc[mt][nt], afr[mt], blf[pt][sub], blf[pt][sub + 1]);
                }
#pragma unroll
            for (int mt = 0; mt < 4; mt++)
                ldsm4(afr[mt], smem_u32(sAl + (a_row + mt * 16) * APITCH + au));
#pragma unroll
            for (int mt = 0; mt < 4; mt++)
#pragma unroll
                for (int nt = 0; nt < 4; nt++) {
                    int pt = nt >> 1, sub = (nt & 1) * 2;
                    mma_bf16(acc[mt][nt], afr[mt], bhf[pt][sub], bhf[pt][sub + 1]);
                }
        }
        __syncthreads();
    }

    // epilogue
    __nv_bfloat16* Oh = nullptr;
    __nv_bfloat16* Ol = nullptr;
    if (mode == 0) {
        Oh = (zy == 0) ? g_Qh : (zy == 1) ? g_Kh : g_Vh;
        Ol = (zy == 0) ? g_Ql : (zy == 1) ? g_Kl : g_Vl;
    }
    const int er = (lane >> 2), ec = (lane & 3) * 2;
#pragma unroll
    for (int mt = 0; mt < 4; mt++) {
        int r = row0 + warp_m * 64 + mt * 16 + er;
#pragma unroll
        for (int nt = 0; nt < 4; nt++) {
            int c = n0 + warp_n * 32 + nt * 8 + ec;
            float2 bv = *(const float2*)(bias + c);
            float o0x = acc[mt][nt][0] + bv.x, o0y = acc[mt][nt][1] + bv.y;
            float o1x = acc[mt][nt][2] + bv.x, o1y = acc[mt][nt][3] + bv.y;
            if (feat) {
                o0x = (o0x > 0.f) ? (o0x + 1.f) : __expf(o0x);
                o0y = (o0y > 0.f) ? (o0y + 1.f) : __expf(o0y);
                o1x = (o1x > 0.f) ? (o1x + 1.f) : __expf(o1x);
                o1y = (o1y > 0.f) ? (o1y + 1.f) : __expf(o1y);
            }
            if (mode == 0) {
                uint32_t h, l;
                split2(o0x, o0y, h, l);
                *(uint32_t*)&Oh[(size_t)r * D_ + c] = h;
                *(uint32_t*)&Ol[(size_t)r * D_ + c] = l;
                split2(o1x, o1y, h, l);
                *(uint32_t*)&Oh[(size_t)(r + 8) * D_ + c] = h;
                *(uint32_t*)&Ol[(size_t)(r + 8) * D_ + c] = l;
            } else {
                float2 a0 = {o0x, o0y}, a1 = {o1x, o1y};
                *(float2*)(dout + (size_t)r * D_ + c) = a0;
                *(float2*)(dout + (size_t)(r + 8) * D_ + c) = a1;
            }
        }
    }
}

// ---------------- per-chunk KV / Z sums via HMMA ------------------------------
__global__ __launch_bounds__(128)
void chunksum_h() {
    __shared__ __nv_bfloat16 sK[2][C_ * PB];   // hi, lo
    __shared__ __nv_bfloat16 sV[2][C_ * PB];
    const int chunk = blockIdx.x, bh = blockIdx.y;
    const int b = bh >> 2, h = bh & 3;
    const int tid = threadIdx.x, lane = tid & 31, wid = tid >> 5;
    const size_t base = (size_t)(b * T_ + chunk * C_) * D_ + h * DH;

#pragma unroll
    for (int i = 0; i < 4; i++) {
        int idx = tid + i * 128;
        int r = idx >> 3, u = idx & 7;
        size_t g = base + (size_t)r * D_ + u * 8;
        *(uint4*)&sK[0][r * PB + u * 8] = *(const uint4*)(g_Kh + g);
        *(uint4*)&sK[1][r * PB + u * 8] = *(const uint4*)(g_Kl + g);
        *(uint4*)&sV[0][r * PB + u * 8] = *(const uint4*)(g_Vh + g);
        *(uint4*)&sV[1][r * PB + u * 8] = *(const uint4*)(g_Vl + g);
    }
    __syncthreads();

    const int i4 = lane >> 3, r8 = lane & 7;
    const int d0 = wid * 16;
    float acc[8][4];
#pragma unroll
    for (int a = 0; a < 8; a++)
#pragma unroll
        for (int r = 0; r < 4; r++) acc[a][r] = 0.f;

#pragma unroll
    for (int p = 0; p < 3; p++) {
        const __nv_bfloat16* A = sK[p == 2 ? 1 : 0];
        const __nv_bfloat16* Bv = sV[p == 1 ? 1 : 0];
#pragma unroll
        for (int ks = 0; ks < 4; ks++) {
            uint32_t af[4];
            ldsm4t(af, smem_u32(A + (ks * 16 + (i4 >> 1) * 8 + r8) * PB
                                + d0 + (i4 & 1) * 8));
#pragma unroll
            for (int ng = 0; ng < 4; ng++) {
                uint32_t bf[4];
                ldsm4t(bf, smem_u32(Bv + (ks * 16 + (i4 & 1) * 8 + r8) * PB
                                    + ng * 16 + (i4 >> 1) * 8));
                mma_bf16(acc[ng * 2], af, bf[0], bf[1]);
                mma_bf16(acc[ng * 2 + 1], af, bf[2], bf[3]);
            }
        }
    }

    const int er = lane >> 2, ec = (lane & 3) * 2;
    size_t ob = (size_t)(bh * NC + chunk) * DH;
#pragma unroll
    for (int a = 0; a < 8; a++) {
        int m = a * 8 + ec;
        float2 c0 = {acc[a][0], acc[a][1]};
        float2 c1 = {acc[a][2], acc[a][3]};
        *(float2*)&g_cKV[(ob + d0 + er) * DH + m] = c0;
        *(float2*)&g_cKV[(ob + d0 + er + 8) * DH + m] = c1;
    }
    if (tid < DH) {
        float zv = 0.f;
        for (int s = 0; s < C_; s++)
            zv += __bfloat162float(sK[0][s * PB + tid])
                + __bfloat162float(sK[1][s * PB + tid]);
        g_cZ[ob + tid] = zv;
    }
}

// ---------------- exclusive prefix (writes Sp as bf16 hi/lo) ------------------
__global__ __launch_bounds__(256)
void prefix_kernel() {
    const int bh = blockIdx.x, tid = threadIdx.x;
    float4 run[4];
#pragma unroll
    for (int j = 0; j < 4; j++) run[j] = make_float4(0.f, 0.f, 0.f, 0.f);
    float zrun = 0.f;
    for (int c = 0; c < NC; c++) {
        size_t base = (size_t)(bh * NC + c) * (DH * DH) + (size_t)tid * 16;
#pragma unroll
        for (int j = 0; j < 4; j++) {
            float4 t = *(float4*)(g_cKV + base + j * 4);
            uint32_t h0, l0, h1, l1;
            split2(run[j].x, run[j].y, h0, l0);
            split2(run[j].z, run[j].w, h1, l1);
            *(uint32_t*)&g_Sph[base + j * 4]     = h0;
            *(uint32_t*)&g_Sph[base + j * 4 + 2] = h1;
            *(uint32_t*)&g_Spl[base + j * 4]     = l0;
            *(uint32_t*)&g_Spl[base + j * 4 + 2] = l1;
            run[j].x += t.x; run[j].y += t.y; run[j].z += t.z; run[j].w += t.w;
        }
        if (tid < DH) {
            float* zp = g_cZ + (size_t)(bh * NC + c) * DH + tid;
            float t = *zp; *zp = zrun; zrun += t;
        }
    }
}

// ---------------- per-chunk output via HMMA -----------------------------------
#define TILEB (C_ * PB)
#define COSM  (10 * TILEB * 2 + 2 * 64 * 4)

__global__ __launch_bounds__(128)
void chunk_out_h() {
    extern __shared__ __nv_bfloat16 smc[];
    __nv_bfloat16* sQh = smc;
    __nv_bfloat16* sQl = smc + 1 * TILEB;
    __nv_bfloat16* sKh = smc + 2 * TILEB;
    __nv_bfloat16* sKl = smc + 3 * TILEB;
    __nv_bfloat16* sVh = smc + 4 * TILEB;
    __nv_bfloat16* sVl = smc + 5 * TILEB;
    __nv_bfloat16* sPh = smc + 6 * TILEB;
    __nv_bfloat16* sPl = smc + 7 * TILEB;
    __nv_bfloat16* sSh = smc + 8 * TILEB;
    __nv_bfloat16* sSl = smc + 9 * TILEB;
    float* sZp  = (float*)(smc + 10 * TILEB);
    float* sDen = sZp + 64;

    const int chunk = blockIdx.x, bh = blockIdx.y;
    const int b = bh >> 2, h = bh & 3;
    const int tid = threadIdx.x, lane = tid & 31, wid = tid >> 5;
    const size_t grow = (size_t)(b * T_ + chunk * C_);
    const size_t spbase = (size_t)(bh * NC + chunk) * (DH * DH);

#pragma unroll
    for (int i = 0; i < 4; i++) {
        int idx = tid + i * 128;
        int r = idx >> 3, u = idx & 7;
        size_t g = (grow + r) * D_ + h * DH + u * 8;
        *(uint4*)&sQh[r * PB + u * 8] = *(const uint4*)(g_Qh + g);
        *(uint4*)&sQl[r * PB + u * 8] = *(const uint4*)(g_Ql + g);
        *(uint4*)&sKh[r * PB + u * 8] = *(const uint4*)(g_Kh + g);
        *(uint4*)&sKl[r * PB + u * 8] = *(const uint4*)(g_Kl + g);
        *(uint4*)&sVh[r * PB + u * 8] = *(const uint4*)(g_Vh + g);
        *(uint4*)&sVl[r * PB + u * 8] = *(const uint4*)(g_Vl + g);
        size_t sp = spbase + (size_t)r * DH + u * 8;
        *(uint4*)&sPh[r * PB + u * 8] = *(const uint4*)(g_Sph + sp);
        *(uint4*)&sPl[r * PB + u * 8] = *(const uint4*)(g_Spl + sp);
    }
    if (tid < DH) sZp[tid] = g_cZ[(size_t)(bh * NC + chunk) * DH + tid];
    __syncthreads();

    const int i4 = lane >> 3, r8 = lane & 7;
    const int t0 = wid * 16;
    const int er = lane >> 2, ec = (lane & 3) * 2;
    const int tA = t0 + er, tB = tA + 8;

    // ---- S = Q K^T (3-pass split) ----
    float accS[8][4];
#pragma unroll
    for (int a = 0; a < 8; a++)
#pragma unroll
        for (int r = 0; r < 4; r++) accS[a][r] = 0.f;
#pragma unroll
    for (int p = 0; p < 3; p++) {
        const __nv_bfloat16* A  = (p == 2) ? sQl : sQh;
        const __nv_bfloat16* Bk = (p == 1) ? sKl : sKh;
#pragma unroll
        for (int ks = 0; ks < 4; ks++) {
            uint32_t af[4];
            ldsm4(af, smem_u32(A + (t0 + (i4 & 1) * 8 + r8) * PB
                               + ks * 16 + (i4 >> 1) * 8));
#pragma unroll
            for (int ng = 0; ng < 4; ng++) {
                uint32_t bf[4];
                ldsm4(bf, smem_u32(Bk + (ng * 16 + (i4 >> 1) * 8 + r8) * PB
                                   + ks * 16 + (i4 & 1) * 8));
                mma_bf16(accS[ng * 2], af, bf[0], bf[1]);
                mma_bf16(accS[ng * 2 + 1], af, bf[2], bf[3]);
            }
        }
    }

    // ---- mask, row-sum, split S -> smem ----
    float rsA = 0.f, rsB = 0.f;
#pragma unroll
    for (int a = 0; a < 8; a++) {
        int s0 = a * 8 + ec;
        float c0 = (s0     <= tA) ? accS[a][0] : 0.f;
        float c1 = (s0 + 1 <= tA) ? accS[a][1] : 0.f;
        float c2 = (s0     <= tB) ? accS[a][2] : 0.f;
        float c3 = (s0 + 1 <= tB) ? accS[a][3] : 0.f;
        rsA += c0 + c1; rsB += c2 + c3;
        uint32_t hh, ll;
        split2(c0, c1, hh, ll);
        *(uint32_t*)&sSh[tA * PB + s0] = hh;
        *(uint32_t*)&sSl[tA * PB + s0] = ll;
        split2(c2, c3, hh, ll);
        *(uint32_t*)&sSh[tB * PB + s0] = hh;
        *(uint32_t*)&sSl[tB * PB + s0] = ll;
    }
    rsA += __shfl_xor_sync(0xFFFFFFFF, rsA, 1);
    rsA += __shfl_xor_sync(0xFFFFFFFF, rsA, 2);
    rsB += __shfl_xor_sync(0xFFFFFFFF, rsB, 1);
    rsB += __shfl_xor_sync(0xFFFFFFFF, rsB, 2);
    if ((lane & 3) == 0) { sDen[tA] = rsA; sDen[tB] = rsB; }
    __syncthreads();

    // ---- denominators: += Q . Zp + EPS ----
    if (tid < C_) {
        float qz = 0.f;
#pragma unroll
        for (int d = 0; d < DH; d += 2) {
            __nv_bfloat162 hv = *(__nv_bfloat162*)&sQh[tid * PB + d];
            __nv_bfloat162 lv = *(__nv_bfloat162*)&sQl[tid * PB + d];
            qz += (__bfloat162float(hv.x) + __bfloat162float(lv.x)) * sZp[d]
                + (__bfloat162float(hv.y) + __bfloat162float(lv.y)) * sZp[d + 1];
        }
        sDen[tid] += qz + EPS_;
    }
    __syncthreads();

    // ---- O = S@V + Q@Sp (6 passes) ----
    float accO[8][4];
#pragma unroll
    for (int a = 0; a < 8; a++)
#pragma unroll
        for (int r = 0; r < 4; r++) accO[a][r] = 0.f;
#pragma unroll
    for (int p = 0; p < 6; p++) {
        const __nv_bfloat16* A  = (p == 0 || p == 1) ? sSh
                                : (p == 2) ? sSl
                                : (p == 5) ? sQl : sQh;
        const __nv_bfloat16* Bt = (p == 0 || p == 2) ? sVh
                                : (p == 1) ? sVl
                                : (p == 4) ? sPl : sPh;
#pragma unroll
        for (int ks = 0; ks < 4; ks++) {
            uint32_t af[4];
            ldsm4(af, smem_u32(A + (t0 + (i4 & 1) * 8 + r8) * PB
                               + ks * 16 + (i4 >> 1) * 8));
#pragma unroll
            for (int ng = 0; ng < 4; ng++) {
                uint32_t bf[4];
                ldsm4t(bf, smem_u32(Bt + (ks * 16 + (i4 & 1) * 8 + r8) * PB
                                    + ng * 16 + (i4 >> 1) * 8));
                mma_bf16(accO[ng * 2], af, bf[0], bf[1]);
                mma_bf16(accO[ng * 2 + 1], af, bf[2], bf[3]);
            }
        }
    }

    // ---- divide + write y as bf16 hi/lo ----
    const float invA = 1.f / sDen[tA];
    const float invB = 1.f / sDen[tB];
#pragma unroll
    for (int a = 0; a < 8; a++) {
        int c = a * 8 + ec;
        size_t gA = (grow + tA) * D_ + h * DH + c;
        size_t gB = (grow + tB) * D_ + h * DH + c;
        uint32_t hh, ll;
        split2(accO[a][0] * invA, accO[a][1] * invA, hh, ll);
        *(uint32_t*)&g_yh[gA] = hh;
        *(uint32_t*)&g_yl[gA] = ll;
        split2(accO[a][2] * invB, accO[a][3] * invB, hh, ll);
        *(uint32_t*)&g_yh[gB] = hh;
        *(uint32_t*)&g_yl[gB] = ll;
    }
}

// ---------------- launch -----------------------------------------------------
extern "C" void kernel_launch(void* const* d_in, const int* in_sizes, int n_in,
                              void* d_out, int out_size) {
    const float* x  = (const float*)d_in[0];
    const float* Wq = (const float*)d_in[1];
    const float* bq = (const float*)d_in[2];
    const float* Wk = (const float*)d_in[3];
    const float* bk = (const float*)d_in[4];
    const float* Wv = (const float*)d_in[5];
    const float* bv = (const float*)d_in[6];
    const float* Wo = (const float*)d_in[7];
    const float* bo = (const float*)d_in[8];
    float* out = (float*)d_out;

    cudaFuncSetAttribute(hmma_gemm_kernel,
                         cudaFuncAttributeMaxDynamicSharedMemorySize, GEMM_SMEM);
    cudaFuncSetAttribute(chunk_out_h,
                         cudaFuncAttributeMaxDynamicSharedMemorySize, COSM);

    __nv_bfloat16 *xh, *xl, *yh, *yl;
    cudaGetSymbolAddress((void**)&xh, g_xh);
    cudaGetSymbolAddress((void**)&xl, g_xl);
    cudaGetSymbolAddress((void**)&yh, g_yh);
    cudaGetSymbolAddress((void**)&yl, g_yl);

    split_kernel<<<M_ * D_ / 1024, 256>>>(x, xh, xl);
    wt_kernel<<<dim3(8, 8, 4), dim3(32, 8)>>>(Wq, Wk, Wv, Wo);

    hmma_gemm_kernel<<<dim3(2, 64, 3), 256, GEMM_SMEM>>>(xh, xl, bq, bk, bv,
                                                         nullptr, 0);

    chunksum_h<<<dim3(NC, BHN), 128>>>();
    prefix_kernel<<<BHN, 256>>>();
    chunk_out_h<<<dim3(NC, BHN), 128, COSM>>>();

    hmma_gemm_kernel<<<dim3(2, 64, 1), 256, GEMM_SMEM>>>(yh, yl, bo, bo, bo,
                                                         out, 1);
}

// round 9
// speedup vs baseline: 3.2979x; 1.1897x over previous
#include <cuda_runtime.h>
#include <cuda_fp16.h>
#include <stdint.h>
#include <math.h>

#define B_   4
#define T_   2048
#define D_   256
#define H_   4
#define DH   64
#define C_   64
#define NC   (T_/C_)     // 32
#define BHN  (B_*H_)     // 16
#define M_   (B_*T_)     // 8192
#define EPS_ 1e-6f
#define PB   72          // fp16 tile pitch (144B, conflict-free ldmatrix)

// ---------------- scratch ----------------------------------------------------
__device__ float g_cKV[BHN*NC*DH*DH];
__device__ float g_cZ [BHN*NC*DH];
__device__ __half g_x16[M_*D_];
__device__ __half g_Wh[4*D_*D_], g_Wl[4*D_*D_];    // W^T [n][k] hi/lo
__device__ __half g_Q16[M_*D_];
__device__ __half g_Kh[M_*D_],  g_Kl[M_*D_];
__device__ __half g_Vh[M_*D_],  g_Vl[M_*D_];
__device__ __half g_y16[M_*D_];
__device__ __half g_Sph[BHN*NC*DH*DH], g_Spl[BHN*NC*DH*DH];

// ---------------- PTX helpers -------------------------------------------------
__device__ __forceinline__ uint32_t smem_u32(const void* p) {
    uint32_t a;
    asm("{ .reg .u64 t; cvta.to.shared.u64 t, %1; cvt.u32.u64 %0, t; }"
        : "=r"(a) : "l"(p));
    return a;
}
__device__ __forceinline__ void ldsm4(uint32_t* r, uint32_t addr) {
    asm volatile("ldmatrix.sync.aligned.m8n8.x4.shared.b16 {%0,%1,%2,%3}, [%4];"
        : "=r"(r[0]), "=r"(r[1]), "=r"(r[2]), "=r"(r[3]) : "r"(addr));
}
__device__ __forceinline__ void ldsm4t(uint32_t* r, uint32_t addr) {
    asm volatile("ldmatrix.sync.aligned.m8n8.x4.trans.shared.b16 {%0,%1,%2,%3}, [%4];"
        : "=r"(r[0]), "=r"(r[1]), "=r"(r[2]), "=r"(r[3]) : "r"(addr));
}
__device__ __forceinline__ void mma_f16(float* c, const uint32_t* a,
                                        uint32_t b0, uint32_t b1) {
    asm volatile(
        "mma.sync.aligned.m16n8k16.row.col.f32.f16.f16.f32 "
        "{%0,%1,%2,%3}, {%4,%5,%6,%7}, {%8,%9}, {%0,%1,%2,%3};"
        : "+f"(c[0]), "+f"(c[1]), "+f"(c[2]), "+f"(c[3])
        : "r"(a[0]), "r"(a[1]), "r"(a[2]), "r"(a[3]), "r"(b0), "r"(b1));
}
__device__ __forceinline__ uint32_t pack_h2(float a, float b) {
    __half2 v = __floats2half2_rn(a, b);
    return *(uint32_t*)&v;
}
__device__ __forceinline__ void split2h(float a, float b, uint32_t& h, uint32_t& l) {
    __half ha = __float2half_rn(a);
    __half hb = __float2half_rn(b);
    __half2 hv; hv.x = ha; hv.y = hb;
    __half2 lv;
    lv.x = __float2half_rn(a - __half2float(ha));
    lv.y = __float2half_rn(b - __half2float(hb));
    h = *(uint32_t*)&hv; l = *(uint32_t*)&lv;
}

// ---------------- conversion kernels ------------------------------------------
__global__ __launch_bounds__(256)
void cvt_kernel(const float* __restrict__ in, __half* __restrict__ o16) {
    int idx = blockIdx.x * 256 + threadIdx.x;
    float4 v = *(const float4*)(in + (size_t)idx * 4);
    uint2 o;
    o.x = pack_h2(v.x, v.y);
    o.y = pack_h2(v.z, v.w);
    *(uint2*)(o16 + (size_t)idx * 4) = o;
}

__global__ __launch_bounds__(256)
void wt_kernel(const float* __restrict__ Wq, const float* __restrict__ Wk,
               const float* __restrict__ Wv, const float* __restrict__ Wo) {
    __shared__ float s[32][33];
    const int n0 = blockIdx.x * 32, k0 = blockIdx.y * 32, z = blockIdx.z;
    const float* W = (z == 0) ? Wq : (z == 1) ? Wk : (z == 2) ? Wv : Wo;
    const int tx = threadIdx.x, ty = threadIdx.y;
#pragma unroll
    for (int r = 0; r < 4; r++) {
        int k = k0 + ty + r * 8;
        s[ty + r * 8][tx] = W[(size_t)k * D_ + n0 + tx];
    }
    __syncthreads();
#pragma unroll
    for (int r = 0; r < 4; r++) {
        int n = n0 + ty + r * 8;
        float v = s[tx][ty + r * 8];
        __half h = __float2half_rn(v);
        __half l = __float2half_rn(v - __half2float(h));
        size_t o = (size_t)z * D_ * D_ + (size_t)n * D_ + k0 + tx;
        g_Wh[o] = h;
        g_Wl[o] = l;
    }
}

// ---------------- HMMA fp16 asymmetric-split GEMM -----------------------------
// C = f(A @ W + b):  A fp16 (rounded), W^T split hi/lo -> 2 passes.
#define APITCH 72
#define GEMM_SMEM (3 * 128 * APITCH * 2)

__global__ __launch_bounds__(256, 2)
void hmma_gemm_kernel(const __half* __restrict__ A16,
                      const float* __restrict__ b0, const float* __restrict__ b1,
                      const float* __restrict__ b2,
                      float* __restrict__ dout, int mode) {
    extern __shared__ __half sm2[];
    __half* sA  = sm2;
    __half* sBh = sm2 + 128 * APITCH;
    __half* sBl = sm2 + 2 * 128 * APITCH;

    const int tid = threadIdx.x, lane = tid & 31, wid = tid >> 5;
    const int warp_m = wid >> 2, warp_n = wid & 3;
    const int n0 = blockIdx.x * 128, row0 = blockIdx.y * 128;
    const int zy = blockIdx.z;
    const int z = (mode == 0) ? zy : 3;
    const float* bias = (mode == 0) ? ((zy == 0) ? b0 : (zy == 1) ? b1 : b2) : b0;
    const int feat = (mode == 0) && (zy < 2);
    const __half* Bh = g_Wh + (size_t)z * D_ * D_;
    const __half* Bl = g_Wl + (size_t)z * D_ * D_;

    float acc[4][4][4];
#pragma unroll
    for (int mt = 0; mt < 4; mt++)
#pragma unroll
        for (int nt = 0; nt < 4; nt++)
#pragma unroll
            for (int r = 0; r < 4; r++) acc[mt][nt][r] = 0.f;

    const int i4 = lane >> 3, r8 = lane & 7;
    const int a_row = warp_m * 64 + (i4 & 1) * 8 + r8;
    const int a_ku  = (i4 >> 1);
    const int b_row = warp_n * 32 + (i4 >> 1) * 8 + r8;
    const int b_ku  = (i4 & 1);

    for (int kc = 0; kc < 4; kc++) {
#pragma unroll
        for (int i = 0; i < 4; i++) {
            int idx = tid + i * 256;           // 1024 16B-units per array
            int r = idx >> 3, u = idx & 7;
            size_t ga = (size_t)(row0 + r) * D_ + kc * 64 + u * 8;
            size_t gb = (size_t)(n0 + r) * D_ + kc * 64 + u * 8;
            *(uint4*)(sA  + r * APITCH + u * 8) = *(const uint4*)(A16 + ga);
            *(uint4*)(sBh + r * APITCH + u * 8) = *(const uint4*)(Bh + gb);
            *(uint4*)(sBl + r * APITCH + u * 8) = *(const uint4*)(Bl + gb);
        }
        __syncthreads();

#pragma unroll
        for (int ks = 0; ks < 4; ks++) {
            const int au = (ks * 2 + a_ku) * 8;
            const int bu = (ks * 2 + b_ku) * 8;
            uint32_t afr[4][4], bhf[2][4], blf[2][4];
#pragma unroll
            for (int mt = 0; mt < 4; mt++)
                ldsm4(afr[mt], smem_u32(sA + (a_row + mt * 16) * APITCH + au));
#pragma unroll
            for (int pt = 0; pt < 2; pt++) {
                ldsm4(bhf[pt], smem_u32(sBh + (b_row + pt * 16) * APITCH + bu));
                ldsm4(blf[pt], smem_u32(sBl + (b_row + pt * 16) * APITCH + bu));
            }
#pragma unroll
            for (int mt = 0; mt < 4; mt++)
#pragma unroll
                for (int nt = 0; nt < 4; nt++) {
                    int pt = nt >> 1, sub = (nt & 1) * 2;
                    mma_f16(acc[mt][nt], afr[mt], bhf[pt][sub], bhf[pt][sub + 1]);
                    mma_f16(acc[mt][nt], afr[mt], blf[pt][sub], blf[pt][sub + 1]);
                }
        }
        __syncthreads();
    }

    // epilogue
    const int er = (lane >> 2), ec = (lane & 3) * 2;
#pragma unroll
    for (int mt = 0; mt < 4; mt++) {
        int r = row0 + warp_m * 64 + mt * 16 + er;
#pragma unroll
        for (int nt = 0; nt < 4; nt++) {
            int c = n0 + warp_n * 32 + nt * 8 + ec;
            float2 bv = *(const float2*)(bias + c);
            float o0x = acc[mt][nt][0] + bv.x, o0y = acc[mt][nt][1] + bv.y;
            float o1x = acc[mt][nt][2] + bv.x, o1y = acc[mt][nt][3] + bv.y;
            if (feat) {
                o0x = (o0x > 0.f) ? (o0x + 1.f) : __expf(o0x);
                o0y = (o0y > 0.f) ? (o0y + 1.f) : __expf(o0y);
                o1x = (o1x > 0.f) ? (o1x + 1.f) : __expf(o1x);
                o1y = (o1y > 0.f) ? (o1y + 1.f) : __expf(o1y);
            }
            if (mode == 1) {
                float2 a0 = {o0x, o0y}, a1 = {o1x, o1y};
                *(float2*)(dout + (size_t)r * D_ + c) = a0;
                *(float2*)(dout + (size_t)(r + 8) * D_ + c) = a1;
            } else if (zy == 0) {           // Q: single fp16
                *(uint32_t*)&g_Q16[(size_t)r * D_ + c] = pack_h2(o0x, o0y);
                *(uint32_t*)&g_Q16[(size_t)(r + 8) * D_ + c] = pack_h2(o1x, o1y);
            } else {                        // K or V: hi/lo split
                __half* Oh = (zy == 1) ? g_Kh : g_Vh;
                __half* Ol = (zy == 1) ? g_Kl : g_Vl;
                uint32_t h, l;
                split2h(o0x, o0y, h, l);
                *(uint32_t*)&Oh[(size_t)r * D_ + c] = h;
                *(uint32_t*)&Ol[(size_t)r * D_ + c] = l;
                split2h(o1x, o1y, h, l);
                *(uint32_t*)&Oh[(size_t)(r + 8) * D_ + c] = h;
                *(uint32_t*)&Ol[(size_t)(r + 8) * D_ + c] = l;
            }
        }
    }
}

// ---------------- per-chunk KV / Z sums (K fp16, V hi/lo -> 2 passes) ---------
__global__ __launch_bounds__(128)
void chunksum_h() {
    __shared__ __half sK [C_ * PB];
    __shared__ __half sVh[C_ * PB];
    __shared__ __half sVl[C_ * PB];
    const int chunk = blockIdx.x, bh = blockIdx.y;
    const int b = bh >> 2, h = bh & 3;
    const int tid = threadIdx.x, lane = tid & 31, wid = tid >> 5;
    const size_t base = (size_t)(b * T_ + chunk * C_) * D_ + h * DH;

#pragma unroll
    for (int i = 0; i < 4; i++) {
        int idx = tid + i * 128;               // 512 units
        int r = idx >> 3, u = idx & 7;
        size_t g = base + (size_t)r * D_ + u * 8;
        *(uint4*)&sK [r * PB + u * 8] = *(const uint4*)(g_Kh + g);
        *(uint4*)&sVh[r * PB + u * 8] = *(const uint4*)(g_Vh + g);
        *(uint4*)&sVl[r * PB + u * 8] = *(const uint4*)(g_Vl + g);
    }
    __syncthreads();

    const int i4 = lane >> 3, r8 = lane & 7;
    const int d0 = wid * 16;
    float acc[8][4];
#pragma unroll
    for (int a = 0; a < 8; a++)
#pragma unroll
        for (int r = 0; r < 4; r++) acc[a][r] = 0.f;

#pragma unroll
    for (int ks = 0; ks < 4; ks++) {
        uint32_t af[4];
        ldsm4t(af, smem_u32(sK + (ks * 16 + (i4 >> 1) * 8 + r8) * PB
                            + d0 + (i4 & 1) * 8));
#pragma unroll
        for (int p = 0; p < 2; p++) {
            const __half* Bv = p ? sVl : sVh;
#pragma unroll
            for (int ng = 0; ng < 4; ng++) {
                uint32_t bf[4];
                ldsm4t(bf, smem_u32(Bv + (ks * 16 + (i4 & 1) * 8 + r8) * PB
                                    + ng * 16 + (i4 >> 1) * 8));
                mma_f16(acc[ng * 2], af, bf[0], bf[1]);
                mma_f16(acc[ng * 2 + 1], af, bf[2], bf[3]);
            }
        }
    }

    const int er = lane >> 2, ec = (lane & 3) * 2;
    size_t ob = (size_t)(bh * NC + chunk) * DH;
#pragma unroll
    for (int a = 0; a < 8; a++) {
        int m = a * 8 + ec;
        float2 c0 = {acc[a][0], acc[a][1]};
        float2 c1 = {acc[a][2], acc[a][3]};
        *(float2*)&g_cKV[(ob + d0 + er) * DH + m] = c0;
        *(float2*)&g_cKV[(ob + d0 + er + 8) * DH + m] = c1;
    }
    if (tid < DH) {
        float zv = 0.f;
        for (int s = 0; s < C_; s++)
            zv += __half2float(sK[s * PB + tid]);
        g_cZ[ob + tid] = zv;
    }
}

// ---------------- exclusive prefix (writes Sp as fp16 hi/lo) ------------------
__global__ __launch_bounds__(256)
void prefix_kernel() {
    const int bh = blockIdx.x, tid = threadIdx.x;
    float4 run[4];
#pragma unroll
    for (int j = 0; j < 4; j++) run[j] = make_float4(0.f, 0.f, 0.f, 0.f);
    float zrun = 0.f;
    for (int c = 0; c < NC; c++) {
        size_t base = (size_t)(bh * NC + c) * (DH * DH) + (size_t)tid * 16;
#pragma unroll
        for (int j = 0; j < 4; j++) {
            float4 t = *(float4*)(g_cKV + base + j * 4);
            uint32_t h0, l0, h1, l1;
            split2h(run[j].x, run[j].y, h0, l0);
            split2h(run[j].z, run[j].w, h1, l1);
            *(uint32_t*)&g_Sph[base + j * 4]     = h0;
            *(uint32_t*)&g_Sph[base + j * 4 + 2] = h1;
            *(uint32_t*)&g_Spl[base + j * 4]     = l0;
            *(uint32_t*)&g_Spl[base + j * 4 + 2] = l1;
            run[j].x += t.x; run[j].y += t.y; run[j].z += t.z; run[j].w += t.w;
        }
        if (tid < DH) {
            float* zp = g_cZ + (size_t)(bh * NC + c) * DH + tid;
            float t = *zp; *zp = zrun; zrun += t;
        }
    }
}

// ---------------- per-chunk output (fp16, 2+4 passes) -------------------------
#define TILEH (C_ * PB)
#define COSM  (8 * TILEH * 2 + 2 * 64 * 4)

__global__ __launch_bounds__(128)
void chunk_out_h() {
    extern __shared__ __half smc[];
    __half* sQ  = smc;
    __half* sKh = smc + 1 * TILEH;
    __half* sKl = smc + 2 * TILEH;
    __half* sVh = smc + 3 * TILEH;
    __half* sVl = smc + 4 * TILEH;
    __half* sPh = smc + 5 * TILEH;
    __half* sPl = smc + 6 * TILEH;
    __half* sS  = smc + 7 * TILEH;
    float* sZp  = (float*)(smc + 8 * TILEH);
    float* sDen = sZp + 64;

    const int chunk = blockIdx.x, bh = blockIdx.y;
    const int b = bh >> 2, h = bh & 3;
    const int tid = threadIdx.x, lane = tid & 31, wid = tid >> 5;
    const size_t grow = (size_t)(b * T_ + chunk * C_);
    const size_t spbase = (size_t)(bh * NC + chunk) * (DH * DH);

#pragma unroll
    for (int i = 0; i < 4; i++) {
        int idx = tid + i * 128;
        int r = idx >> 3, u = idx & 7;
        size_t g = (grow + r) * D_ + h * DH + u * 8;
        *(uint4*)&sQ [r * PB + u * 8] = *(const uint4*)(g_Q16 + g);
        *(uint4*)&sKh[r * PB + u * 8] = *(const uint4*)(g_Kh + g);
        *(uint4*)&sKl[r * PB + u * 8] = *(const uint4*)(g_Kl + g);
        *(uint4*)&sVh[r * PB + u * 8] = *(const uint4*)(g_Vh + g);
        *(uint4*)&sVl[r * PB + u * 8] = *(const uint4*)(g_Vl + g);
        size_t sp = spbase + (size_t)r * DH + u * 8;
        *(uint4*)&sPh[r * PB + u * 8] = *(const uint4*)(g_Sph + sp);
        *(uint4*)&sPl[r * PB + u * 8] = *(const uint4*)(g_Spl + sp);
    }
    if (tid < DH) sZp[tid] = g_cZ[(size_t)(bh * NC + chunk) * DH + tid];
    __syncthreads();

    const int i4 = lane >> 3, r8 = lane & 7;
    const int t0 = wid * 16;
    const int er = lane >> 2, ec = (lane & 3) * 2;
    const int tA = t0 + er, tB = tA + 8;

    // ---- S = Q K^T (Q fp16, K hi/lo: 2 passes) ----
    float accS[8][4];
#pragma unroll
    for (int a = 0; a < 8; a++)
#pragma unroll
        for (int r = 0; r < 4; r++) accS[a][r] = 0.f;
#pragma unroll
    for (int ks = 0; ks < 4; ks++) {
        uint32_t af[4];
        ldsm4(af, smem_u32(sQ + (t0 + (i4 & 1) * 8 + r8) * PB
                           + ks * 16 + (i4 >> 1) * 8));
#pragma unroll
        for (int p = 0; p < 2; p++) {
            const __half* Bk = p ? sKl : sKh;
#pragma unroll
            for (int ng = 0; ng < 4; ng++) {
                uint32_t bf[4];
                ldsm4(bf, smem_u32(Bk + (ng * 16 + (i4 >> 1) * 8 + r8) * PB
                                   + ks * 16 + (i4 & 1) * 8));
                mma_f16(accS[ng * 2], af, bf[0], bf[1]);
                mma_f16(accS[ng * 2 + 1], af, bf[2], bf[3]);
            }
        }
    }

    // ---- mask, row-sum, store S (single fp16) ----
    float rsA = 0.f, rsB = 0.f;
#pragma unroll
    for (int a = 0; a < 8; a++) {
        int s0 = a * 8 + ec;
        float c0 = (s0     <= tA) ? accS[a][0] : 0.f;
        float c1 = (s0 + 1 <= tA) ? accS[a][1] : 0.f;
        float c2 = (s0     <= tB) ? accS[a][2] : 0.f;
        float c3 = (s0 + 1 <= tB) ? accS[a][3] : 0.f;
        rsA += c0 + c1; rsB += c2 + c3;
        *(uint32_t*)&sS[tA * PB + s0] = pack_h2(c0, c1);
        *(uint32_t*)&sS[tB * PB + s0] = pack_h2(c2, c3);
    }
    rsA += __shfl_xor_sync(0xFFFFFFFF, rsA, 1);
    rsA += __shfl_xor_sync(0xFFFFFFFF, rsA, 2);
    rsB += __shfl_xor_sync(0xFFFFFFFF, rsB, 1);
    rsB += __shfl_xor_sync(0xFFFFFFFF, rsB, 2);
    if ((lane & 3) == 0) { sDen[tA] = rsA; sDen[tB] = rsB; }
    __syncthreads();

    // ---- denominators: += Q . Zp + EPS ----
    if (tid < C_) {
        float qz = 0.f;
#pragma unroll
        for (int d = 0; d < DH; d += 2) {
            __half2 hv = *(__half2*)&sQ[tid * PB + d];
            qz += __half2float(hv.x) * sZp[d]
                + __half2float(hv.y) * sZp[d + 1];
        }
        sDen[tid] += qz + EPS_;
    }
    __syncthreads();

    // ---- O = S@V (2 passes) + Q@Sp (2 passes) ----
    float accO[8][4];
#pragma unroll
    for (int a = 0; a < 8; a++)
#pragma unroll
        for (int r = 0; r < 4; r++) accO[a][r] = 0.f;
#pragma unroll
    for (int ks = 0; ks < 4; ks++) {
        uint32_t af[4];
        ldsm4(af, smem_u32(sS + (t0 + (i4 & 1) * 8 + r8) * PB
                           + ks * 16 + (i4 >> 1) * 8));
#pragma unroll
        for (int p = 0; p < 2; p++) {
            const __half* Bt = p ? sVl : sVh;
#pragma unroll
            for (int ng = 0; ng < 4; ng++) {
                uint32_t bf[4];
                ldsm4t(bf, smem_u32(Bt + (ks * 16 + (i4 & 1) * 8 + r8) * PB
                                    + ng * 16 + (i4 >> 1) * 8));
                mma_f16(accO[ng * 2], af, bf[0], bf[1]);
                mma_f16(accO[ng * 2 + 1], af, bf[2], bf[3]);
            }
        }
    }
#pragma unroll
    for (int ks = 0; ks < 4; ks++) {
        uint32_t af[4];
        ldsm4(af, smem_u32(sQ + (t0 + (i4 & 1) * 8 + r8) * PB
                           + ks * 16 + (i4 >> 1) * 8));
#pragma unroll
        for (int p = 0; p < 2; p++) {
            const __half* Bt = p ? sPl : sPh;
#pragma unroll
            for (int ng = 0; ng < 4; ng++) {
                uint32_t bf[4];
                ldsm4t(bf, smem_u32(Bt + (ks * 16 + (i4 & 1) * 8 + r8) * PB
                                    + ng * 16 + (i4 >> 1) * 8));
                mma_f16(accO[ng * 2], af, bf[0], bf[1]);
                mma_f16(accO[ng * 2 + 1], af, bf[2], bf[3]);
            }
        }
    }

    // ---- divide + write y (single fp16) ----
    const float invA = 1.f / sDen[tA];
    const float invB = 1.f / sDen[tB];
#pragma unroll
    for (int a = 0; a < 8; a++) {
        int c = a * 8 + ec;
        size_t gA = (grow + tA) * D_ + h * DH + c;
        size_t gB = (grow + tB) * D_ + h * DH + c;
        *(uint32_t*)&g_y16[gA] = pack_h2(accO[a][0] * invA, accO[a][1] * invA);
        *(uint32_t*)&g_y16[gB] = pack_h2(accO[a][2] * invB, accO[a][3] * invB);
    }
}

// ---------------- launch ------------------------------------------------------
extern "C" void kernel_launch(void* const* d_in, const int* in_sizes, int n_in,
                              void* d_out, int out_size) {
    const float* x  = (const float*)d_in[0];
    const float* Wq = (const float*)d_in[1];
    const float* bq = (const float*)d_in[2];
    const float* Wk = (const float*)d_in[3];
    const float* bk = (const float*)d_in[4];
    const float* Wv = (const float*)d_in[5];
    const float* bv = (const float*)d_in[6];
    const float* Wo = (const float*)d_in[7];
    const float* bo = (const float*)d_in[8];
    float* out = (float*)d_out;

    cudaFuncSetAttribute(hmma_gemm_kernel,
                         cudaFuncAttributeMaxDynamicSharedMemorySize, GEMM_SMEM);
    cudaFuncSetAttribute(chunk_out_h,
                         cudaFuncAttributeMaxDynamicSharedMemorySize, COSM);

    __half *x16, *y16;
    cudaGetSymbolAddress((void**)&x16, g_x16);
    cudaGetSymbolAddress((void**)&y16, g_y16);

    cvt_kernel<<<M_ * D_ / 1024, 256>>>(x, x16);
    wt_kernel<<<dim3(8, 8, 4), dim3(32, 8)>>>(Wq, Wk, Wv, Wo);

    hmma_gemm_kernel<<<dim3(2, 64, 3), 256, GEMM_SMEM>>>(x16, bq, bk, bv,
                                                         nullptr, 0);

    chunksum_h<<<dim3(NC, BHN), 128>>>();
    prefix_kernel<<<BHN, 256>>>();
    chunk_out_h<<<dim3(NC, BHN), 128, COSM>>>();

    hmma_gemm_kernel<<<dim3(2, 64, 1), 256, GEMM_SMEM>>>(y16, bo, bo, bo,
                                                         out, 1);
}

// round 10
// speedup vs baseline: 3.3517x; 1.0163x over previous
#include <cuda_runtime.h>
#include <cuda_fp16.h>
#include <stdint.h>
#include <math.h>

#define B_   4
#define T_   2048
#define D_   256
#define H_   4
#define DH   64
#define C_   64
#define NC   (T_/C_)     // 32
#define BHN  (B_*H_)     // 16
#define M_   (B_*T_)     // 8192
#define EPS_ 1e-6f
#define PB   72          // chunk-kernel pitch (144B, conflict-free ldmatrix)

// ---------------- scratch ----------------------------------------------------
__device__ float g_cKV[BHN*NC*DH*DH];
__device__ float g_cZ [BHN*NC*DH];
__device__ __half g_x16[M_*D_];
__device__ __half g_Wh[4*D_*D_], g_Wl[4*D_*D_];    // W^T [n][k] hi/lo
__device__ __half g_Q16[M_*D_];
__device__ __half g_Kh[M_*D_],  g_Kl[M_*D_];
__device__ __half g_Vh[M_*D_],  g_Vl[M_*D_];
__device__ __half g_y16[M_*D_];
__device__ __half g_Sph[BHN*NC*DH*DH], g_Spl[BHN*NC*DH*DH];

// ---------------- PTX helpers -------------------------------------------------
__device__ __forceinline__ uint32_t smem_u32(const void* p) {
    uint32_t a;
    asm("{ .reg .u64 t; cvta.to.shared.u64 t, %1; cvt.u32.u64 %0, t; }"
        : "=r"(a) : "l"(p));
    return a;
}
__device__ __forceinline__ void ldsm4(uint32_t* r, uint32_t addr) {
    asm volatile("ldmatrix.sync.aligned.m8n8.x4.shared.b16 {%0,%1,%2,%3}, [%4];"
        : "=r"(r[0]), "=r"(r[1]), "=r"(r[2]), "=r"(r[3]) : "r"(addr));
}
__device__ __forceinline__ void ldsm4t(uint32_t* r, uint32_t addr) {
    asm volatile("ldmatrix.sync.aligned.m8n8.x4.trans.shared.b16 {%0,%1,%2,%3}, [%4];"
        : "=r"(r[0]), "=r"(r[1]), "=r"(r[2]), "=r"(r[3]) : "r"(addr));
}
__device__ __forceinline__ void mma_f16(float* c, const uint32_t* a,
                                        uint32_t b0, uint32_t b1) {
    asm volatile(
        "mma.sync.aligned.m16n8k16.row.col.f32.f16.f16.f32 "
        "{%0,%1,%2,%3}, {%4,%5,%6,%7}, {%8,%9}, {%0,%1,%2,%3};"
        : "+f"(c[0]), "+f"(c[1]), "+f"(c[2]), "+f"(c[3])
        : "r"(a[0]), "r"(a[1]), "r"(a[2]), "r"(a[3]), "r"(b0), "r"(b1));
}
__device__ __forceinline__ void cpa16(uint32_t s, const void* g) {
    asm volatile("cp.async.cg.shared.global [%0], [%1], 16;" :: "r"(s), "l"(g));
}
#define CPA_COMMIT() asm volatile("cp.async.commit_group;" ::: "memory")
#define CPA_WAIT(n)  asm volatile("cp.async.wait_group %0;" :: "n"(n) : "memory")
__device__ __forceinline__ uint32_t pack_h2(float a, float b) {
    __half2 v = __floats2half2_rn(a, b);
    return *(uint32_t*)&v;
}
__device__ __forceinline__ void split2h(float a, float b, uint32_t& h, uint32_t& l) {
    __half ha = __float2half_rn(a);
    __half hb = __float2half_rn(b);
    __half2 hv; hv.x = ha; hv.y = hb;
    __half2 lv;
    lv.x = __float2half_rn(a - __half2float(ha));
    lv.y = __float2half_rn(b - __half2float(hb));
    h = *(uint32_t*)&hv; l = *(uint32_t*)&lv;
}

// ---------------- conversion kernels ------------------------------------------
__global__ __launch_bounds__(256)
void cvt_kernel(const float* __restrict__ in, __half* __restrict__ o16) {
    int idx = blockIdx.x * 256 + threadIdx.x;
    float4 v = *(const float4*)(in + (size_t)idx * 4);
    uint2 o;
    o.x = pack_h2(v.x, v.y);
    o.y = pack_h2(v.z, v.w);
    *(uint2*)(o16 + (size_t)idx * 4) = o;
}

__global__ __launch_bounds__(256)
void wt_kernel(const float* __restrict__ Wq, const float* __restrict__ Wk,
               const float* __restrict__ Wv, const float* __restrict__ Wo) {
    __shared__ float s[32][33];
    const int n0 = blockIdx.x * 32, k0 = blockIdx.y * 32, z = blockIdx.z;
    const float* W = (z == 0) ? Wq : (z == 1) ? Wk : (z == 2) ? Wv : Wo;
    const int tx = threadIdx.x, ty = threadIdx.y;
#pragma unroll
    for (int r = 0; r < 4; r++) {
        int k = k0 + ty + r * 8;
        s[ty + r * 8][tx] = W[(size_t)k * D_ + n0 + tx];
    }
    __syncthreads();
#pragma unroll
    for (int r = 0; r < 4; r++) {
        int n = n0 + ty + r * 8;
        float v = s[tx][ty + r * 8];
        __half h = __float2half_rn(v);
        __half l = __float2half_rn(v - __half2float(h));
        size_t o = (size_t)z * D_ * D_ + (size_t)n * D_ + k0 + tx;
        g_Wh[o] = h;
        g_Wl[o] = l;
    }
}

// ---------------- HMMA fp16 GEMM, cp.async double-buffered --------------------
// C = f(A @ W + b):  A fp16 (rounded), W^T split hi/lo -> 2 passes.
// 8 K-stages of 32, two buffers.  Pitch 40 halves (80B): ldmatrix conflict-free.
#define PK   40
#define STG  (128 * PK)                 // halves per array per stage
#define GEMM_SMEM (2 * 3 * STG * 2)     // 61440 B

__global__ __launch_bounds__(256, 2)
void hmma_gemm_kernel(const __half* __restrict__ A16,
                      const float* __restrict__ b0, const float* __restrict__ b1,
                      const float* __restrict__ b2,
                      float* __restrict__ dout, int mode) {
    extern __shared__ __half sm2[];
    const uint32_t sb = smem_u32(sm2);

    const int tid = threadIdx.x, lane = tid & 31, wid = tid >> 5;
    const int warp_m = wid >> 2, warp_n = wid & 3;
    const int n0 = blockIdx.x * 128, row0 = blockIdx.y * 128;
    const int zy = blockIdx.z;
    const int z = (mode == 0) ? zy : 3;
    const float* bias = (mode == 0) ? ((zy == 0) ? b0 : (zy == 1) ? b1 : b2) : b0;
    const int feat = (mode == 0) && (zy < 2);
    const __half* Bh = g_Wh + (size_t)z * D_ * D_;
    const __half* Bl = g_Wl + (size_t)z * D_ * D_;

    // per-thread load role: 512 16B-units per array per stage
    const int lr = tid >> 2, lu = tid & 3;     // row, unit(0..3) for i=0; +64 rows for i=1

    float acc[4][4][4];
#pragma unroll
    for (int mt = 0; mt < 4; mt++)
#pragma unroll
        for (int nt = 0; nt < 4; nt++)
#pragma unroll
            for (int r = 0; r < 4; r++) acc[mt][nt][r] = 0.f;

    const int i4 = lane >> 3, r8 = lane & 7;
    const int a_row = warp_m * 64 + (i4 & 1) * 8 + r8;
    const int b_row = warp_n * 32 + (i4 >> 1) * 8 + r8;
    const int a_co  = (i4 >> 1) * 8;      // + ks*16
    const int b_co  = (i4 & 1) * 8;       // + ks*16

#define LOAD_STAGE(s, buf) do {                                              \
    int _k0 = (s) * 32;                                                      \
    uint32_t _sb0 = sb + (uint32_t)((buf) * 3 * STG) * 2;                    \
    _Pragma("unroll")                                                        \
    for (int _i = 0; _i < 2; _i++) {                                         \
        int _r = lr + _i * 64;                                               \
        uint32_t _so = (uint32_t)(_r * PK + lu * 8) * 2;                     \
        size_t _ga = (size_t)(row0 + _r) * D_ + _k0 + lu * 8;                \
        size_t _gb = (size_t)(n0 + _r) * D_ + _k0 + lu * 8;                  \
        cpa16(_sb0 + _so,                 A16 + _ga);                        \
        cpa16(_sb0 + STG * 2 + _so,      Bh + _gb);                          \
        cpa16(_sb0 + 2 * STG * 2 + _so,  Bl + _gb);                          \
    }                                                                        \
} while (0)

    LOAD_STAGE(0, 0);
    CPA_COMMIT();

    for (int s = 0; s < 8; s++) {
        if (s < 7) {
            LOAD_STAGE(s + 1, (s + 1) & 1);
            CPA_COMMIT();
            CPA_WAIT(1);
        } else {
            CPA_WAIT(0);
        }
        __syncthreads();

        const uint32_t bufb = sb + (uint32_t)((s & 1) * 3 * STG) * 2;
        const uint32_t aB = bufb;
        const uint32_t hB = bufb + STG * 2;
        const uint32_t lB = bufb + 2 * STG * 2;

#pragma unroll
        for (int ks = 0; ks < 2; ks++) {
            const int ac = ks * 16 + a_co;
            const int bc = ks * 16 + b_co;
            uint32_t afr[4][4], bhf[2][4], blf[2][4];
#pragma unroll
            for (int mt = 0; mt < 4; mt++)
                ldsm4(afr[mt], aB + (uint32_t)((a_row + mt * 16) * PK + ac) * 2);
#pragma unroll
            for (int pt = 0; pt < 2; pt++) {
                ldsm4(bhf[pt], hB + (uint32_t)((b_row + pt * 16) * PK + bc) * 2);
                ldsm4(blf[pt], lB + (uint32_t)((b_row + pt * 16) * PK + bc) * 2);
            }
#pragma unroll
            for (int mt = 0; mt < 4; mt++)
#pragma unroll
                for (int nt = 0; nt < 4; nt++) {
                    int pt = nt >> 1, sub = (nt & 1) * 2;
                    mma_f16(acc[mt][nt], afr[mt], bhf[pt][sub], bhf[pt][sub + 1]);
                    mma_f16(acc[mt][nt], afr[mt], blf[pt][sub], blf[pt][sub + 1]);
                }
        }
        __syncthreads();
    }
#undef LOAD_STAGE

    // epilogue
    const int er = (lane >> 2), ec = (lane & 3) * 2;
#pragma unroll
    for (int mt = 0; mt < 4; mt++) {
        int r = row0 + warp_m * 64 + mt * 16 + er;
#pragma unroll
        for (int nt = 0; nt < 4; nt++) {
            int c = n0 + warp_n * 32 + nt * 8 + ec;
            float2 bv = *(const float2*)(bias + c);
            float o0x = acc[mt][nt][0] + bv.x, o0y = acc[mt][nt][1] + bv.y;
            float o1x = acc[mt][nt][2] + bv.x, o1y = acc[mt][nt][3] + bv.y;
            if (feat) {
                o0x = (o0x > 0.f) ? (o0x + 1.f) : __expf(o0x);
                o0y = (o0y > 0.f) ? (o0y + 1.f) : __expf(o0y);
                o1x = (o1x > 0.f) ? (o1x + 1.f) : __expf(o1x);
                o1y = (o1y > 0.f) ? (o1y + 1.f) : __expf(o1y);
            }
            if (mode == 1) {
                float2 a0 = {o0x, o0y}, a1 = {o1x, o1y};
                *(float2*)(dout + (size_t)r * D_ + c) = a0;
                *(float2*)(dout + (size_t)(r + 8) * D_ + c) = a1;
            } else if (zy == 0) {           // Q: single fp16
                *(uint32_t*)&g_Q16[(size_t)r * D_ + c] = pack_h2(o0x, o0y);
                *(uint32_t*)&g_Q16[(size_t)(r + 8) * D_ + c] = pack_h2(o1x, o1y);
            } else {                        // K or V: hi/lo split
                __half* Oh = (zy == 1) ? g_Kh : g_Vh;
                __half* Ol = (zy == 1) ? g_Kl : g_Vl;
                uint32_t h, l;
                split2h(o0x, o0y, h, l);
                *(uint32_t*)&Oh[(size_t)r * D_ + c] = h;
                *(uint32_t*)&Ol[(size_t)r * D_ + c] = l;
                split2h(o1x, o1y, h, l);
                *(uint32_t*)&Oh[(size_t)(r + 8) * D_ + c] = h;
                *(uint32_t*)&Ol[(size_t)(r + 8) * D_ + c] = l;
            }
        }
    }
}

// ---------------- per-chunk KV / Z sums (K fp16, V hi/lo -> 2 passes) ---------
__global__ __launch_bounds__(128)
void chunksum_h() {
    __shared__ __half sK [C_ * PB];
    __shared__ __half sVh[C_ * PB];
    __shared__ __half sVl[C_ * PB];
    const int chunk = blockIdx.x, bh = blockIdx.y;
    const int b = bh >> 2, h = bh & 3;
    const int tid = threadIdx.x, lane = tid & 31, wid = tid >> 5;
    const size_t base = (size_t)(b * T_ + chunk * C_) * D_ + h * DH;

#pragma unroll
    for (int i = 0; i < 4; i++) {
        int idx = tid + i * 128;               // 512 units
        int r = idx >> 3, u = idx & 7;
        size_t g = base + (size_t)r * D_ + u * 8;
        *(uint4*)&sK [r * PB + u * 8] = *(const uint4*)(g_Kh + g);
        *(uint4*)&sVh[r * PB + u * 8] = *(const uint4*)(g_Vh + g);
        *(uint4*)&sVl[r * PB + u * 8] = *(const uint4*)(g_Vl + g);
    }
    __syncthreads();

    const int i4 = lane >> 3, r8 = lane & 7;
    const int d0 = wid * 16;
    float acc[8][4];
#pragma unroll
    for (int a = 0; a < 8; a++)
#pragma unroll
        for (int r = 0; r < 4; r++) acc[a][r] = 0.f;

#pragma unroll
    for (int ks = 0; ks < 4; ks++) {
        uint32_t af[4];
        ldsm4t(af, smem_u32(sK + (ks * 16 + (i4 >> 1) * 8 + r8) * PB
                            + d0 + (i4 & 1) * 8));
#pragma unroll
        for (int p = 0; p < 2; p++) {
            const __half* Bv = p ? sVl : sVh;
#pragma unroll
            for (int ng = 0; ng < 4; ng++) {
                uint32_t bf[4];
                ldsm4t(bf, smem_u32(Bv + (ks * 16 + (i4 & 1) * 8 + r8) * PB
                                    + ng * 16 + (i4 >> 1) * 8));
                mma_f16(acc[ng * 2], af, bf[0], bf[1]);
                mma_f16(acc[ng * 2 + 1], af, bf[2], bf[3]);
            }
        }
    }

    const int er = lane >> 2, ec = (lane & 3) * 2;
    size_t ob = (size_t)(bh * NC + chunk) * DH;
#pragma unroll
    for (int a = 0; a < 8; a++) {
        int m = a * 8 + ec;
        float2 c0 = {acc[a][0], acc[a][1]};
        float2 c1 = {acc[a][2], acc[a][3]};
        *(float2*)&g_cKV[(ob + d0 + er) * DH + m] = c0;
        *(float2*)&g_cKV[(ob + d0 + er + 8) * DH + m] = c1;
    }
    if (tid < DH) {
        float zv = 0.f;
        for (int s = 0; s < C_; s++)
            zv += __half2float(sK[s * PB + tid]);
        g_cZ[ob + tid] = zv;
    }
}

// ---------------- exclusive prefix (writes Sp as fp16 hi/lo) ------------------
__global__ __launch_bounds__(256)
void prefix_kernel() {
    const int bh = blockIdx.x, tid = threadIdx.x;
    float4 run[4];
#pragma unroll
    for (int j = 0; j < 4; j++) run[j] = make_float4(0.f, 0.f, 0.f, 0.f);
    float zrun = 0.f;
    for (int c = 0; c < NC; c++) {
        size_t base = (size_t)(bh * NC + c) * (DH * DH) + (size_t)tid * 16;
#pragma unroll
        for (int j = 0; j < 4; j++) {
            float4 t = *(float4*)(g_cKV + base + j * 4);
            uint32_t h0, l0, h1, l1;
            split2h(run[j].x, run[j].y, h0, l0);
            split2h(run[j].z, run[j].w, h1, l1);
            *(uint32_t*)&g_Sph[base + j * 4]     = h0;
            *(uint32_t*)&g_Sph[base + j * 4 + 2] = h1;
            *(uint32_t*)&g_Spl[base + j * 4]     = l0;
            *(uint32_t*)&g_Spl[base + j * 4 + 2] = l1;
            run[j].x += t.x; run[j].y += t.y; run[j].z += t.z; run[j].w += t.w;
        }
        if (tid < DH) {
            float* zp = g_cZ + (size_t)(bh * NC + c) * DH + tid;
            float t = *zp; *zp = zrun; zrun += t;
        }
    }
}

// ---------------- per-chunk output (fp16, 2+4 passes) -------------------------
#define TILEH (C_ * PB)
#define COSM  (8 * TILEH * 2 + 2 * 64 * 4)

__global__ __launch_bounds__(128)
void chunk_out_h() {
    extern __shared__ __half smc[];
    __half* sQ  = smc;
    __half* sKh = smc + 1 * TILEH;
    __half* sKl = smc + 2 * TILEH;
    __half* sVh = smc + 3 * TILEH;
    __half* sVl = smc + 4 * TILEH;
    __half* sPh = smc + 5 * TILEH;
    __half* sPl = smc + 6 * TILEH;
    __half* sS  = smc + 7 * TILEH;
    float* sZp  = (float*)(smc + 8 * TILEH);
    float* sDen = sZp + 64;

    const int chunk = blockIdx.x, bh = blockIdx.y;
    const int b = bh >> 2, h = bh & 3;
    const int tid = threadIdx.x, lane = tid & 31, wid = tid >> 5;
    const size_t grow = (size_t)(b * T_ + chunk * C_);
    const size_t spbase = (size_t)(bh * NC + chunk) * (DH * DH);

#pragma unroll
    for (int i = 0; i < 4; i++) {
        int idx = tid + i * 128;
        int r = idx >> 3, u = idx & 7;
        size_t g = (grow + r) * D_ + h * DH + u * 8;
        *(uint4*)&sQ [r * PB + u * 8] = *(const uint4*)(g_Q16 + g);
        *(uint4*)&sKh[r * PB + u * 8] = *(const uint4*)(g_Kh + g);
        *(uint4*)&sKl[r * PB + u * 8] = *(const uint4*)(g_Kl + g);
        *(uint4*)&sVh[r * PB + u * 8] = *(const uint4*)(g_Vh + g);
        *(uint4*)&sVl[r * PB + u * 8] = *(const uint4*)(g_Vl + g);
        size_t sp = spbase + (size_t)r * DH + u * 8;
        *(uint4*)&sPh[r * PB + u * 8] = *(const uint4*)(g_Sph + sp);
        *(uint4*)&sPl[r * PB + u * 8] = *(const uint4*)(g_Spl + sp);
    }
    if (tid < DH) sZp[tid] = g_cZ[(size_t)(bh * NC + chunk) * DH + tid];
    __syncthreads();

    const int i4 = lane >> 3, r8 = lane & 7;
    const int t0 = wid * 16;
    const int er = lane >> 2, ec = (lane & 3) * 2;
    const int tA = t0 + er, tB = tA + 8;

    // ---- S = Q K^T (Q fp16, K hi/lo: 2 passes) ----
    float accS[8][4];
#pragma unroll
    for (int a = 0; a < 8; a++)
#pragma unroll
        for (int r = 0; r < 4; r++) accS[a][r] = 0.f;
#pragma unroll
    for (int ks = 0; ks < 4; ks++) {
        uint32_t af[4];
        ldsm4(af, smem_u32(sQ + (t0 + (i4 & 1) * 8 + r8) * PB
                           + ks * 16 + (i4 >> 1) * 8));
#pragma unroll
        for (int p = 0; p < 2; p++) {
            const __half* Bk = p ? sKl : sKh;
#pragma unroll
            for (int ng = 0; ng < 4; ng++) {
                uint32_t bf[4];
                ldsm4(bf, smem_u32(Bk + (ng * 16 + (i4 >> 1) * 8 + r8) * PB
                                   + ks * 16 + (i4 & 1) * 8));
                mma_f16(accS[ng * 2], af, bf[0], bf[1]);
                mma_f16(accS[ng * 2 + 1], af, bf[2], bf[3]);
            }
        }
    }

    // ---- mask, row-sum, store S (single fp16) ----
    float rsA = 0.f, rsB = 0.f;
#pragma unroll
    for (int a = 0; a < 8; a++) {
        int s0 = a * 8 + ec;
        float c0 = (s0     <= tA) ? accS[a][0] : 0.f;
        float c1 = (s0 + 1 <= tA) ? accS[a][1] : 0.f;
        float c2 = (s0     <= tB) ? accS[a][2] : 0.f;
        float c3 = (s0 + 1 <= tB) ? accS[a][3] : 0.f;
        rsA += c0 + c1; rsB += c2 + c3;
        *(uint32_t*)&sS[tA * PB + s0] = pack_h2(c0, c1);
        *(uint32_t*)&sS[tB * PB + s0] = pack_h2(c2, c3);
    }
    rsA += __shfl_xor_sync(0xFFFFFFFF, rsA, 1);
    rsA += __shfl_xor_sync(0xFFFFFFFF, rsA, 2);
    rsB += __shfl_xor_sync(0xFFFFFFFF, rsB, 1);
    rsB += __shfl_xor_sync(0xFFFFFFFF, rsB, 2);
    if ((lane & 3) == 0) { sDen[tA] = rsA; sDen[tB] = rsB; }
    __syncthreads();

    // ---- denominators: += Q . Zp + EPS ----
    if (tid < C_) {
        float qz = 0.f;
#pragma unroll
        for (int d = 0; d < DH; d += 2) {
            __half2 hv = *(__half2*)&sQ[tid * PB + d];
            qz += __half2float(hv.x) * sZp[d]
                + __half2float(hv.y) * sZp[d + 1];
        }
        sDen[tid] += qz + EPS_;
    }
    __syncthreads();

    // ---- O = S@V (2 passes) + Q@Sp (2 passes) ----
    float accO[8][4];
#pragma unroll
    for (int a = 0; a < 8; a++)
#pragma unroll
        for (int r = 0; r < 4; r++) accO[a][r] = 0.f;
#pragma unroll
    for (int ks = 0; ks < 4; ks++) {
        uint32_t af[4];
        ldsm4(af, smem_u32(sS + (t0 + (i4 & 1) * 8 + r8) * PB
                           + ks * 16 + (i4 >> 1) * 8));
#pragma unroll
        for (int p = 0; p < 2; p++) {
            const __half* Bt = p ? sVl : sVh;
#pragma unroll
            for (int ng = 0; ng < 4; ng++) {
                uint32_t bf[4];
                ldsm4t(bf, smem_u32(Bt + (ks * 16 + (i4 & 1) * 8 + r8) * PB
                                    + ng * 16 + (i4 >> 1) * 8));
                mma_f16(accO[ng * 2], af, bf[0], bf[1]);
                mma_f16(accO[ng * 2 + 1], af, bf[2], bf[3]);
            }
        }
    }
#pragma unroll
    for (int ks = 0; ks < 4; ks++) {
        uint32_t af[4];
        ldsm4(af, smem_u32(sQ + (t0 + (i4 & 1) * 8 + r8) * PB
                           + ks * 16 + (i4 >> 1) * 8));
#pragma unroll
        for (int p = 0; p < 2; p++) {
            const __half* Bt = p ? sPl : sPh;
#pragma unroll
            for (int ng = 0; ng < 4; ng++) {
                uint32_t bf[4];
                ldsm4t(bf, smem_u32(Bt + (ks * 16 + (i4 & 1) * 8 + r8) * PB
                                    + ng * 16 + (i4 >> 1) * 8));
                mma_f16(accO[ng * 2], af, bf[0], bf[1]);
                mma_f16(accO[ng * 2 + 1], af, bf[2], bf[3]);
            }
        }
    }

    // ---- divide + write y (single fp16) ----
    const float invA = 1.f / sDen[tA];
    const float invB = 1.f / sDen[tB];
#pragma unroll
    for (int a = 0; a < 8; a++) {
        int c = a * 8 + ec;
        size_t gA = (grow + tA) * D_ + h * DH + c;
        size_t gB = (grow + tB) * D_ + h * DH + c;
        *(uint32_t*)&g_y16[gA] = pack_h2(accO[a][0] * invA, accO[a][1] * invA);
        *(uint32_t*)&g_y16[gB] = pack_h2(accO[a][2] * invB, accO[a][3] * invB);
    }
}

// ---------------- launch ------------------------------------------------------
extern "C" void kernel_launch(void* const* d_in, const int* in_sizes, int n_in,
                              void* d_out, int out_size) {
    const float* x  = (const float*)d_in[0];
    const float* Wq = (const float*)d_in[1];
    const float* bq = (const float*)d_in[2];
    const float* Wk = (const float*)d_in[3];
    const float* bk = (const float*)d_in[4];
    const float* Wv = (const float*)d_in[5];
    const float* bv = (const float*)d_in[6];
    const float* Wo = (const float*)d_in[7];
    const float* bo = (const float*)d_in[8];
    float* out = (float*)d_out;

    cudaFuncSetAttribute(hmma_gemm_kernel,
                         cudaFuncAttributeMaxDynamicSharedMemorySize, GEMM_SMEM);
    cudaFuncSetAttribute(chunk_out_h,
                         cudaFuncAttributeMaxDynamicSharedMemorySize, COSM);

    __half *x16, *y16;
    cudaGetSymbolAddress((void**)&x16, g_x16);
    cudaGetSymbolAddress((void**)&y16, g_y16);

    cvt_kernel<<<M_ * D_ / 1024, 256>>>(x, x16);
    wt_kernel<<<dim3(8, 8, 4), dim3(32, 8)>>>(Wq, Wk, Wv, Wo);

    hmma_gemm_kernel<<<dim3(2, 64, 3), 256, GEMM_SMEM>>>(x16, bq, bk, bv,
                                                         nullptr, 0);

    chunksum_h<<<dim3(NC, BHN), 128>>>();
    prefix_kernel<<<BHN, 256>>>();
    chunk_out_h<<<dim3(NC, BHN), 128, COSM>>>();

    hmma_gemm_kernel<<<dim3(2, 64, 1), 256, GEMM_SMEM>>>(y16, bo, bo, bo,
                                                         out, 1);
}

// round 12
// speedup vs baseline: 6.1118x; 1.8235x over previous
#include <cuda_runtime.h>
#include <cuda_fp16.h>
#include <stdint.h>
#include <math.h>

#define B_   4
#define T_   2048
#define D_   256
#define H_   4
#define DH   64
#define C_   64
#define NC   (T_/C_)     // 32
#define BHN  (B_*H_)     // 16
#define M_   (B_*T_)     // 8192
#define EPS_ 1e-6f
#define PB   72          // chunk-kernel pitch (144B, conflict-free ldmatrix)

// ---------------- scratch ----------------------------------------------------
__device__ float g_cKV[BHN*NC*DH*DH];
__device__ float g_cZ [BHN*NC*DH];
__device__ __half g_x16[M_*D_];
__device__ __half g_Wh[4*D_*D_], g_Wl[4*D_*D_];    // W^T [n][k] hi/lo
__device__ __half g_Q16[M_*D_];
__device__ __half g_K16[M_*D_];
__device__ __half g_Vh[M_*D_],  g_Vl[M_*D_];
__device__ __half g_y16[M_*D_];
__device__ __half g_Sph[BHN*NC*DH*DH], g_Spl[BHN*NC*DH*DH];

// ---------------- PTX helpers -------------------------------------------------
__device__ __forceinline__ uint32_t smem_u32(const void* p) {
    uint32_t a;
    asm("{ .reg .u64 t; cvta.to.shared.u64 t, %1; cvt.u32.u64 %0, t; }"
        : "=r"(a) : "l"(p));
    return a;
}
__device__ __forceinline__ void ldsm4(uint32_t* r, uint32_t addr) {
    asm volatile("ldmatrix.sync.aligned.m8n8.x4.shared.b16 {%0,%1,%2,%3}, [%4];"
        : "=r"(r[0]), "=r"(r[1]), "=r"(r[2]), "=r"(r[3]) : "r"(addr));
}
__device__ __forceinline__ void ldsm4t(uint32_t* r, uint32_t addr) {
    asm volatile("ldmatrix.sync.aligned.m8n8.x4.trans.shared.b16 {%0,%1,%2,%3}, [%4];"
        : "=r"(r[0]), "=r"(r[1]), "=r"(r[2]), "=r"(r[3]) : "r"(addr));
}
__device__ __forceinline__ void mma_f16(float* c, const uint32_t* a,
                                        uint32_t b0, uint32_t b1) {
    asm volatile(
        "mma.sync.aligned.m16n8k16.row.col.f32.f16.f16.f32 "
        "{%0,%1,%2,%3}, {%4,%5,%6,%7}, {%8,%9}, {%0,%1,%2,%3};"
        : "+f"(c[0]), "+f"(c[1]), "+f"(c[2]), "+f"(c[3])
        : "r"(a[0]), "r"(a[1]), "r"(a[2]), "r"(a[3]), "r"(b0), "r"(b1));
}
__device__ __forceinline__ void cpa16(uint32_t s, const void* g) {
    asm volatile("cp.async.cg.shared.global [%0], [%1], 16;" :: "r"(s), "l"(g));
}
#define CPA_COMMIT() asm volatile("cp.async.commit_group;" ::: "memory")
#define CPA_WAIT(n)  asm volatile("cp.async.wait_group %0;" :: "n"(n) : "memory")
__device__ __forceinline__ uint32_t pack_h2(float a, float b) {
    __half2 v = __floats2half2_rn(a, b);
    return *(uint32_t*)&v;
}
__device__ __forceinline__ void split2h(float a, float b, uint32_t& h, uint32_t& l) {
    __half ha = __float2half_rn(a);
    __half hb = __float2half_rn(b);
    __half2 hv; hv.x = ha; hv.y = hb;
    __half2 lv;
    lv.x = __float2half_rn(a - __half2float(ha));
    lv.y = __float2half_rn(b - __half2float(hb));
    h = *(uint32_t*)&hv; l = *(uint32_t*)&lv;
}

// ---------------- fused pre-processing: weights split + x convert -------------
// blocks [0,256): weight transpose+split (4 z * 8 * 8 tiles)
// blocks [256, 2304): x -> fp16
__global__ __launch_bounds__(256)
void pre_kernel(const float* __restrict__ x,
                const float* __restrict__ Wq, const float* __restrict__ Wk,
                const float* __restrict__ Wv, const float* __restrict__ Wo) {
    __shared__ float s[32][33];
    const int bid = blockIdx.x, tid = threadIdx.x;
    if (bid < 256) {
        const int z = bid >> 6, rem = bid & 63;
        const int n0 = (rem >> 3) * 32, k0 = (rem & 7) * 32;
        const float* W = (z == 0) ? Wq : (z == 1) ? Wk : (z == 2) ? Wv : Wo;
        const int tx = tid & 31, ty = tid >> 5;
#pragma unroll
        for (int r = 0; r < 4; r++) {
            int k = k0 + ty + r * 8;
            s[ty + r * 8][tx] = W[(size_t)k * D_ + n0 + tx];
        }
        __syncthreads();
#pragma unroll
        for (int r = 0; r < 4; r++) {
            int n = n0 + ty + r * 8;
            float v = s[tx][ty + r * 8];
            __half h = __float2half_rn(v);
            __half l = __float2half_rn(v - __half2float(h));
            size_t o = (size_t)z * D_ * D_ + (size_t)n * D_ + k0 + tx;
            g_Wh[o] = h;
            g_Wl[o] = l;
        }
    } else {
        int idx = (bid - 256) * 256 + tid;
        float4 v = *(const float4*)(x + (size_t)idx * 4);
        uint2 o;
        o.x = pack_h2(v.x, v.y);
        o.y = pack_h2(v.z, v.w);
        *(uint2*)(g_x16 + (size_t)idx * 4) = o;
    }
}

// ---------------- HMMA fp16 GEMM, cp.async double-buffered --------------------
// C = f(A @ W + b).  A fp16.  W^T hi (+ lo pass only for V projection / out proj).
#define PK   40
#define STG  (128 * PK)                 // halves per array per stage
#define GEMM_SMEM (2 * 3 * STG * 2)     // 61440 B

__global__ __launch_bounds__(256, 2)
void hmma_gemm_kernel(const __half* __restrict__ A16,
                      const float* __restrict__ b0, const float* __restrict__ b1,
                      const float* __restrict__ b2,
                      float* __restrict__ dout, int mode) {
    extern __shared__ __half sm2[];
    const uint32_t sb = smem_u32(sm2);

    const int tid = threadIdx.x, lane = tid & 31, wid = tid >> 5;
    const int warp_m = wid >> 2, warp_n = wid & 3;
    const int n0 = blockIdx.x * 128, row0 = blockIdx.y * 128;
    const int zy = blockIdx.z;
    const int z = (mode == 0) ? zy : 3;
    const float* bias = (mode == 0) ? ((zy == 0) ? b0 : (zy == 1) ? b1 : b2) : b0;
    const int feat = (mode == 0) && (zy < 2);
    const int use_lo = (mode == 1) || (zy == 2);   // V projection & out-proj keep lo pass
    const __half* Bh = g_Wh + (size_t)z * D_ * D_;
    const __half* Bl = g_Wl + (size_t)z * D_ * D_;

    const int lr = tid >> 2, lu = tid & 3;

    float acc[4][4][4];
#pragma unroll
    for (int mt = 0; mt < 4; mt++)
#pragma unroll
        for (int nt = 0; nt < 4; nt++)
#pragma unroll
            for (int r = 0; r < 4; r++) acc[mt][nt][r] = 0.f;

    const int i4 = lane >> 3, r8 = lane & 7;
    const int a_row = warp_m * 64 + (i4 & 1) * 8 + r8;
    const int b_row = warp_n * 32 + (i4 >> 1) * 8 + r8;
    const int a_co  = (i4 >> 1) * 8;
    const int b_co  = (i4 & 1) * 8;

#define LOAD_STAGE(s, buf) do {                                              \
    int _k0 = (s) * 32;                                                      \
    uint32_t _sb0 = sb + (uint32_t)((buf) * 3 * STG) * 2;                    \
    _Pragma("unroll")                                                        \
    for (int _i = 0; _i < 2; _i++) {                                         \
        int _r = lr + _i * 64;                                               \
        uint32_t _so = (uint32_t)(_r * PK + lu * 8) * 2;                     \
        size_t _ga = (size_t)(row0 + _r) * D_ + _k0 + lu * 8;                \
        size_t _gb = (size_t)(n0 + _r) * D_ + _k0 + lu * 8;                  \
        cpa16(_sb0 + _so,                 A16 + _ga);                        \
        cpa16(_sb0 + STG * 2 + _so,      Bh + _gb);                          \
        if (use_lo) cpa16(_sb0 + 2 * STG * 2 + _so,  Bl + _gb);              \
    }                                                                        \
} while (0)

    LOAD_STAGE(0, 0);
    CPA_COMMIT();

    for (int s = 0; s < 8; s++) {
        if (s < 7) {
            LOAD_STAGE(s + 1, (s + 1) & 1);
            CPA_COMMIT();
            CPA_WAIT(1);
        } else {
            CPA_WAIT(0);
        }
        __syncthreads();

        const uint32_t bufb = sb + (uint32_t)((s & 1) * 3 * STG) * 2;
        const uint32_t aB = bufb;
        const uint32_t hB = bufb + STG * 2;
        const uint32_t lB = bufb + 2 * STG * 2;

#pragma unroll
        for (int ks = 0; ks < 2; ks++) {
            const int ac = ks * 16 + a_co;
            const int bc = ks * 16 + b_co;
            uint32_t afr[4][4], bhf[2][4], blf[2][4];
#pragma unroll
            for (int mt = 0; mt < 4; mt++)
                ldsm4(afr[mt], aB + (uint32_t)((a_row + mt * 16) * PK + ac) * 2);
#pragma unroll
            for (int pt = 0; pt < 2; pt++) {
                ldsm4(bhf[pt], hB + (uint32_t)((b_row + pt * 16) * PK + bc) * 2);
                if (use_lo)
                    ldsm4(blf[pt], lB + (uint32_t)((b_row + pt * 16) * PK + bc) * 2);
            }
#pragma unroll
            for (int mt = 0; mt < 4; mt++)
#pragma unroll
                for (int nt = 0; nt < 4; nt++) {
                    int pt = nt >> 1, sub = (nt & 1) * 2;
                    mma_f16(acc[mt][nt], afr[mt], bhf[pt][sub], bhf[pt][sub + 1]);
                    if (use_lo)
                        mma_f16(acc[mt][nt], afr[mt], blf[pt][sub], blf[pt][sub + 1]);
                }
        }
        __syncthreads();
    }
#undef LOAD_STAGE

    // epilogue
    const int er = (lane >> 2), ec = (lane & 3) * 2;
#pragma unroll
    for (int mt = 0; mt < 4; mt++) {
        int r = row0 + warp_m * 64 + mt * 16 + er;
#pragma unroll
        for (int nt = 0; nt < 4; nt++) {
            int c = n0 + warp_n * 32 + nt * 8 + ec;
            float2 bv = *(const float2*)(bias + c);
            float o0x = acc[mt][nt][0] + bv.x, o0y = acc[mt][nt][1] + bv.y;
            float o1x = acc[mt][nt][2] + bv.x, o1y = acc[mt][nt][3] + bv.y;
            if (feat) {
                o0x = (o0x > 0.f) ? (o0x + 1.f) : __expf(o0x);
                o0y = (o0y > 0.f) ? (o0y + 1.f) : __expf(o0y);
                o1x = (o1x > 0.f) ? (o1x + 1.f) : __expf(o1x);
                o1y = (o1y > 0.f) ? (o1y + 1.f) : __expf(o1y);
            }
            if (mode == 1) {
                float2 a0 = {o0x, o0y}, a1 = {o1x, o1y};
                *(float2*)(dout + (size_t)r * D_ + c) = a0;
                *(float2*)(dout + (size_t)(r + 8) * D_ + c) = a1;
            } else if (zy < 2) {            // Q or K: single fp16
                __half* O16 = (zy == 0) ? g_Q16 : g_K16;
                *(uint32_t*)&O16[(size_t)r * D_ + c] = pack_h2(o0x, o0y);
                *(uint32_t*)&O16[(size_t)(r + 8) * D_ + c] = pack_h2(o1x, o1y);
            } else {                        // V: hi/lo split
                uint32_t h, l;
                split2h(o0x, o0y, h, l);
                *(uint32_t*)&g_Vh[(size_t)r * D_ + c] = h;
                *(uint32_t*)&g_Vl[(size_t)r * D_ + c] = l;
                split2h(o1x, o1y, h, l);
                *(uint32_t*)&g_Vh[(size_t)(r + 8) * D_ + c] = h;
                *(uint32_t*)&g_Vl[(size_t)(r + 8) * D_ + c] = l;
            }
        }
    }
}

// ---------------- per-chunk KV / Z sums (K fp16, V hi/lo -> 2 passes) ---------
__global__ __launch_bounds__(128)
void chunksum_h() {
    __shared__ __half sK [C_ * PB];
    __shared__ __half sVh[C_ * PB];
    __shared__ __half sVl[C_ * PB];
    const int chunk = blockIdx.x, bh = blockIdx.y;
    const int b = bh >> 2, h = bh & 3;
    const int tid = threadIdx.x, lane = tid & 31, wid = tid >> 5;
    const size_t base = (size_t)(b * T_ + chunk * C_) * D_ + h * DH;

#pragma unroll
    for (int i = 0; i < 4; i++) {
        int idx = tid + i * 128;
        int r = idx >> 3, u = idx & 7;
        size_t g = base + (size_t)r * D_ + u * 8;
        *(uint4*)&sK [r * PB + u * 8] = *(const uint4*)(g_K16 + g);
        *(uint4*)&sVh[r * PB + u * 8] = *(const uint4*)(g_Vh + g);
        *(uint4*)&sVl[r * PB + u * 8] = *(const uint4*)(g_Vl + g);
    }
    __syncthreads();

    const int i4 = lane >> 3, r8 = lane & 7;
    const int d0 = wid * 16;
    float acc[8][4];
#pragma unroll
    for (int a = 0; a < 8; a++)
#pragma unroll
        for (int r = 0; r < 4; r++) acc[a][r] = 0.f;

#pragma unroll
    for (int ks = 0; ks < 4; ks++) {
        uint32_t af[4];
        ldsm4t(af, smem_u32(sK + (ks * 16 + (i4 >> 1) * 8 + r8) * PB
                            + d0 + (i4 & 1) * 8));
#pragma unroll
        for (int p = 0; p < 2; p++) {
            const __half* Bv = p ? sVl : sVh;
#pragma unroll
            for (int ng = 0; ng < 4; ng++) {
                uint32_t bf[4];
                ldsm4t(bf, smem_u32(Bv + (ks * 16 + (i4 & 1) * 8 + r8) * PB
                                    + ng * 16 + (i4 >> 1) * 8));
                mma_f16(acc[ng * 2], af, bf[0], bf[1]);
                mma_f16(acc[ng * 2 + 1], af, bf[2], bf[3]);
            }
        }
    }

    const int er = lane >> 2, ec = (lane & 3) * 2;
    size_t ob = (size_t)(bh * NC + chunk) * DH;
#pragma unroll
    for (int a = 0; a < 8; a++) {
        int m = a * 8 + ec;
        float2 c0 = {acc[a][0], acc[a][1]};
        float2 c1 = {acc[a][2], acc[a][3]};
        *(float2*)&g_cKV[(ob + d0 + er) * DH + m] = c0;
        *(float2*)&g_cKV[(ob + d0 + er + 8) * DH + m] = c1;
    }
    if (tid < DH) {
        float zv = 0.f;
        for (int s = 0; s < C_; s++)
            zv += __half2float(sK[s * PB + tid]);
        g_cZ[ob + tid] = zv;
    }
}

// ---------------- exclusive prefix, parallel (4 CTAs per bh) ------------------
__global__ __launch_bounds__(256)
void prefix_kernel() {
    const int bh = blockIdx.y;
    const int e4 = (blockIdx.x * 256 + threadIdx.x) * 4;   // 0..4092
    float4 run = make_float4(0.f, 0.f, 0.f, 0.f);
    for (int c = 0; c < NC; c++) {
        size_t base = (size_t)(bh * NC + c) * (DH * DH) + e4;
        float4 t = *(const float4*)(g_cKV + base);
        uint32_t h0, l0, h1, l1;
        split2h(run.x, run.y, h0, l0);
        split2h(run.z, run.w, h1, l1);
        *(uint32_t*)&g_Sph[base]     = h0;
        *(uint32_t*)&g_Sph[base + 2] = h1;
        *(uint32_t*)&g_Spl[base]     = l0;
        *(uint32_t*)&g_Spl[base + 2] = l1;
        run.x += t.x; run.y += t.y; run.z += t.z; run.w += t.w;
    }
    if (blockIdx.x == 0 && threadIdx.x < DH) {
        float zrun = 0.f;
        for (int c = 0; c < NC; c++) {
            size_t zb = (size_t)(bh * NC + c) * DH + threadIdx.x;
            float t = g_cZ[zb];
            g_cZ[zb] = zrun;
            zrun += t;
        }
    }
}

// ---------------- per-chunk output (K fp16, S hi/lo) --------------------------
#define TILEH (C_ * PB)
#define COSM  (8 * TILEH * 2 + 2 * 64 * 4)

__global__ __launch_bounds__(128)
void chunk_out_h() {
    extern __shared__ __half smc[];
    __half* sQ  = smc;
    __half* sK  = smc + 1 * TILEH;
    __half* sVh = smc + 2 * TILEH;
    __half* sVl = smc + 3 * TILEH;
    __half* sPh = smc + 4 * TILEH;
    __half* sPl = smc + 5 * TILEH;
    __half* sSh = smc + 6 * TILEH;
    __half* sSl = smc + 7 * TILEH;
    float* sZp  = (float*)(smc + 8 * TILEH);
    float* sDen = sZp + 64;

    const int chunk = blockIdx.x, bh = blockIdx.y;
    const int b = bh >> 2, h = bh & 3;
    const int tid = threadIdx.x, lane = tid & 31, wid = tid >> 5;
    const size_t grow = (size_t)(b * T_ + chunk * C_);
    const size_t spbase = (size_t)(bh * NC + chunk) * (DH * DH);

#pragma unroll
    for (int i = 0; i < 4; i++) {
        int idx = tid + i * 128;
        int r = idx >> 3, u = idx & 7;
        size_t g = (grow + r) * D_ + h * DH + u * 8;
        *(uint4*)&sQ [r * PB + u * 8] = *(const uint4*)(g_Q16 + g);
        *(uint4*)&sK [r * PB + u * 8] = *(const uint4*)(g_K16 + g);
        *(uint4*)&sVh[r * PB + u * 8] = *(const uint4*)(g_Vh + g);
        *(uint4*)&sVl[r * PB + u * 8] = *(const uint4*)(g_Vl + g);
        size_t sp = spbase + (size_t)r * DH + u * 8;
        *(uint4*)&sPh[r * PB + u * 8] = *(const uint4*)(g_Sph + sp);
        *(uint4*)&sPl[r * PB + u * 8] = *(const uint4*)(g_Spl + sp);
    }
    if (tid < DH) sZp[tid] = g_cZ[(size_t)(bh * NC + chunk) * DH + tid];
    __syncthreads();

    const int i4 = lane >> 3, r8 = lane & 7;
    const int t0 = wid * 16;
    const int er = lane >> 2, ec = (lane & 3) * 2;
    const int tA = t0 + er, tB = tA + 8;

    // ---- S = Q K^T (both single fp16: 1 pass) ----
    float accS[8][4];
#pragma unroll
    for (int a = 0; a < 8; a++)
#pragma unroll
        for (int r = 0; r < 4; r++) accS[a][r] = 0.f;
#pragma unroll
    for (int ks = 0; ks < 4; ks++) {
        uint32_t af[4];
        ldsm4(af, smem_u32(sQ + (t0 + (i4 & 1) * 8 + r8) * PB
                           + ks * 16 + (i4 >> 1) * 8));
#pragma unroll
        for (int ng = 0; ng < 4; ng++) {
            uint32_t bf[4];
            ldsm4(bf, smem_u32(sK + (ng * 16 + (i4 >> 1) * 8 + r8) * PB
                               + ks * 16 + (i4 & 1) * 8));
            mma_f16(accS[ng * 2], af, bf[0], bf[1]);
            mma_f16(accS[ng * 2 + 1], af, bf[2], bf[3]);
        }
    }

    // ---- mask, row-sum, store S as hi/lo ----
    float rsA = 0.f, rsB = 0.f;
#pragma unroll
    for (int a = 0; a < 8; a++) {
        int s0 = a * 8 + ec;
        float c0 = (s0     <= tA) ? accS[a][0] : 0.f;
        float c1 = (s0 + 1 <= tA) ? accS[a][1] : 0.f;
        float c2 = (s0     <= tB) ? accS[a][2] : 0.f;
        float c3 = (s0 + 1 <= tB) ? accS[a][3] : 0.f;
        rsA += c0 + c1; rsB += c2 + c3;
        uint32_t hh, ll;
        split2h(c0, c1, hh, ll);
        *(uint32_t*)&sSh[tA * PB + s0] = hh;
        *(uint32_t*)&sSl[tA * PB + s0] = ll;
        split2h(c2, c3, hh, ll);
        *(uint32_t*)&sSh[tB * PB + s0] = hh;
        *(uint32_t*)&sSl[tB * PB + s0] = ll;
    }
    rsA += __shfl_xor_sync(0xFFFFFFFF, rsA, 1);
    rsA += __shfl_xor_sync(0xFFFFFFFF, rsA, 2);
    rsB += __shfl_xor_sync(0xFFFFFFFF, rsB, 1);
    rsB += __shfl_xor_sync(0xFFFFFFFF, rsB, 2);
    if ((lane & 3) == 0) { sDen[tA] = rsA; sDen[tB] = rsB; }
    __syncthreads();

    // ---- denominators: += Q . Zp + EPS ----
    if (tid < C_) {
        float qz = 0.f;
#pragma unroll
        for (int d = 0; d < DH; d += 2) {
            __half2 hv = *(__half2*)&sQ[tid * PB + d];
            qz += __half2float(hv.x) * sZp[d]
                + __half2float(hv.y) * sZp[d + 1];
        }
        sDen[tid] += qz + EPS_;
    }
    __syncthreads();

    // ---- O = Sh@Vh + Sh@Vl + Sl@Vh + Q@Ph + Q@Pl (5 passes) ----
    float accO[8][4];
#pragma unroll
    for (int a = 0; a < 8; a++)
#pragma unroll
        for (int r = 0; r < 4; r++) accO[a][r] = 0.f;
#pragma unroll
    for (int ks = 0; ks < 4; ks++) {
        const int arow = (t0 + (i4 & 1) * 8 + r8) * PB + ks * 16 + (i4 >> 1) * 8;
        const int brow = (ks * 16 + (i4 & 1) * 8 + r8) * PB;
        const int bco  = (i4 >> 1) * 8;
        uint32_t aSh[4], aSl[4], aQ[4];
        ldsm4(aSh, smem_u32(sSh + arow));
        ldsm4(aSl, smem_u32(sSl + arow));
        ldsm4(aQ,  smem_u32(sQ  + arow));
#pragma unroll
        for (int ng = 0; ng < 4; ng++) {
            uint32_t bf[4];
            ldsm4t(bf, smem_u32(sVh + brow + ng * 16 + bco));
            mma_f16(accO[ng * 2],     aSh, bf[0], bf[1]);
            mma_f16(accO[ng * 2 + 1], aSh, bf[2], bf[3]);
            mma_f16(accO[ng * 2],     aSl, bf[0], bf[1]);
            mma_f16(accO[ng * 2 + 1], aSl, bf[2], bf[3]);
            ldsm4t(bf, smem_u32(sVl + brow + ng * 16 + bco));
            mma_f16(accO[ng * 2],     aSh, bf[0], bf[1]);
            mma_f16(accO[ng * 2 + 1], aSh, bf[2], bf[3]);
            ldsm4t(bf, smem_u32(sPh + brow + ng * 16 + bco));
            mma_f16(accO[ng * 2],     aQ, bf[0], bf[1]);
            mma_f16(accO[ng * 2 + 1], aQ, bf[2], bf[3]);
            ldsm4t(bf, smem_u32(sPl + brow + ng * 16 + bco));
            mma_f16(accO[ng * 2],     aQ, bf[0], bf[1]);
            mma_f16(accO[ng * 2 + 1], aQ, bf[2], bf[3]);
        }
    }

    // ---- divide + write y (single fp16) ----
    const float invA = 1.f / sDen[tA];
    const float invB = 1.f / sDen[tB];
#pragma unroll
    for (int a = 0; a < 8; a++) {
        int c = a * 8 + ec;
        size_t gA = (grow + tA) * D_ + h * DH + c;
        size_t gB = (grow + tB) * D_ + h * DH + c;
        *(uint32_t*)&g_y16[gA] = pack_h2(accO[a][0] * invA, accO[a][1] * invA);
        *(uint32_t*)&g_y16[gB] = pack_h2(accO[a][2] * invB, accO[a][3] * invB);
    }
}

// ---------------- launch ------------------------------------------------------
extern "C" void kernel_launch(void* const* d_in, const int* in_sizes, int n_in,
                              void* d_out, int out_size) {
    const float* x  = (const float*)d_in[0];
    const float* Wq = (const float*)d_in[1];
    const float* bq = (const float*)d_in[2];
    const float* Wk = (const float*)d_in[3];
    const float* bk = (const float*)d_in[4];
    const float* Wv = (const float*)d_in[5];
    const float* bv = (const float*)d_in[6];
    const float* Wo = (const float*)d_in[7];
    const float* bo = (const float*)d_in[8];
    float* out = (float*)d_out;

    cudaFuncSetAttribute(hmma_gemm_kernel,
                         cudaFuncAttributeMaxDynamicSharedMemorySize, GEMM_SMEM);
    cudaFuncSetAttribute(chunk_out_h,
                         cudaFuncAttributeMaxDynamicSharedMemorySize, COSM);

    __half *x16, *y16;
    cudaGetSymbolAddress((void**)&x16, g_x16);
    cudaGetSymbolAddress((void**)&y16, g_y16);

    pre_kernel<<<256 + M_ * D_ / 1024, 256>>>(x, Wq, Wk, Wv, Wo);

    hmma_gemm_kernel<<<dim3(2, 64, 3), 256, GEMM_SMEM>>>(x16, bq, bk, bv,
                                                         nullptr, 0);

    chunksum_h<<<dim3(NC, BHN), 128>>>();
    prefix_kernel<<<dim3(4, BHN), 256>>>();
    chunk_out_h<<<dim3(NC, BHN), 128, COSM>>>();

    hmma_gemm_kernel<<<dim3(2, 64, 1), 256, GEMM_SMEM>>>(y16, bo, bo, bo,
                                                         out, 1);
}

// round 13
// speedup vs baseline: 6.5211x; 1.0670x over previous
#include <cuda_runtime.h>
#include <cuda_fp16.h>
#include <stdint.h>
#include <math.h>

#define B_   4
#define T_   2048
#define D_   256
#define H_   4
#define DH   64
#define C_   64
#define NC   (T_/C_)     // 32
#define BHN  (B_*H_)     // 16
#define M_   (B_*T_)     // 8192
#define EPS_ 1e-6f
#define PB   72          // chunk-kernel pitch (144B, conflict-free ldmatrix)

// ---------------- scratch ----------------------------------------------------
__device__ float g_cKV[BHN*NC*DH*DH];
__device__ float g_cZ [BHN*NC*DH];
__device__ __half g_x16[M_*D_];
__device__ __half g_Wh[4*D_*D_], g_Wl[4*D_*D_];    // W^T [n][k] hi/lo
__device__ __half g_Q16[M_*D_];
__device__ __half g_K16[M_*D_];
__device__ __half g_Vh[M_*D_],  g_Vl[M_*D_];
__device__ __half g_y16[M_*D_];
__device__ __half g_Sph[BHN*NC*DH*DH], g_Spl[BHN*NC*DH*DH];

// ---------------- PTX helpers -------------------------------------------------
__device__ __forceinline__ uint32_t smem_u32(const void* p) {
    uint32_t a;
    asm("{ .reg .u64 t; cvta.to.shared.u64 t, %1; cvt.u32.u64 %0, t; }"
        : "=r"(a) : "l"(p));
    return a;
}
__device__ __forceinline__ void ldsm4(uint32_t* r, uint32_t addr) {
    asm volatile("ldmatrix.sync.aligned.m8n8.x4.shared.b16 {%0,%1,%2,%3}, [%4];"
        : "=r"(r[0]), "=r"(r[1]), "=r"(r[2]), "=r"(r[3]) : "r"(addr));
}
__device__ __forceinline__ void ldsm4t(uint32_t* r, uint32_t addr) {
    asm volatile("ldmatrix.sync.aligned.m8n8.x4.trans.shared.b16 {%0,%1,%2,%3}, [%4];"
        : "=r"(r[0]), "=r"(r[1]), "=r"(r[2]), "=r"(r[3]) : "r"(addr));
}
__device__ __forceinline__ void mma_f16(float* c, const uint32_t* a,
                                        uint32_t b0, uint32_t b1) {
    asm volatile(
        "mma.sync.aligned.m16n8k16.row.col.f32.f16.f16.f32 "
        "{%0,%1,%2,%3}, {%4,%5,%6,%7}, {%8,%9}, {%0,%1,%2,%3};"
        : "+f"(c[0]), "+f"(c[1]), "+f"(c[2]), "+f"(c[3])
        : "r"(a[0]), "r"(a[1]), "r"(a[2]), "r"(a[3]), "r"(b0), "r"(b1));
}
__device__ __forceinline__ void cpa16(uint32_t s, const void* g) {
    asm volatile("cp.async.cg.shared.global [%0], [%1], 16;" :: "r"(s), "l"(g));
}
#define CPA_COMMIT() asm volatile("cp.async.commit_group;" ::: "memory")
#define CPA_WAIT(n)  asm volatile("cp.async.wait_group %0;" :: "n"(n) : "memory")
__device__ __forceinline__ uint32_t pack_h2(float a, float b) {
    __half2 v = __floats2half2_rn(a, b);
    return *(uint32_t*)&v;
}
__device__ __forceinline__ void split2h(float a, float b, uint32_t& h, uint32_t& l) {
    __half ha = __float2half_rn(a);
    __half hb = __float2half_rn(b);
    __half2 hv; hv.x = ha; hv.y = hb;
    __half2 lv;
    lv.x = __float2half_rn(a - __half2float(ha));
    lv.y = __float2half_rn(b - __half2float(hb));
    h = *(uint32_t*)&hv; l = *(uint32_t*)&lv;
}

// ---------------- fused pre-processing: weights split + x convert -------------
__global__ __launch_bounds__(256)
void pre_kernel(const float* __restrict__ x,
                const float* __restrict__ Wq, const float* __restrict__ Wk,
                const float* __restrict__ Wv, const float* __restrict__ Wo) {
    __shared__ float s[32][33];
    const int bid = blockIdx.x, tid = threadIdx.x;
    if (bid < 256) {
        const int z = bid >> 6, rem = bid & 63;
        const int n0 = (rem >> 3) * 32, k0 = (rem & 7) * 32;
        const float* W = (z == 0) ? Wq : (z == 1) ? Wk : (z == 2) ? Wv : Wo;
        const int tx = tid & 31, ty = tid >> 5;
#pragma unroll
        for (int r = 0; r < 4; r++) {
            int k = k0 + ty + r * 8;
            s[ty + r * 8][tx] = W[(size_t)k * D_ + n0 + tx];
        }
        __syncthreads();
#pragma unroll
        for (int r = 0; r < 4; r++) {
            int n = n0 + ty + r * 8;
            float v = s[tx][ty + r * 8];
            __half h = __float2half_rn(v);
            __half l = __float2half_rn(v - __half2float(h));
            size_t o = (size_t)z * D_ * D_ + (size_t)n * D_ + k0 + tx;
            g_Wh[o] = h;
            g_Wl[o] = l;
        }
    } else {
        int idx = (bid - 256) * 256 + tid;
        float4 v = *(const float4*)(x + (size_t)idx * 4);
        uint2 o;
        o.x = pack_h2(v.x, v.y);
        o.y = pack_h2(v.z, v.w);
        *(uint2*)(g_x16 + (size_t)idx * 4) = o;
    }
}

// ---------------- HMMA fp16 GEMM, cp.async double-buffered --------------------
#define PK   40
#define STG  (128 * PK)                 // halves per array per stage
#define GEMM_SMEM (2 * 3 * STG * 2)     // 61440 B

__global__ __launch_bounds__(256, 2)
void hmma_gemm_kernel(const __half* __restrict__ A16,
                      const float* __restrict__ b0, const float* __restrict__ b1,
                      const float* __restrict__ b2,
                      float* __restrict__ dout, int mode) {
    extern __shared__ __half sm2[];
    const uint32_t sb = smem_u32(sm2);

    const int tid = threadIdx.x, lane = tid & 31, wid = tid >> 5;
    const int warp_m = wid >> 2, warp_n = wid & 3;
    const int n0 = blockIdx.x * 128, row0 = blockIdx.y * 128;
    const int zy = blockIdx.z;
    const int z = (mode == 0) ? zy : 3;
    const float* bias = (mode == 0) ? ((zy == 0) ? b0 : (zy == 1) ? b1 : b2) : b0;
    const int feat = (mode == 0) && (zy < 2);
    const int use_lo = (mode == 1) || (zy == 2);
    const __half* Bh = g_Wh + (size_t)z * D_ * D_;
    const __half* Bl = g_Wl + (size_t)z * D_ * D_;

    const int lr = tid >> 2, lu = tid & 3;

    float acc[4][4][4];
#pragma unroll
    for (int mt = 0; mt < 4; mt++)
#pragma unroll
        for (int nt = 0; nt < 4; nt++)
#pragma unroll
            for (int r = 0; r < 4; r++) acc[mt][nt][r] = 0.f;

    const int i4 = lane >> 3, r8 = lane & 7;
    const int a_row = warp_m * 64 + (i4 & 1) * 8 + r8;
    const int b_row = warp_n * 32 + (i4 >> 1) * 8 + r8;
    const int a_co  = (i4 >> 1) * 8;
    const int b_co  = (i4 & 1) * 8;

#define LOAD_STAGE(s, buf) do {                                              \
    int _k0 = (s) * 32;                                                      \
    uint32_t _sb0 = sb + (uint32_t)((buf) * 3 * STG) * 2;                    \
    _Pragma("unroll")                                                        \
    for (int _i = 0; _i < 2; _i++) {                                         \
        int _r = lr + _i * 64;                                               \
        uint32_t _so = (uint32_t)(_r * PK + lu * 8) * 2;                     \
        size_t _ga = (size_t)(row0 + _r) * D_ + _k0 + lu * 8;                \
        size_t _gb = (size_t)(n0 + _r) * D_ + _k0 + lu * 8;                  \
        cpa16(_sb0 + _so,                 A16 + _ga);                        \
        cpa16(_sb0 + STG * 2 + _so,      Bh + _gb);                          \
        if (use_lo) cpa16(_sb0 + 2 * STG * 2 + _so,  Bl + _gb);              \
    }                                                                        \
} while (0)

    LOAD_STAGE(0, 0);
    CPA_COMMIT();

    for (int s = 0; s < 8; s++) {
        if (s < 7) {
            LOAD_STAGE(s + 1, (s + 1) & 1);
            CPA_COMMIT();
            CPA_WAIT(1);
        } else {
            CPA_WAIT(0);
        }
        __syncthreads();

        const uint32_t bufb = sb + (uint32_t)((s & 1) * 3 * STG) * 2;
        const uint32_t aB = bufb;
        const uint32_t hB = bufb + STG * 2;
        const uint32_t lB = bufb + 2 * STG * 2;

#pragma unroll
        for (int ks = 0; ks < 2; ks++) {
            const int ac = ks * 16 + a_co;
            const int bc = ks * 16 + b_co;
            uint32_t afr[4][4], bhf[2][4], blf[2][4];
#pragma unroll
            for (int mt = 0; mt < 4; mt++)
                ldsm4(afr[mt], aB + (uint32_t)((a_row + mt * 16) * PK + ac) * 2);
#pragma unroll
            for (int pt = 0; pt < 2; pt++) {
                ldsm4(bhf[pt], hB + (uint32_t)((b_row + pt * 16) * PK + bc) * 2);
                if (use_lo)
                    ldsm4(blf[pt], lB + (uint32_t)((b_row + pt * 16) * PK + bc) * 2);
            }
#pragma unroll
            for (int mt = 0; mt < 4; mt++)
#pragma unroll
                for (int nt = 0; nt < 4; nt++) {
                    int pt = nt >> 1, sub = (nt & 1) * 2;
                    mma_f16(acc[mt][nt], afr[mt], bhf[pt][sub], bhf[pt][sub + 1]);
                    if (use_lo)
                        mma_f16(acc[mt][nt], afr[mt], blf[pt][sub], blf[pt][sub + 1]);
                }
        }
        __syncthreads();
    }
#undef LOAD_STAGE

    // epilogue
    const int er = (lane >> 2), ec = (lane & 3) * 2;
#pragma unroll
    for (int mt = 0; mt < 4; mt++) {
        int r = row0 + warp_m * 64 + mt * 16 + er;
#pragma unroll
        for (int nt = 0; nt < 4; nt++) {
            int c = n0 + warp_n * 32 + nt * 8 + ec;
            float2 bv = *(const float2*)(bias + c);
            float o0x = acc[mt][nt][0] + bv.x, o0y = acc[mt][nt][1] + bv.y;
            float o1x = acc[mt][nt][2] + bv.x, o1y = acc[mt][nt][3] + bv.y;
            if (feat) {
                o0x = (o0x > 0.f) ? (o0x + 1.f) : __expf(o0x);
                o0y = (o0y > 0.f) ? (o0y + 1.f) : __expf(o0y);
                o1x = (o1x > 0.f) ? (o1x + 1.f) : __expf(o1x);
                o1y = (o1y > 0.f) ? (o1y + 1.f) : __expf(o1y);
            }
            if (mode == 1) {
                float2 a0 = {o0x, o0y}, a1 = {o1x, o1y};
                *(float2*)(dout + (size_t)r * D_ + c) = a0;
                *(float2*)(dout + (size_t)(r + 8) * D_ + c) = a1;
            } else if (zy < 2) {
                __half* O16 = (zy == 0) ? g_Q16 : g_K16;
                *(uint32_t*)&O16[(size_t)r * D_ + c] = pack_h2(o0x, o0y);
                *(uint32_t*)&O16[(size_t)(r + 8) * D_ + c] = pack_h2(o1x, o1y);
            } else {
                uint32_t h, l;
                split2h(o0x, o0y, h, l);
                *(uint32_t*)&g_Vh[(size_t)r * D_ + c] = h;
                *(uint32_t*)&g_Vl[(size_t)r * D_ + c] = l;
                split2h(o1x, o1y, h, l);
                *(uint32_t*)&g_Vh[(size_t)(r + 8) * D_ + c] = h;
                *(uint32_t*)&g_Vl[(size_t)(r + 8) * D_ + c] = l;
            }
        }
    }
}

// ---------------- per-chunk KV / Z sums (K fp16, V hi/lo -> 2 passes) ---------
__global__ __launch_bounds__(128)
void chunksum_h() {
    __shared__ __half sK [C_ * PB];
    __shared__ __half sVh[C_ * PB];
    __shared__ __half sVl[C_ * PB];
    const int chunk = blockIdx.x, bh = blockIdx.y;
    const int b = bh >> 2, h = bh & 3;
    const int tid = threadIdx.x, lane = tid & 31, wid = tid >> 5;
    const size_t base = (size_t)(b * T_ + chunk * C_) * D_ + h * DH;

#pragma unroll
    for (int i = 0; i < 4; i++) {
        int idx = tid + i * 128;
        int r = idx >> 3, u = idx & 7;
        size_t g = base + (size_t)r * D_ + u * 8;
        *(uint4*)&sK [r * PB + u * 8] = *(const uint4*)(g_K16 + g);
        *(uint4*)&sVh[r * PB + u * 8] = *(const uint4*)(g_Vh + g);
        *(uint4*)&sVl[r * PB + u * 8] = *(const uint4*)(g_Vl + g);
    }
    __syncthreads();

    const int i4 = lane >> 3, r8 = lane & 7;
    const int d0 = wid * 16;
    float acc[8][4];
#pragma unroll
    for (int a = 0; a < 8; a++)
#pragma unroll
        for (int r = 0; r < 4; r++) acc[a][r] = 0.f;

#pragma unroll
    for (int ks = 0; ks < 4; ks++) {
        uint32_t af[4];
        ldsm4t(af, smem_u32(sK + (ks * 16 + (i4 >> 1) * 8 + r8) * PB
                            + d0 + (i4 & 1) * 8));
#pragma unroll
        for (int p = 0; p < 2; p++) {
            const __half* Bv = p ? sVl : sVh;
#pragma unroll
            for (int ng = 0; ng < 4; ng++) {
                uint32_t bf[4];
                ldsm4t(bf, smem_u32(Bv + (ks * 16 + (i4 & 1) * 8 + r8) * PB
                                    + ng * 16 + (i4 >> 1) * 8));
                mma_f16(acc[ng * 2], af, bf[0], bf[1]);
                mma_f16(acc[ng * 2 + 1], af, bf[2], bf[3]);
            }
        }
    }

    const int er = lane >> 2, ec = (lane & 3) * 2;
    size_t ob = (size_t)(bh * NC + chunk) * DH;
#pragma unroll
    for (int a = 0; a < 8; a++) {
        int m = a * 8 + ec;
        float2 c0 = {acc[a][0], acc[a][1]};
        float2 c1 = {acc[a][2], acc[a][3]};
        *(float2*)&g_cKV[(ob + d0 + er) * DH + m] = c0;
        *(float2*)&g_cKV[(ob + d0 + er + 8) * DH + m] = c1;
    }
    if (tid < DH) {
        float zv = 0.f;
        for (int s = 0; s < C_; s++)
            zv += __half2float(sK[s * PB + tid]);
        g_cZ[ob + tid] = zv;
    }
}

// ---------------- exclusive prefix: load-all-then-scan (MLP-hidden) -----------
// blocks [0,256): KV scan, thread -> (bh, e) of 4096 elements
// blocks [256,260): Z scan, thread -> (bh, d)
__global__ __launch_bounds__(256)
void prefix_kernel() {
    const int bid = blockIdx.x;
    if (bid < 256) {
        const int gid = bid * 256 + threadIdx.x;     // 0..65535
        const int bh = gid >> 12;                    // /4096
        const int e  = gid & 4095;
        float v[NC];
#pragma unroll
        for (int c = 0; c < NC; c++)
            v[c] = g_cKV[((size_t)(bh * NC + c) << 12) + e];
        float run = 0.f;
#pragma unroll
        for (int c = 0; c < NC; c++) {
            __half hh = __float2half_rn(run);
            __half ll = __float2half_rn(run - __half2float(hh));
            size_t base = ((size_t)(bh * NC + c) << 12) + e;
            g_Sph[base] = hh;
            g_Spl[base] = ll;
            run += v[c];
        }
    } else {
        const int gid = (bid - 256) * 256 + threadIdx.x;   // 0..1023
        const int bh = gid >> 6, d = gid & 63;
        float v[NC];
#pragma unroll
        for (int c = 0; c < NC; c++)
            v[c] = g_cZ[(size_t)(bh * NC + c) * DH + d];
        float run = 0.f;
#pragma unroll
        for (int c = 0; c < NC; c++) {
            g_cZ[(size_t)(bh * NC + c) * DH + d] = run;
            run += v[c];
        }
    }
}

// ---------------- per-chunk output (K fp16, S hi/lo) --------------------------
#define TILEH (C_ * PB)
#define COSM  (8 * TILEH * 2 + 2 * 64 * 4)

__global__ __launch_bounds__(128)
void chunk_out_h() {
    extern __shared__ __half smc[];
    __half* sQ  = smc;
    __half* sK  = smc + 1 * TILEH;
    __half* sVh = smc + 2 * TILEH;
    __half* sVl = smc + 3 * TILEH;
    __half* sPh = smc + 4 * TILEH;
    __half* sPl = smc + 5 * TILEH;
    __half* sSh = smc + 6 * TILEH;
    __half* sSl = smc + 7 * TILEH;
    float* sZp  = (float*)(smc + 8 * TILEH);
    float* sDen = sZp + 64;

    const int chunk = blockIdx.x, bh = blockIdx.y;
    const int b = bh >> 2, h = bh & 3;
    const int tid = threadIdx.x, lane = tid & 31, wid = tid >> 5;
    const size_t grow = (size_t)(b * T_ + chunk * C_);
    const size_t spbase = (size_t)(bh * NC + chunk) * (DH * DH);

#pragma unroll
    for (int i = 0; i < 4; i++) {
        int idx = tid + i * 128;
        int r = idx >> 3, u = idx & 7;
        size_t g = (grow + r) * D_ + h * DH + u * 8;
        *(uint4*)&sQ [r * PB + u * 8] = *(const uint4*)(g_Q16 + g);
        *(uint4*)&sK [r * PB + u * 8] = *(const uint4*)(g_K16 + g);
        *(uint4*)&sVh[r * PB + u * 8] = *(const uint4*)(g_Vh + g);
        *(uint4*)&sVl[r * PB + u * 8] = *(const uint4*)(g_Vl + g);
        size_t sp = spbase + (size_t)r * DH + u * 8;
        *(uint4*)&sPh[r * PB + u * 8] = *(const uint4*)(g_Sph + sp);
        *(uint4*)&sPl[r * PB + u * 8] = *(const uint4*)(g_Spl + sp);
    }
    if (tid < DH) sZp[tid] = g_cZ[(size_t)(bh * NC + chunk) * DH + tid];
    __syncthreads();

    const int i4 = lane >> 3, r8 = lane & 7;
    const int t0 = wid * 16;
    const int er = lane >> 2, ec = (lane & 3) * 2;
    const int tA = t0 + er, tB = tA + 8;

    // ---- S = Q K^T (both single fp16: 1 pass) ----
    float accS[8][4];
#pragma unroll
    for (int a = 0; a < 8; a++)
#pragma unroll
        for (int r = 0; r < 4; r++) accS[a][r] = 0.f;
#pragma unroll
    for (int ks = 0; ks < 4; ks++) {
        uint32_t af[4];
        ldsm4(af, smem_u32(sQ + (t0 + (i4 & 1) * 8 + r8) * PB
                           + ks * 16 + (i4 >> 1) * 8));
#pragma unroll
        for (int ng = 0; ng < 4; ng++) {
            uint32_t bf[4];
            ldsm4(bf, smem_u32(sK + (ng * 16 + (i4 >> 1) * 8 + r8) * PB
                               + ks * 16 + (i4 & 1) * 8));
            mma_f16(accS[ng * 2], af, bf[0], bf[1]);
            mma_f16(accS[ng * 2 + 1], af, bf[2], bf[3]);
        }
    }

    // ---- mask, row-sum, store S as hi/lo ----
    float rsA = 0.f, rsB = 0.f;
#pragma unroll
    for (int a = 0; a < 8; a++) {
        int s0 = a * 8 + ec;
        float c0 = (s0     <= tA) ? accS[a][0] : 0.f;
        float c1 = (s0 + 1 <= tA) ? accS[a][1] : 0.f;
        float c2 = (s0     <= tB) ? accS[a][2] : 0.f;
        float c3 = (s0 + 1 <= tB) ? accS[a][3] : 0.f;
        rsA += c0 + c1; rsB += c2 + c3;
        uint32_t hh, ll;
        split2h(c0, c1, hh, ll);
        *(uint32_t*)&sSh[tA * PB + s0] = hh;
        *(uint32_t*)&sSl[tA * PB + s0] = ll;
        split2h(c2, c3, hh, ll);
        *(uint32_t*)&sSh[tB * PB + s0] = hh;
        *(uint32_t*)&sSl[tB * PB + s0] = ll;
    }
    rsA += __shfl_xor_sync(0xFFFFFFFF, rsA, 1);
    rsA += __shfl_xor_sync(0xFFFFFFFF, rsA, 2);
    rsB += __shfl_xor_sync(0xFFFFFFFF, rsB, 1);
    rsB += __shfl_xor_sync(0xFFFFFFFF, rsB, 2);
    if ((lane & 3) == 0) { sDen[tA] = rsA; sDen[tB] = rsB; }
    __syncthreads();

    // ---- denominators: += Q . Zp + EPS ----
    if (tid < C_) {
        float qz = 0.f;
#pragma unroll
        for (int d = 0; d < DH; d += 2) {
            __half2 hv = *(__half2*)&sQ[tid * PB + d];
            qz += __half2float(hv.x) * sZp[d]
                + __half2float(hv.y) * sZp[d + 1];
        }
        sDen[tid] += qz + EPS_;
    }
    __syncthreads();

    // ---- O = Sh@Vh + Sh@Vl + Sl@Vh + Q@Ph + Q@Pl (5 passes) ----
    float accO[8][4];
#pragma unroll
    for (int a = 0; a < 8; a++)
#pragma unroll
        for (int r = 0; r < 4; r++) accO[a][r] = 0.f;
#pragma unroll
    for (int ks = 0; ks < 4; ks++) {
        const int arow = (t0 + (i4 & 1) * 8 + r8) * PB + ks * 16 + (i4 >> 1) * 8;
        const int brow = (ks * 16 + (i4 & 1) * 8 + r8) * PB;
        const int bco  = (i4 >> 1) * 8;
        uint32_t aSh[4], aSl[4], aQ[4];
        ldsm4(aSh, smem_u32(sSh + arow));
        ldsm4(aSl, smem_u32(sSl + arow));
        ldsm4(aQ,  smem_u32(sQ  + arow));
#pragma unroll
        for (int ng = 0; ng < 4; ng++) {
            uint32_t bf[4];
            ldsm4t(bf, smem_u32(sVh + brow + ng * 16 + bco));
            mma_f16(accO[ng * 2],     aSh, bf[0], bf[1]);
            mma_f16(accO[ng * 2 + 1], aSh, bf[2], bf[3]);
            mma_f16(accO[ng * 2],     aSl, bf[0], bf[1]);
            mma_f16(accO[ng * 2 + 1], aSl, bf[2], bf[3]);
            ldsm4t(bf, smem_u32(sVl + brow + ng * 16 + bco));
            mma_f16(accO[ng * 2],     aSh, bf[0], bf[1]);
            mma_f16(accO[ng * 2 + 1], aSh, bf[2], bf[3]);
            ldsm4t(bf, smem_u32(sPh + brow + ng * 16 + bco));
            mma_f16(accO[ng * 2],     aQ, bf[0], bf[1]);
            mma_f16(accO[ng * 2 + 1], aQ, bf[2], bf[3]);
            ldsm4t(bf, smem_u32(sPl + brow + ng * 16 + bco));
            mma_f16(accO[ng * 2],     aQ, bf[0], bf[1]);
            mma_f16(accO[ng * 2 + 1], aQ, bf[2], bf[3]);
        }
    }

    // ---- divide + write y (single fp16) ----
    const float invA = 1.f / sDen[tA];
    const float invB = 1.f / sDen[tB];
#pragma unroll
    for (int a = 0; a < 8; a++) {
        int c = a * 8 + ec;
        size_t gA = (grow + tA) * D_ + h * DH + c;
        size_t gB = (grow + tB) * D_ + h * DH + c;
        *(uint32_t*)&g_y16[gA] = pack_h2(accO[a][0] * invA, accO[a][1] * invA);
        *(uint32_t*)&g_y16[gB] = pack_h2(accO[a][2] * invB, accO[a][3] * invB);
    }
}

// ---------------- launch ------------------------------------------------------
extern "C" void kernel_launch(void* const* d_in, const int* in_sizes, int n_in,
                              void* d_out, int out_size) {
    const float* x  = (const float*)d_in[0];
    const float* Wq = (const float*)d_in[1];
    const float* bq = (const float*)d_in[2];
    const float* Wk = (const float*)d_in[3];
    const float* bk = (const float*)d_in[4];
    const float* Wv = (const float*)d_in[5];
    const float* bv = (const float*)d_in[6];
    const float* Wo = (const float*)d_in[7];
    const float* bo = (const float*)d_in[8];
    float* out = (float*)d_out;

    cudaFuncSetAttribute(hmma_gemm_kernel,
                         cudaFuncAttributeMaxDynamicSharedMemorySize, GEMM_SMEM);
    cudaFuncSetAttribute(chunk_out_h,
                         cudaFuncAttributeMaxDynamicSharedMemorySize, COSM);

    __half *x16, *y16;
    cudaGetSymbolAddress((void**)&x16, g_x16);
    cudaGetSymbolAddress((void**)&y16, g_y16);

    pre_kernel<<<256 + M_ * D_ / 1024, 256>>>(x, Wq, Wk, Wv, Wo);

    hmma_gemm_kernel<<<dim3(2, 64, 3), 256, GEMM_SMEM>>>(x16, bq, bk, bv,
                                                         nullptr, 0);

    chunksum_h<<<dim3(NC, BHN), 128>>>();
    prefix_kernel<<<260, 256>>>();
    chunk_out_h<<<dim3(NC, BHN), 128, COSM>>>();

    hmma_gemm_kernel<<<dim3(2, 64, 1), 256, GEMM_SMEM>>>(y16, bo, bo, bo,
                                                         out, 1);
}

// round 17
// speedup vs baseline: 6.7034x; 1.0280x over previous
#include <cuda_runtime.h>
#include <cuda_fp16.h>
#include <stdint.h>
#include <math.h>

#define B_   4
#define T_   2048
#define D_   256
#define H_   4
#define DH   64
#define C_   64
#define NC   (T_/C_)     // 32
#define BHN  (B_*H_)     // 16
#define M_   (B_*T_)     // 8192
#define EPS_ 1e-6f
#define PB   72          // chunk-kernel pitch (144B, conflict-free ldmatrix)

// ---------------- scratch ----------------------------------------------------
__device__ float g_cKV[BHN*NC*DH*DH];
__device__ float g_cZ [BHN*NC*DH];
__device__ __half g_x16[M_*D_];
__device__ __half g_Wh[4*D_*D_], g_Wl[4*D_*D_];    // W^T [n][k] hi/lo
__device__ __half g_Q16[M_*D_];
__device__ __half g_K16[M_*D_];
__device__ __half g_Vh[M_*D_],  g_Vl[M_*D_];
__device__ __half g_y16[M_*D_];
__device__ __half g_Sph[BHN*NC*DH*DH], g_Spl[BHN*NC*DH*DH];

// ---------------- PTX helpers -------------------------------------------------
__device__ __forceinline__ uint32_t smem_u32(const void* p) {
    uint32_t a;
    asm("{ .reg .u64 t; cvta.to.shared.u64 t, %1; cvt.u32.u64 %0, t; }"
        : "=r"(a) : "l"(p));
    return a;
}
__device__ __forceinline__ void ldsm4(uint32_t* r, uint32_t addr) {
    asm volatile("ldmatrix.sync.aligned.m8n8.x4.shared.b16 {%0,%1,%2,%3}, [%4];"
        : "=r"(r[0]), "=r"(r[1]), "=r"(r[2]), "=r"(r[3]) : "r"(addr));
}
__device__ __forceinline__ void ldsm4t(uint32_t* r, uint32_t addr) {
    asm volatile("ldmatrix.sync.aligned.m8n8.x4.trans.shared.b16 {%0,%1,%2,%3}, [%4];"
        : "=r"(r[0]), "=r"(r[1]), "=r"(r[2]), "=r"(r[3]) : "r"(addr));
}
__device__ __forceinline__ void mma_f16(float* c, const uint32_t* a,
                                        uint32_t b0, uint32_t b1) {
    asm volatile(
        "mma.sync.aligned.m16n8k16.row.col.f32.f16.f16.f32 "
        "{%0,%1,%2,%3}, {%4,%5,%6,%7}, {%8,%9}, {%0,%1,%2,%3};"
        : "+f"(c[0]), "+f"(c[1]), "+f"(c[2]), "+f"(c[3])
        : "r"(a[0]), "r"(a[1]), "r"(a[2]), "r"(a[3]), "r"(b0), "r"(b1));
}
__device__ __forceinline__ void cpa16(uint32_t s, const void* g) {
    asm volatile("cp.async.cg.shared.global [%0], [%1], 16;" :: "r"(s), "l"(g));
}
#define CPA_COMMIT() asm volatile("cp.async.commit_group;" ::: "memory")
#define CPA_WAIT(n)  asm volatile("cp.async.wait_group %0;" :: "n"(n) : "memory")
__device__ __forceinline__ uint32_t pack_h2(float a, float b) {
    __half2 v = __floats2half2_rn(a, b);
    return *(uint32_t*)&v;
}
__device__ __forceinline__ void split2h(float a, float b, uint32_t& h, uint32_t& l) {
    __half ha = __float2half_rn(a);
    __half hb = __float2half_rn(b);
    __half2 hv; hv.x = ha; hv.y = hb;
    __half2 lv;
    lv.x = __float2half_rn(a - __half2float(ha));
    lv.y = __float2half_rn(b - __half2float(hb));
    h = *(uint32_t*)&hv; l = *(uint32_t*)&lv;
}

// ---------------- fused pre-processing: weights split + x convert -------------
__global__ __launch_bounds__(256)
void pre_kernel(const float* __restrict__ x,
                const float* __restrict__ Wq, const float* __restrict__ Wk,
                const float* __restrict__ Wv, const float* __restrict__ Wo) {
    __shared__ float s[32][33];
    const int bid = blockIdx.x, tid = threadIdx.x;
    if (bid < 256) {
        const int z = bid >> 6, rem = bid & 63;
        const int n0 = (rem >> 3) * 32, k0 = (rem & 7) * 32;
        const float* W = (z == 0) ? Wq : (z == 1) ? Wk : (z == 2) ? Wv : Wo;
        const int tx = tid & 31, ty = tid >> 5;
#pragma unroll
        for (int r = 0; r < 4; r++) {
            int k = k0 + ty + r * 8;
            s[ty + r * 8][tx] = W[(size_t)k * D_ + n0 + tx];
        }
        __syncthreads();
#pragma unroll
        for (int r = 0; r < 4; r++) {
            int n = n0 + ty + r * 8;
            float v = s[tx][ty + r * 8];
            __half h = __float2half_rn(v);
            __half l = __float2half_rn(v - __half2float(h));
            size_t o = (size_t)z * D_ * D_ + (size_t)n * D_ + k0 + tx;
            g_Wh[o] = h;
            g_Wl[o] = l;
        }
    } else {
        int idx = (bid - 256) * 256 + tid;
        float4 v = *(const float4*)(x + (size_t)idx * 4);
        uint2 o;
        o.x = pack_h2(v.x, v.y);
        o.y = pack_h2(v.z, v.w);
        *(uint2*)(g_x16 + (size_t)idx * 4) = o;
    }
}

// ---------------- HMMA fp16 GEMM, cp.async double-buffered --------------------
#define PK   40
#define STG  (128 * PK)                 // halves per array per stage
#define GEMM_SMEM (2 * 3 * STG * 2)     // 61440 B

__global__ __launch_bounds__(256, 2)
void hmma_gemm_kernel(const __half* __restrict__ A16,
                      const float* __restrict__ b0, const float* __restrict__ b1,
                      const float* __restrict__ b2,
                      float* __restrict__ dout, int mode) {
    extern __shared__ __half sm2[];
    const uint32_t sb = smem_u32(sm2);

    const int tid = threadIdx.x, lane = tid & 31, wid = tid >> 5;
    const int warp_m = wid >> 2, warp_n = wid & 3;
    const int n0 = blockIdx.x * 128, row0 = blockIdx.y * 128;
    const int zy = blockIdx.z;
    const int z = (mode == 0) ? zy : 3;
    const float* bias = (mode == 0) ? ((zy == 0) ? b0 : (zy == 1) ? b1 : b2) : b0;
    const int feat = (mode == 0) && (zy < 2);
    const int use_lo = (mode == 0) && (zy == 2);   // only V projection keeps lo pass
    const __half* Bh = g_Wh + (size_t)z * D_ * D_;
    const __half* Bl = g_Wl + (size_t)z * D_ * D_;

    const int lr = tid >> 2, lu = tid & 3;

    float acc[4][4][4];
#pragma unroll
    for (int mt = 0; mt < 4; mt++)
#pragma unroll
        for (int nt = 0; nt < 4; nt++)
#pragma unroll
            for (int r = 0; r < 4; r++) acc[mt][nt][r] = 0.f;

    const int i4 = lane >> 3, r8 = lane & 7;
    const int a_row = warp_m * 64 + (i4 & 1) * 8 + r8;
    const int b_row = warp_n * 32 + (i4 >> 1) * 8 + r8;
    const int a_co  = (i4 >> 1) * 8;
    const int b_co  = (i4 & 1) * 8;

#define LOAD_STAGE(s, buf) do {                                              \
    int _k0 = (s) * 32;                                                      \
    uint32_t _sb0 = sb + (uint32_t)((buf) * 3 * STG) * 2;                    \
    _Pragma("unroll")                                                        \
    for (int _i = 0; _i < 2; _i++) {                                         \
        int _r = lr + _i * 64;                                               \
        uint32_t _so = (uint32_t)(_r * PK + lu * 8) * 2;                     \
        size_t _ga = (size_t)(row0 + _r) * D_ + _k0 + lu * 8;                \
        size_t _gb = (size_t)(n0 + _r) * D_ + _k0 + lu * 8;                  \
        cpa16(_sb0 + _so,                 A16 + _ga);                        \
        cpa16(_sb0 + STG * 2 + _so,      Bh + _gb);                          \
        if (use_lo) cpa16(_sb0 + 2 * STG * 2 + _so,  Bl + _gb);              \
    }                                                                        \
} while (0)

    LOAD_STAGE(0, 0);
    CPA_COMMIT();

    for (int s = 0; s < 8; s++) {
        if (s < 7) {
            LOAD_STAGE(s + 1, (s + 1) & 1);
            CPA_COMMIT();
            CPA_WAIT(1);
        } else {
            CPA_WAIT(0);
        }
        __syncthreads();

        const uint32_t bufb = sb + (uint32_t)((s & 1) * 3 * STG) * 2;
        const uint32_t aB = bufb;
        const uint32_t hB = bufb + STG * 2;
        const uint32_t lB = bufb + 2 * STG * 2;

#pragma unroll
        for (int ks = 0; ks < 2; ks++) {
            const int ac = ks * 16 + a_co;
            const int bc = ks * 16 + b_co;
            uint32_t afr[4][4], bhf[2][4], blf[2][4];
#pragma unroll
            for (int mt = 0; mt < 4; mt++)
                ldsm4(afr[mt], aB + (uint32_t)((a_row + mt * 16) * PK + ac) * 2);
#pragma unroll
            for (int pt = 0; pt < 2; pt++) {
                ldsm4(bhf[pt], hB + (uint32_t)((b_row + pt * 16) * PK + bc) * 2);
                if (use_lo)
                    ldsm4(blf[pt], lB + (uint32_t)((b_row + pt * 16) * PK + bc) * 2);
            }
#pragma unroll
            for (int mt = 0; mt < 4; mt++)
#pragma unroll
                for (int nt = 0; nt < 4; nt++) {
                    int pt = nt >> 1, sub = (nt & 1) * 2;
                    mma_f16(acc[mt][nt], afr[mt], bhf[pt][sub], bhf[pt][sub + 1]);
                    if (use_lo)
                        mma_f16(acc[mt][nt], afr[mt], blf[pt][sub], blf[pt][sub + 1]);
                }
        }
        __syncthreads();
    }
#undef LOAD_STAGE

    // epilogue
    const int er = (lane >> 2), ec = (lane & 3) * 2;
#pragma unroll
    for (int mt = 0; mt < 4; mt++) {
        int r = row0 + warp_m * 64 + mt * 16 + er;
#pragma unroll
        for (int nt = 0; nt < 4; nt++) {
            int c = n0 + warp_n * 32 + nt * 8 + ec;
            float2 bv = *(const float2*)(bias + c);
            float o0x = acc[mt][nt][0] + bv.x, o0y = acc[mt][nt][1] + bv.y;
            float o1x = acc[mt][nt][2] + bv.x, o1y = acc[mt][nt][3] + bv.y;
            if (feat) {
                o0x = (o0x > 0.f) ? (o0x + 1.f) : __expf(o0x);
                o0y = (o0y > 0.f) ? (o0y + 1.f) : __expf(o0y);
                o1x = (o1x > 0.f) ? (o1x + 1.f) : __expf(o1x);
                o1y = (o1y > 0.f) ? (o1y + 1.f) : __expf(o1y);
            }
            if (mode == 1) {
                float2 a0 = {o0x, o0y}, a1 = {o1x, o1y};
                *(float2*)(dout + (size_t)r * D_ + c) = a0;
                *(float2*)(dout + (size_t)(r + 8) * D_ + c) = a1;
            } else if (zy < 2) {
                __half* O16 = (zy == 0) ? g_Q16 : g_K16;
                *(uint32_t*)&O16[(size_t)r * D_ + c] = pack_h2(o0x, o0y);
                *(uint32_t*)&O16[(size_t)(r + 8) * D_ + c] = pack_h2(o1x, o1y);
            } else {
                uint32_t h, l;
                split2h(o0x, o0y, h, l);
                *(uint32_t*)&g_Vh[(size_t)r * D_ + c] = h;
                *(uint32_t*)&g_Vl[(size_t)r * D_ + c] = l;
                split2h(o1x, o1y, h, l);
                *(uint32_t*)&g_Vh[(size_t)(r + 8) * D_ + c] = h;
                *(uint32_t*)&g_Vl[(size_t)(r + 8) * D_ + c] = l;
            }
        }
    }
}

// ---------------- per-chunk KV / Z sums (K fp16, V hi only -> 1 pass) ---------
__global__ __launch_bounds__(128)
void chunksum_h() {
    __shared__ __half sK [C_ * PB];
    __shared__ __half sVh[C_ * PB];
    const int chunk = blockIdx.x, bh = blockIdx.y;
    const int b = bh >> 2, h = bh & 3;
    const int tid = threadIdx.x, lane = tid & 31, wid = tid >> 5;
    const size_t base = (size_t)(b * T_ + chunk * C_) * D_ + h * DH;

#pragma unroll
    for (int i = 0; i < 4; i++) {
        int idx = tid + i * 128;
        int r = idx >> 3, u = idx & 7;
        size_t g = base + (size_t)r * D_ + u * 8;
        *(uint4*)&sK [r * PB + u * 8] = *(const uint4*)(g_K16 + g);
        *(uint4*)&sVh[r * PB + u * 8] = *(const uint4*)(g_Vh + g);
    }
    __syncthreads();

    const int i4 = lane >> 3, r8 = lane & 7;
    const int d0 = wid * 16;
    float acc[8][4];
#pragma unroll
    for (int a = 0; a < 8; a++)
#pragma unroll
        for (int r = 0; r < 4; r++) acc[a][r] = 0.f;

#pragma unroll
    for (int ks = 0; ks < 4; ks++) {
        uint32_t af[4];
        ldsm4t(af, smem_u32(sK + (ks * 16 + (i4 >> 1) * 8 + r8) * PB
                            + d0 + (i4 & 1) * 8));
#pragma unroll
        for (int ng = 0; ng < 4; ng++) {
            uint32_t bf[4];
            ldsm4t(bf, smem_u32(sVh + (ks * 16 + (i4 & 1) * 8 + r8) * PB
                                + ng * 16 + (i4 >> 1) * 8));
            mma_f16(acc[ng * 2], af, bf[0], bf[1]);
            mma_f16(acc[ng * 2 + 1], af, bf[2], bf[3]);
        }
    }

    const int er = lane >> 2, ec = (lane & 3) * 2;
    size_t ob = (size_t)(bh * NC + chunk) * DH;
#pragma unroll
    for (int a = 0; a < 8; a++) {
        int m = a * 8 + ec;
        float2 c0 = {acc[a][0], acc[a][1]};
        float2 c1 = {acc[a][2], acc[a][3]};
        *(float2*)&g_cKV[(ob + d0 + er) * DH + m] = c0;
        *(float2*)&g_cKV[(ob + d0 + er + 8) * DH + m] = c1;
    }
    if (tid < DH) {
        float zv = 0.f;
        for (int s = 0; s < C_; s++)
            zv += __half2float(sK[s * PB + tid]);
        g_cZ[ob + tid] = zv;
    }
}

// ---------------- exclusive prefix: float2 per thread, no spill ---------------
// blocks [0,256): KV scan, 128 threads each, thread -> (bh, 2 elements)
// blocks [256,264): Z scan, thread -> (bh, d)
__global__ __launch_bounds__(128)
void prefix_kernel() {
    const int bid = blockIdx.x;
    if (bid < 256) {
        const int gid = bid * 128 + threadIdx.x;     // 0..32767
        const int bh = gid >> 11;                    // /2048
        const int e  = (gid & 2047) * 2;
        float2 v[NC];
#pragma unroll
        for (int c = 0; c < NC; c++)
            v[c] = *(const float2*)(g_cKV + ((size_t)(bh * NC + c) << 12) + e);
        float rx = 0.f, ry = 0.f;
#pragma unroll
        for (int c = 0; c < NC; c++) {
            uint32_t hh, ll;
            split2h(rx, ry, hh, ll);
            size_t base = ((size_t)(bh * NC + c) << 12) + e;
            *(uint32_t*)&g_Sph[base] = hh;
            *(uint32_t*)&g_Spl[base] = ll;
            rx += v[c].x; ry += v[c].y;
        }
    } else {
        const int gid = (bid - 256) * 128 + threadIdx.x;   // 0..1023
        const int bh = gid >> 6, d = gid & 63;
        float v[NC];
#pragma unroll
        for (int c = 0; c < NC; c++)
            v[c] = g_cZ[(size_t)(bh * NC + c) * DH + d];
        float run = 0.f;
#pragma unroll
        for (int c = 0; c < NC; c++) {
            g_cZ[(size_t)(bh * NC + c) * DH + d] = run;
            run += v[c];
        }
    }
}

// ---------------- per-chunk output (K fp16, S hi/lo) --------------------------
#define TILEH (C_ * PB)
#define COSM  (8 * TILEH * 2 + 2 * 64 * 4)

__global__ __launch_bounds__(128)
void chunk_out_h() {
    extern __shared__ __half smc[];
    __half* sQ  = smc;
    __half* sK  = smc + 1 * TILEH;
    __half* sVh = smc + 2 * TILEH;
    __half* sVl = smc + 3 * TILEH;
    __half* sPh = smc + 4 * TILEH;
    __half* sPl = smc + 5 * TILEH;
    __half* sSh = smc + 6 * TILEH;
    __half* sSl = smc + 7 * TILEH;
    float* sZp  = (float*)(smc + 8 * TILEH);
    float* sDen = sZp + 64;

    const int chunk = blockIdx.x, bh = blockIdx.y;
    const int b = bh >> 2, h = bh & 3;
    const int tid = threadIdx.x, lane = tid & 31, wid = tid >> 5;
    const size_t grow = (size_t)(b * T_ + chunk * C_);
    const size_t spbase = (size_t)(bh * NC + chunk) * (DH * DH);

#pragma unroll
    for (int i = 0; i < 4; i++) {
        int idx = tid + i * 128;
        int r = idx >> 3, u = idx & 7;
        size_t g = (grow + r) * D_ + h * DH + u * 8;
        *(uint4*)&sQ [r * PB + u * 8] = *(const uint4*)(g_Q16 + g);
        *(uint4*)&sK [r * PB + u * 8] = *(const uint4*)(g_K16 + g);
        *(uint4*)&sVh[r * PB + u * 8] = *(const uint4*)(g_Vh + g);
        *(uint4*)&sVl[r * PB + u * 8] = *(const uint4*)(g_Vl + g);
        size_t sp = spbase + (size_t)r * DH + u * 8;
        *(uint4*)&sPh[r * PB + u * 8] = *(const uint4*)(g_Sph + sp);
        *(uint4*)&sPl[r * PB + u * 8] = *(const uint4*)(g_Spl + sp);
    }
    if (tid < DH) sZp[tid] = g_cZ[(size_t)(bh * NC + chunk) * DH + tid];
    __syncthreads();

    const int i4 = lane >> 3, r8 = lane & 7;
    const int t0 = wid * 16;
    const int er = lane >> 2, ec = (lane & 3) * 2;
    const int tA = t0 + er, tB = tA + 8;

    // ---- S = Q K^T (both single fp16: 1 pass) ----
    float accS[8][4];
#pragma unroll
    for (int a = 0; a < 8; a++)
#pragma unroll
        for (int r = 0; r < 4; r++) accS[a][r] = 0.f;
#pragma unroll
    for (int ks = 0; ks < 4; ks++) {
        uint32_t af[4];
        ldsm4(af, smem_u32(sQ + (t0 + (i4 & 1) * 8 + r8) * PB
                           + ks * 16 + (i4 >> 1) * 8));
#pragma unroll
        for (int ng = 0; ng < 4; ng++) {
            uint32_t bf[4];
            ldsm4(bf, smem_u32(sK + (ng * 16 + (i4 >> 1) * 8 + r8) * PB
                               + ks * 16 + (i4 & 1) * 8));
            mma_f16(accS[ng * 2], af, bf[0], bf[1]);
            mma_f16(accS[ng * 2 + 1], af, bf[2], bf[3]);
        }
    }

    // ---- mask, row-sum, store S as hi/lo ----
    float rsA = 0.f, rsB = 0.f;
#pragma unroll
    for (int a = 0; a < 8; a++) {
        int s0 = a * 8 + ec;
        float c0 = (s0     <= tA) ? accS[a][0] : 0.f;
        float c1 = (s0 + 1 <= tA) ? accS[a][1] : 0.f;
        float c2 = (s0     <= tB) ? accS[a][2] : 0.f;
        float c3 = (s0 + 1 <= tB) ? accS[a][3] : 0.f;
        rsA += c0 + c1; rsB += c2 + c3;
        uint32_t hh, ll;
        split2h(c0, c1, hh, ll);
        *(uint32_t*)&sSh[tA * PB + s0] = hh;
        *(uint32_t*)&sSl[tA * PB + s0] = ll;
        split2h(c2, c3, hh, ll);
        *(uint32_t*)&sSh[tB * PB + s0] = hh;
        *(uint32_t*)&sSl[tB * PB + s0] = ll;
    }
    rsA += __shfl_xor_sync(0xFFFFFFFF, rsA, 1);
    rsA += __shfl_xor_sync(0xFFFFFFFF, rsA, 2);
    rsB += __shfl_xor_sync(0xFFFFFFFF, rsB, 1);
    rsB += __shfl_xor_sync(0xFFFFFFFF, rsB, 2);
    if ((lane & 3) == 0) { sDen[tA] = rsA; sDen[tB] = rsB; }
    __syncthreads();

    // ---- denominators: += Q . Zp + EPS ----
    if (tid < C_) {
        float qz = 0.f;
#pragma unroll
        for (int d = 0; d < DH; d += 2) {
            __half2 hv = *(__half2*)&sQ[tid * PB + d];
            qz += __half2float(hv.x) * sZp[d]
                + __half2float(hv.y) * sZp[d + 1];
        }
        sDen[tid] += qz + EPS_;
    }
    __syncthreads();

    // ---- O = Sh@Vh + Sh@Vl + Sl@Vh + Q@Ph + Q@Pl (5 passes) ----
    float accO[8][4];
#pragma unroll
    for (int a = 0; a < 8; a++)
#pragma unroll
        for (int r = 0; r < 4; r++) accO[a][r] = 0.f;
#pragma unroll
    for (int ks = 0; ks < 4; ks++) {
        const int arow = (t0 + (i4 & 1) * 8 + r8) * PB + ks * 16 + (i4 >> 1) * 8;
        const int brow = (ks * 16 + (i4 & 1) * 8 + r8) * PB;
        const int bco  = (i4 >> 1) * 8;
        uint32_t aSh[4], aSl[4], aQ[4];
        ldsm4(aSh, smem_u32(sSh + arow));
        ldsm4(aSl, smem_u32(sSl + arow));
        ldsm4(aQ,  smem_u32(sQ  + arow));
#pragma unroll
        for (int ng = 0; ng < 4; ng++) {
            uint32_t bf[4];
            ldsm4t(bf, smem_u32(sVh + brow + ng * 16 + bco));
            mma_f16(accO[ng * 2],     aSh, bf[0], bf[1]);
            mma_f16(accO[ng * 2 + 1], aSh, bf[2], bf[3]);
            mma_f16(accO[ng * 2],     aSl, bf[0], bf[1]);
            mma_f16(accO[ng * 2 + 1], aSl, bf[2], bf[3]);
            ldsm4t(bf, smem_u32(sVl + brow + ng * 16 + bco));
            mma_f16(accO[ng * 2],     aSh, bf[0], bf[1]);
            mma_f16(accO[ng * 2 + 1], aSh, bf[2], bf[3]);
            ldsm4t(bf, smem_u32(sPh + brow + ng * 16 + bco));
            mma_f16(accO[ng * 2],     aQ, bf[0], bf[1]);
            mma_f16(accO[ng * 2 + 1], aQ, bf[2], bf[3]);
            ldsm4t(bf, smem_u32(sPl + brow + ng * 16 + bco));
            mma_f16(accO[ng * 2],     aQ, bf[0], bf[1]);
            mma_f16(accO[ng * 2 + 1], aQ, bf[2], bf[3]);
        }
    }

    // ---- divide + write y (single fp16) ----
    const float invA = 1.f / sDen[tA];
    const float invB = 1.f / sDen[tB];
#pragma unroll
    for (int a = 0; a < 8; a++) {
        int c = a * 8 + ec;
        size_t gA = (grow + tA) * D_ + h * DH + c;
        size_t gB = (grow + tB) * D_ + h * DH + c;
        *(uint32_t*)&g_y16[gA] = pack_h2(accO[a][0] * invA, accO[a][1] * invA);
        *(uint32_t*)&g_y16[gB] = pack_h2(accO[a][2] * invB, accO[a][3] * invB);
    }
}

// ---------------- launch ------------------------------------------------------
extern "C" void kernel_launch(void* const* d_in, const int* in_sizes, int n_in,
                              void* d_out, int out_size) {
    const float* x  = (const float*)d_in[0];
    const float* Wq = (const float*)d_in[1];
    const float* bq = (const float*)d_in[2];
    const float* Wk = (const float*)d_in[3];
    const float* bk = (const float*)d_in[4];
    const float* Wv = (const float*)d_in[5];
    const float* bv = (const float*)d_in[6];
    const float* Wo = (const float*)d_in[7];
    const float* bo = (const float*)d_in[8];
    float* out = (float*)d_out;

    cudaFuncSetAttribute(hmma_gemm_kernel,
                         cudaFuncAttributeMaxDynamicSharedMemorySize, GEMM_SMEM);
    cudaFuncSetAttribute(chunk_out_h,
                         cudaFuncAttributeMaxDynamicSharedMemorySize, COSM);

    __half *x16, *y16;
    cudaGetSymbolAddress((void**)&x16, g_x16);
    cudaGetSymbolAddress((void**)&y16, g_y16);

    pre_kernel<<<256 + M_ * D_ / 1024, 256>>>(x, Wq, Wk, Wv, Wo);

    hmma_gemm_kernel<<<dim3(2, 64, 3), 256, GEMM_SMEM>>>(x16, bq, bk, bv,
                                                         nullptr, 0);

    chunksum_h<<<dim3(NC, BHN), 128>>>();
    prefix_kernel<<<264, 128>>>();
    chunk_out_h<<<dim3(NC, BHN), 128, COSM>>>();

    hmma_gemm_kernel<<<dim3(2, 64, 1), 256, GEMM_SMEM>>>(y16, bo, bo, bo,
                                                         out, 1);
}